// round 1
// baseline (speedup 1.0000x reference)
#include <cuda_runtime.h>

#define NN 100000
#define NB 20000
#define INC 64
#define HID 128

// ---------------- scratch (device globals; no runtime allocation) ----------
__device__ float g_xn0[(size_t)NN * HID];
__device__ float g_xn1[(size_t)NN * HID];
__device__ float g_xb0[(size_t)NB * HID];
__device__ float g_xb1[(size_t)NB * HID];
__device__ float g_agg[(size_t)NN * HID];
__device__ float g_proj[(size_t)NN * INC];
__device__ float g_or [(size_t)NN * HID];   // per-relation o buffer / MLP hidden
__device__ float g_outn[(size_t)NN * HID];
__device__ float g_outb[(size_t)NB * HID];
__device__ float g_cnt0[NN];
__device__ float g_cnt1[NN];
__device__ float g_cnt2[NB];
__device__ float g_cnt3[NN];
__device__ float g_cnt4[NB];
__device__ int   g_emode;   // 0 = int32 edges, 1 = int64 edges

// ---------------- edge dtype detection -------------------------------------
__global__ void detect_mode_k(const int* e) {
    // int64 little-endian: every odd 32-bit word is the hi word == 0
    int z = 1;
    for (int i = 1; i < 64; i += 2)
        if (e[i] != 0) z = 0;
    g_emode = z;
}

__device__ __forceinline__ int edge_at(const int* e, long long i) {
    if (g_emode) return (int)((const long long*)e)[i];
    return e[i];
}

// ---------------- edge count per dst ---------------------------------------
__global__ void count_k(const int* __restrict__ e, int E, float* __restrict__ cnt) {
    int i = blockIdx.x * 256 + threadIdx.x;
    if (i >= E) return;
    int d = edge_at(e, (long long)E + i);
    atomicAdd(&cnt[d], 1.0f);
}

// ---------------- edge aggregation (scatter-add of gathered src rows) ------
__global__ void agg_k(const float* __restrict__ xf, const int* __restrict__ e,
                      int E, int C, float* __restrict__ agg) {
    int C4 = C >> 2;
    long long total = (long long)E * C4;
    long long idx = (long long)blockIdx.x * 256 + threadIdx.x;
    if (idx >= total) return;
    int edge = (int)(idx / C4);
    int ch   = (int)(idx % C4);
    int s = edge_at(e, edge);
    int d = edge_at(e, (long long)E + edge);
    float4 v = reinterpret_cast<const float4*>(xf + (size_t)s * C)[ch];
    float* p = agg + (size_t)d * C + ch * 4;
    atomicAdd(p + 0, v.x);
    atomicAdd(p + 1, v.y);
    atomicAdd(p + 2, v.z);
    atomicAdd(p + 3, v.w);
}

// ---------------- divide rows by count (seg-mean) ---------------------------
__global__ void scale_k(float* __restrict__ a, const float* __restrict__ cnt,
                        long long total, int C) {
    long long idx = (long long)blockIdx.x * 256 + threadIdx.x;
    if (idx >= total) return;
    int row = (int)(idx / C);
    a[idx] = a[idx] * (1.0f / fmaxf(cnt[row], 1.0f));
}

// ---------------- generic tiled GEMM: C = act(alpha*(A@W) + bias [+ C]) ----
template <int N, bool RELU, bool ACCUM>
__global__ __launch_bounds__(256) void gemm_k(
    const float* __restrict__ A, const float* __restrict__ W,
    const float* __restrict__ bias, float* __restrict__ C,
    int M, int K, float alpha)
{
    constexpr int G = 256 / N;   // row-groups
    constexpr int R = 64 / G;    // rows per thread
    __shared__ float As[64][33];
    __shared__ float Ws[32][N];
    int t  = threadIdx.x;
    int m0 = blockIdx.x * 64;
    int c  = t % N;
    int g  = t / N;
    float acc[R];
#pragma unroll
    for (int i = 0; i < R; i++) acc[i] = 0.0f;

    for (int k0 = 0; k0 < K; k0 += 32) {
        for (int l = t; l < 64 * 32; l += 256) {
            int i = l >> 5, j = l & 31;
            int m = m0 + i;
            As[i][j] = (m < M) ? A[(size_t)m * K + k0 + j] : 0.0f;
        }
        for (int l = t; l < 32 * N; l += 256) {
            int kk = l / N, cc = l % N;
            Ws[kk][cc] = W[(size_t)(k0 + kk) * N + cc];
        }
        __syncthreads();
#pragma unroll
        for (int kk = 0; kk < 32; kk++) {
            float w = Ws[kk][c];
#pragma unroll
            for (int rr = 0; rr < R; rr++)
                acc[rr] += As[g + rr * G][kk] * w;
        }
        __syncthreads();
    }
#pragma unroll
    for (int rr = 0; rr < R; rr++) {
        int m = m0 + g + rr * G;
        if (m < M) {
            float v = acc[rr] * alpha;
            if (bias) v += bias[c];
            size_t o = (size_t)m * N + c;
            if (ACCUM) v += C[o];
            if (RELU) v = fmaxf(v, 0.0f);
            C[o] = v;
        }
    }
}

// ---------------- L2-normalize rows of o and accumulate into out -----------
__global__ void l2norm_acc_k(const float* __restrict__ o, float* __restrict__ out, int M) {
    int row = blockIdx.x * 8 + (threadIdx.x >> 5);
    if (row >= M) return;
    int lane = threadIdx.x & 31;
    const float* p = o + (size_t)row * 128;
    float v[4]; float ss = 0.0f;
#pragma unroll
    for (int j = 0; j < 4; j++) { v[j] = p[lane + 32 * j]; ss += v[j] * v[j]; }
#pragma unroll
    for (int s = 16; s; s >>= 1) ss += __shfl_xor_sync(0xffffffffu, ss, s);
    float r = 1.0f / fmaxf(sqrtf(ss), 1e-12f);
    float* q = out + (size_t)row * 128;
#pragma unroll
    for (int j = 0; j < 4; j++) q[lane + 32 * j] += v[j] * r;
}

// ---------------- x = LN(relu(acc * invr)) * g + b --------------------------
__global__ void relu_ln_k(const float* __restrict__ acc, float invr,
                          const float* __restrict__ gg, const float* __restrict__ bb,
                          float* __restrict__ xout, int M) {
    int row = blockIdx.x * 8 + (threadIdx.x >> 5);
    if (row >= M) return;
    int lane = threadIdx.x & 31;
    const float* p = acc + (size_t)row * 128;
    float v[4]; float s = 0.0f;
#pragma unroll
    for (int j = 0; j < 4; j++) { v[j] = fmaxf(p[lane + 32 * j] * invr, 0.0f); s += v[j]; }
#pragma unroll
    for (int o = 16; o; o >>= 1) s += __shfl_xor_sync(0xffffffffu, s, o);
    float m = s * (1.0f / 128.0f);
    float ss = 0.0f;
#pragma unroll
    for (int j = 0; j < 4; j++) { float d = v[j] - m; ss += d * d; }
#pragma unroll
    for (int o = 16; o; o >>= 1) ss += __shfl_xor_sync(0xffffffffu, ss, o);
    float inv = rsqrtf(ss * (1.0f / 128.0f) + 1e-5f);
    float* q = xout + (size_t)row * 128;
#pragma unroll
    for (int j = 0; j < 4; j++) {
        int c = lane + 32 * j;
        q[c] = (v[j] - m) * inv * gg[c] + bb[c];
    }
}

// ---------------- BatchNorm eval (running stats mean=0, var=1) --------------
__global__ void bn_k(float* __restrict__ h, const float* __restrict__ g,
                     const float* __restrict__ b, long long total) {
    long long idx = (long long)blockIdx.x * 256 + threadIdx.x;
    if (idx >= total) return;
    int c = (int)(idx & 127);
    float inv = rsqrtf(1.0f + 1e-5f);
    h[idx] = h[idx] * (g[c] * inv) + b[c];
}

// ---------------- host-side GEMM dispatch ----------------------------------
static inline void gemm(const float* A, const float* W, const float* bias, float* C,
                        int M, int K, int N, float alpha, bool relu, bool accum) {
    dim3 grid((M + 63) / 64);
#define GL(NV)                                                                       \
    do {                                                                             \
        if (relu && accum)  gemm_k<NV, true,  true ><<<grid, 256>>>(A, W, bias, C, M, K, alpha); \
        else if (relu)      gemm_k<NV, true,  false><<<grid, 256>>>(A, W, bias, C, M, K, alpha); \
        else if (accum)     gemm_k<NV, false, true ><<<grid, 256>>>(A, W, bias, C, M, K, alpha); \
        else                gemm_k<NV, false, false><<<grid, 256>>>(A, W, bias, C, M, K, alpha); \
    } while (0)
    if (N == 32)      GL(32);
    else if (N == 64) GL(64);
    else              GL(128);
#undef GL
}

extern "C" void kernel_launch(void* const* d_in, const int* in_sizes, int n_in,
                              void* d_out, int out_size) {
    const float* x_note = (const float*)d_in[0];
    const float* x_beat = (const float*)d_in[1];
    const int* e[5] = {(const int*)d_in[2], (const int*)d_in[3], (const int*)d_in[4],
                       (const int*)d_in[5], (const int*)d_in[6]};
    int E[5];
    for (int r = 0; r < 5; r++) E[r] = in_sizes[2 + r] / 2;
    const float* proj_W = (const float*)d_in[7];
    const float* proj_b = (const float*)d_in[8];
    const float* l0_Wl  = (const float*)d_in[9];
    const float* l0_bl  = (const float*)d_in[10];
    const float* l0_Wr  = (const float*)d_in[11];
    const float* Wl     = (const float*)d_in[12];
    const float* bl     = (const float*)d_in[13];
    const float* Wr     = (const float*)d_in[14];
    const float* ln_g   = (const float*)d_in[15];
    const float* ln_b   = (const float*)d_in[16];
    const float* mlp_W1 = (const float*)d_in[17];
    const float* mlp_b1 = (const float*)d_in[18];
    const float* bn_g   = (const float*)d_in[19];
    const float* bn_b   = (const float*)d_in[20];
    const float* mlp_W2 = (const float*)d_in[21];
    const float* mlp_b2 = (const float*)d_in[22];

    float *xn0, *xn1, *xb0, *xb1, *agg, *proj, *orb, *outn, *outb;
    float* cnt[5];
    cudaGetSymbolAddress((void**)&xn0,  g_xn0);
    cudaGetSymbolAddress((void**)&xn1,  g_xn1);
    cudaGetSymbolAddress((void**)&xb0,  g_xb0);
    cudaGetSymbolAddress((void**)&xb1,  g_xb1);
    cudaGetSymbolAddress((void**)&agg,  g_agg);
    cudaGetSymbolAddress((void**)&proj, g_proj);
    cudaGetSymbolAddress((void**)&orb,  g_or);
    cudaGetSymbolAddress((void**)&outn, g_outn);
    cudaGetSymbolAddress((void**)&outb, g_outb);
    cudaGetSymbolAddress((void**)&cnt[0], g_cnt0);
    cudaGetSymbolAddress((void**)&cnt[1], g_cnt1);
    cudaGetSymbolAddress((void**)&cnt[2], g_cnt2);
    cudaGetSymbolAddress((void**)&cnt[3], g_cnt3);
    cudaGetSymbolAddress((void**)&cnt[4], g_cnt4);

    const int st[5] = {0, 0, 0, 1, 1};   // src type: 0=note, 1=beat
    const int dt[5] = {0, 0, 1, 0, 1};   // dst type
    const int nsz[2] = {NN, NB};

    // edge dtype detection (e_onset is large enough for 64-word probe)
    detect_mode_k<<<1, 1>>>(e[0]);

    // per-relation dst-degree counts (layer-invariant)
    for (int r = 0; r < 5; r++) {
        int dn = nsz[dt[r]];
        cudaMemsetAsync(cnt[r], 0, (size_t)dn * sizeof(float));
        count_k<<<(E[r] + 255) / 256, 256>>>(e[r], E[r], cnt[r]);
    }

    // ==================== layer 0 (in 64 -> out 128) ====================
    const float* xin[2] = {x_note, x_beat};
    cudaMemsetAsync(outn, 0, (size_t)NN * HID * sizeof(float));
    cudaMemsetAsync(outb, 0, (size_t)NB * HID * sizeof(float));
    for (int r = 0; r < 5; r++) {
        int sn = nsz[st[r]], dn = nsz[dt[r]];
        const float* xs = xin[st[r]];
        const float* xd = xin[dt[r]];
        float* outd = (dt[r] == 0) ? outn : outb;
        // SAGEConv project=True: xs' = relu(xs @ proj_W[r] + proj_b[r])
        gemm(xs, proj_W + (size_t)r * INC * INC, proj_b + (size_t)r * INC,
             proj, sn, INC, INC, 1.0f, true, false);
        // seg-mean aggregate
        cudaMemsetAsync(agg, 0, (size_t)dn * INC * sizeof(float));
        long long tot = (long long)E[r] * (INC / 4);
        agg_k<<<(unsigned)((tot + 255) / 256), 256>>>(proj, e[r], E[r], INC, agg);
        long long dtot = (long long)dn * INC;
        scale_k<<<(unsigned)((dtot + 255) / 256), 256>>>(agg, cnt[r], dtot, INC);
        // o = agg @ Wl + bl + xd @ Wr ; then l2norm, accumulated into outd
        gemm(agg, l0_Wl + (size_t)r * INC * HID, l0_bl + (size_t)r * HID,
             orb, dn, INC, HID, 1.0f, false, false);
        gemm(xd, l0_Wr + (size_t)r * INC * HID, nullptr,
             orb, dn, INC, HID, 1.0f, false, true);
        l2norm_acc_k<<<(dn + 7) / 8, 256>>>(orb, outd, dn);
    }
    relu_ln_k<<<(NN + 7) / 8, 256>>>(outn, 1.0f / 3.0f, ln_g, ln_b, xn0, NN);
    relu_ln_k<<<(NB + 7) / 8, 256>>>(outb, 1.0f / 2.0f, ln_g, ln_b, xb0, NB);

    // ==================== layers 1,2 (128 -> 128) ====================
    float* curn = xn0; float* curb = xb0;
    float* nxtn = xn1; float* nxtb = xb1;
    for (int L = 1; L < 3; L++) {
        bool last = (L == 2);
        cudaMemsetAsync(outn, 0, (size_t)NN * HID * sizeof(float));
        if (!last) cudaMemsetAsync(outb, 0, (size_t)NB * HID * sizeof(float));
        for (int r = 0; r < 5; r++) {
            if (last && dt[r] == 1) continue;   // beat output of last layer is dead
            int dn = nsz[dt[r]];
            const float* xs = (st[r] == 0) ? curn : curb;
            const float* xd = (dt[r] == 0) ? curn : curb;
            float* outd = (dt[r] == 0) ? outn : outb;
            cudaMemsetAsync(agg, 0, (size_t)dn * HID * sizeof(float));
            long long tot = (long long)E[r] * (HID / 4);
            agg_k<<<(unsigned)((tot + 255) / 256), 256>>>(xs, e[r], E[r], HID, agg);
            long long dtot = (long long)dn * HID;
            scale_k<<<(unsigned)((dtot + 255) / 256), 256>>>(agg, cnt[r], dtot, HID);
            const float* WlL = Wl + ((size_t)(L - 1) * 5 + r) * HID * HID;
            const float* blL = bl + ((size_t)(L - 1) * 5 + r) * HID;
            const float* WrL = Wr + ((size_t)(L - 1) * 5 + r) * HID * HID;
            gemm(agg, WlL, blL,    outd, dn, HID, HID, 1.0f, false, true);
            gemm(xd,  WrL, nullptr, outd, dn, HID, HID, 1.0f, false, true);
        }
        if (!last) {
            relu_ln_k<<<(NN + 7) / 8, 256>>>(outn, 1.0f / 3.0f,
                                             ln_g + (size_t)L * HID, ln_b + (size_t)L * HID, nxtn, NN);
            relu_ln_k<<<(NB + 7) / 8, 256>>>(outb, 1.0f / 2.0f,
                                             ln_g + (size_t)L * HID, ln_b + (size_t)L * HID, nxtb, NB);
            float* t;
            t = curn; curn = nxtn; nxtn = t;
            t = curb; curb = nxtb; nxtb = t;
        }
    }

    // ==================== final MLP on note (outn still needs /3) ============
    // h = relu((outn/3) @ W1 + b1)   -- the /3 folded into alpha
    gemm(outn, mlp_W1, mlp_b1, orb, NN, HID, HID, 1.0f / 3.0f, true, false);
    long long htot = (long long)NN * HID;
    bn_k<<<(unsigned)((htot + 255) / 256), 256>>>(orb, bn_g, bn_b, htot);
    gemm(orb, mlp_W2, mlp_b2, (float*)d_out, NN, HID, 32, 1.0f, false, false);
}

// round 2
// speedup vs baseline: 1.9515x; 1.9515x over previous
#include <cuda_runtime.h>

#define NN 100000
#define NB 20000
#define INC 64
#define HID 128

// ---------------- scratch (device globals; no runtime allocation) ----------
__device__ float g_pn  [(size_t)NN * 192];   // projected note feats (3 rel blocks)
__device__ float g_pb  [(size_t)NB * 128];   // projected beat feats (2 rel blocks)
__device__ float g_aggn[(size_t)NN * 384];   // concat agg, note dst
__device__ float g_aggb[(size_t)NB * 256];   // concat agg, beat dst
__device__ float g_On  [(size_t)NN * 384];   // layer0 per-rel o (note) / MLP hidden
__device__ float g_Ob  [(size_t)NB * 256];   // layer0 per-rel o (beat)
__device__ float g_xn0 [(size_t)NN * HID];
__device__ float g_xn1 [(size_t)NN * HID];
__device__ float g_xb0 [(size_t)NB * HID];
__device__ float g_xb1 [(size_t)NB * HID];
__device__ float g_outn[(size_t)NN * HID];
__device__ float g_outb[(size_t)NB * HID];
__device__ float g_cnt [5][NN];
__device__ int   g_emode;

// weight scratch
__device__ float g_projCatN[64 * 192];
__device__ float g_projCatB[64 * 128];
__device__ float g_pbCatN[192];
__device__ float g_pbCatB[128];
__device__ float g_l0WrCatN[64 * 384];
__device__ float g_l0WrCatB[64 * 256];
__device__ float g_l0blCatN[384];
__device__ float g_l0blCatB[256];
__device__ float g_Wl1CatN[384 * 128];
__device__ float g_Wl1CatB[256 * 128];
__device__ float g_Wl2CatN[384 * 128];
__device__ float g_Wr1SumN[128 * 128];
__device__ float g_Wr1SumB[128 * 128];
__device__ float g_Wr2SumN[128 * 128];
__device__ float g_b1SumN[128];
__device__ float g_b1SumB[128];
__device__ float g_b2SumN[128];
__device__ float g_bnS[128];

// ---------------- edge dtype detection -------------------------------------
__global__ void detect_mode_k(const int* e) {
    int z = 1;
    for (int i = 1; i < 64; i += 2)
        if (e[i] != 0) z = 0;
    g_emode = z;
}
__device__ __forceinline__ int edge_at(const int* e, long long i) {
    if (g_emode) return (int)((const long long*)e)[i];
    return e[i];
}

// ---------------- edge count per dst + inversion ----------------------------
__global__ void count_k(const int* __restrict__ e, int E, float* __restrict__ cnt) {
    int i = blockIdx.x * 256 + threadIdx.x;
    if (i >= E) return;
    int d = edge_at(e, (long long)E + i);
    atomicAdd(&cnt[d], 1.0f);
}
__global__ void inv_k(float* __restrict__ c, int n) {
    int i = blockIdx.x * 256 + threadIdx.x;
    if (i < n) c[i] = 1.0f / fmaxf(c[i], 1.0f);
}

// ---------------- scaled scatter-add aggregation ----------------------------
// gathers src rows (with col offset in a concat buffer), scales by 1/deg(dst),
// scatter-adds into a concat dst buffer -> directly produces seg-mean blocks.
__global__ void agg_k(const float* __restrict__ xf, int lds, int soff,
                      const int* __restrict__ e, int E, int c4shift,
                      const float* __restrict__ invc,
                      float* __restrict__ agg, int ldd, int doff) {
    long long idx = (long long)blockIdx.x * 256 + threadIdx.x;
    long long total = (long long)E << c4shift;
    if (idx >= total) return;
    int edge = (int)(idx >> c4shift);
    int ch   = (int)(idx & ((1 << c4shift) - 1));
    int s = edge_at(e, edge);
    int d = edge_at(e, (long long)E + edge);
    float inv = invc[d];
    float4 v = *reinterpret_cast<const float4*>(xf + (size_t)s * lds + soff + ch * 4);
    float* p = agg + (size_t)d * ldd + doff + ch * 4;
    atomicAdd(p + 0, v.x * inv);
    atomicAdd(p + 1, v.y * inv);
    atomicAdd(p + 2, v.z * inv);
    atomicAdd(p + 3, v.w * inv);
}

// ---------------- register-blocked 128x128 GEMM ------------------------------
// C[m, coff+n] {=,+=} act(alpha*(A@B) + bias[n]) [then *bnS[n]+bnB[n]]
template <bool RELU, bool ACCUM, bool BN>
__global__ __launch_bounds__(256, 2) void gemm128_k(
    const float* __restrict__ A, int lda,
    const float* __restrict__ B, int ldb,
    const float* __restrict__ bias,
    float* __restrict__ C, int ldc, int coff,
    int M, int N, int K, float alpha,
    const float* __restrict__ bnS, const float* __restrict__ bnB)
{
    __shared__ float As[16][136];
    __shared__ float Bs[16][132];
    int tid = threadIdx.x;
    int tx = tid & 15, ty = tid >> 4;
    int m0 = blockIdx.x * 128;
    int n0 = blockIdx.y * 128;
    float acc[8][8];
#pragma unroll
    for (int i = 0; i < 8; i++)
#pragma unroll
        for (int j = 0; j < 8; j++) acc[i][j] = 0.0f;

    int arow = tid >> 2, ac4 = tid & 3;        // A: 64 rows per half, 4 float4/row-tile
    int brow = tid >> 5, bcol = (tid & 31) * 4; // B: 8 rows per half

    for (int k0 = 0; k0 < K; k0 += 16) {
#pragma unroll
        for (int h = 0; h < 2; h++) {
            int r = arow + h * 64;
            int m = m0 + r;
            float4 v = make_float4(0.f, 0.f, 0.f, 0.f);
            if (m < M) v = *(const float4*)(A + (size_t)m * lda + k0 + ac4 * 4);
            As[ac4 * 4 + 0][r] = v.x;
            As[ac4 * 4 + 1][r] = v.y;
            As[ac4 * 4 + 2][r] = v.z;
            As[ac4 * 4 + 3][r] = v.w;
        }
#pragma unroll
        for (int h = 0; h < 2; h++) {
            int r = brow + h * 8;
            float4 v = make_float4(0.f, 0.f, 0.f, 0.f);
            if (n0 + bcol < N) v = *(const float4*)(B + (size_t)(k0 + r) * ldb + n0 + bcol);
            *(float4*)&Bs[r][bcol] = v;
        }
        __syncthreads();
#pragma unroll
        for (int kk = 0; kk < 16; kk++) {
            float a[8], b[8];
            *(float4*)&a[0] = *(const float4*)&As[kk][ty * 8];
            *(float4*)&a[4] = *(const float4*)&As[kk][ty * 8 + 4];
            *(float4*)&b[0] = *(const float4*)&Bs[kk][tx * 8];
            *(float4*)&b[4] = *(const float4*)&Bs[kk][tx * 8 + 4];
#pragma unroll
            for (int i = 0; i < 8; i++)
#pragma unroll
                for (int j = 0; j < 8; j++)
                    acc[i][j] += a[i] * b[j];
        }
        __syncthreads();
    }
#pragma unroll
    for (int i = 0; i < 8; i++) {
        int m = m0 + ty * 8 + i;
        if (m < M) {
#pragma unroll
            for (int j = 0; j < 8; j++) {
                int n = n0 + tx * 8 + j;
                if (n < N) {
                    float v = acc[i][j] * alpha;
                    if (bias) v += bias[n];
                    size_t o = (size_t)m * ldc + coff + n;
                    if (ACCUM) v += C[o];
                    if (RELU) v = fmaxf(v, 0.0f);
                    if (BN) v = v * bnS[n] + bnB[n];
                    C[o] = v;
                }
            }
        }
    }
}

// ---------------- layer0 post: mean_r(l2norm(o_r)) -> relu -> LN ------------
template <int R>
__global__ void l0post_k(const float* __restrict__ O, int ldo,
                         const float* __restrict__ gg, const float* __restrict__ bb,
                         float* __restrict__ xout, int M) {
    int row = blockIdx.x * 8 + (threadIdx.x >> 5);
    if (row >= M) return;
    int lane = threadIdx.x & 31;
    float acc[4] = {0.f, 0.f, 0.f, 0.f};
#pragma unroll
    for (int rb = 0; rb < R; rb++) {
        const float* p = O + (size_t)row * ldo + rb * 128;
        float v[4]; float ss = 0.f;
#pragma unroll
        for (int j = 0; j < 4; j++) { v[j] = p[lane + 32 * j]; ss += v[j] * v[j]; }
#pragma unroll
        for (int s = 16; s; s >>= 1) ss += __shfl_xor_sync(0xffffffffu, ss, s);
        float inv = 1.0f / fmaxf(sqrtf(ss), 1e-12f);
#pragma unroll
        for (int j = 0; j < 4; j++) acc[j] += v[j] * inv;
    }
    const float invR = 1.0f / R;
    float s = 0.f;
#pragma unroll
    for (int j = 0; j < 4; j++) { acc[j] = fmaxf(acc[j] * invR, 0.f); s += acc[j]; }
#pragma unroll
    for (int o = 16; o; o >>= 1) s += __shfl_xor_sync(0xffffffffu, s, o);
    float m = s * (1.0f / 128.0f);
    float ss = 0.f;
#pragma unroll
    for (int j = 0; j < 4; j++) { float d = acc[j] - m; ss += d * d; }
#pragma unroll
    for (int o = 16; o; o >>= 1) ss += __shfl_xor_sync(0xffffffffu, ss, o);
    float inv = rsqrtf(ss * (1.0f / 128.0f) + 1e-5f);
    float* q = xout + (size_t)row * 128;
#pragma unroll
    for (int j = 0; j < 4; j++) {
        int c = lane + 32 * j;
        q[c] = (acc[j] - m) * inv * gg[c] + bb[c];
    }
}

// ---------------- x = LN(relu(acc*invr)) * g + b ----------------------------
__global__ void relu_ln_k(const float* __restrict__ acc, float invr,
                          const float* __restrict__ gg, const float* __restrict__ bb,
                          float* __restrict__ xout, int M) {
    int row = blockIdx.x * 8 + (threadIdx.x >> 5);
    if (row >= M) return;
    int lane = threadIdx.x & 31;
    const float* p = acc + (size_t)row * 128;
    float v[4]; float s = 0.f;
#pragma unroll
    for (int j = 0; j < 4; j++) { v[j] = fmaxf(p[lane + 32 * j] * invr, 0.f); s += v[j]; }
#pragma unroll
    for (int o = 16; o; o >>= 1) s += __shfl_xor_sync(0xffffffffu, s, o);
    float m = s * (1.0f / 128.0f);
    float ss = 0.f;
#pragma unroll
    for (int j = 0; j < 4; j++) { float d = v[j] - m; ss += d * d; }
#pragma unroll
    for (int o = 16; o; o >>= 1) ss += __shfl_xor_sync(0xffffffffu, ss, o);
    float inv = rsqrtf(ss * (1.0f / 128.0f) + 1e-5f);
    float* q = xout + (size_t)row * 128;
#pragma unroll
    for (int j = 0; j < 4; j++) {
        int c = lane + 32 * j;
        q[c] = (v[j] - m) * inv * gg[c] + bb[c];
    }
}

// ---------------- weight prep kernels ---------------------------------------
// column-concat: dst[k][j*C+c] = src[r_j][k][c]
__global__ void catW_k(float* __restrict__ dst, const float* __restrict__ src,
                       int r0, int r1, int r2, int nrel, int K, int C) {
    int idx = blockIdx.x * 256 + threadIdx.x;
    int tot = nrel * K * C;
    if (idx >= tot) return;
    int j = idx / (K * C);
    int rem = idx - j * K * C;
    int k = rem / C, c = rem - (rem / C) * C;
    int r = (j == 0) ? r0 : (j == 1) ? r1 : r2;
    dst[(size_t)k * (nrel * C) + j * C + c] = src[(size_t)r * K * C + (size_t)k * C + c];
}
// row-stack: dst = [src[r0]; src[r1]; src[r2]]  (blocks of `blk` floats)
__global__ void stack_k(float* __restrict__ dst, const float* __restrict__ src,
                        int r0, int r1, int r2, int nrel, int blk) {
    int idx = blockIdx.x * 256 + threadIdx.x;
    if (idx >= nrel * blk) return;
    int j = idx / blk, i = idx - j * blk;
    int r = (j == 0) ? r0 : (j == 1) ? r1 : r2;
    dst[idx] = src[(size_t)r * blk + i];
}
// sum: dst = src[r0] + src[r1] (+ src[r2])
__global__ void sumW_k(float* __restrict__ dst, const float* __restrict__ src,
                       int r0, int r1, int r2, int nrel, int blk) {
    int idx = blockIdx.x * 256 + threadIdx.x;
    if (idx >= blk) return;
    float v = src[(size_t)r0 * blk + idx] + src[(size_t)r1 * blk + idx];
    if (nrel == 3) v += src[(size_t)r2 * blk + idx];
    dst[idx] = v;
}
__global__ void bnprep_k(float* __restrict__ sc, const float* __restrict__ g) {
    int i = threadIdx.x;
    sc[i] = g[i] * rsqrtf(1.0f + 1e-5f);
}

// ---------------- host dispatch ---------------------------------------------
static void gemm(const float* A, int lda, const float* B, int ldb, const float* bias,
                 float* C, int ldc, int coff, int M, int N, int K, float alpha,
                 bool relu, bool accum, const float* bnS, const float* bnB) {
    dim3 grid((M + 127) / 128, (N + 127) / 128);
    if (bnS)
        gemm128_k<true, false, true><<<grid, 256>>>(A, lda, B, ldb, bias, C, ldc, coff, M, N, K, alpha, bnS, bnB);
    else if (relu && !accum)
        gemm128_k<true, false, false><<<grid, 256>>>(A, lda, B, ldb, bias, C, ldc, coff, M, N, K, alpha, nullptr, nullptr);
    else if (accum)
        gemm128_k<false, true, false><<<grid, 256>>>(A, lda, B, ldb, bias, C, ldc, coff, M, N, K, alpha, nullptr, nullptr);
    else
        gemm128_k<false, false, false><<<grid, 256>>>(A, lda, B, ldb, bias, C, ldc, coff, M, N, K, alpha, nullptr, nullptr);
}

extern "C" void kernel_launch(void* const* d_in, const int* in_sizes, int n_in,
                              void* d_out, int out_size) {
    const float* x_note = (const float*)d_in[0];
    const float* x_beat = (const float*)d_in[1];
    const int* e[5] = {(const int*)d_in[2], (const int*)d_in[3], (const int*)d_in[4],
                       (const int*)d_in[5], (const int*)d_in[6]};
    int E[5];
    for (int r = 0; r < 5; r++) E[r] = in_sizes[2 + r] / 2;
    const float* proj_W = (const float*)d_in[7];
    const float* proj_b = (const float*)d_in[8];
    const float* l0_Wl  = (const float*)d_in[9];
    const float* l0_bl  = (const float*)d_in[10];
    const float* l0_Wr  = (const float*)d_in[11];
    const float* Wl     = (const float*)d_in[12];
    const float* bl     = (const float*)d_in[13];
    const float* Wr     = (const float*)d_in[14];
    const float* ln_g   = (const float*)d_in[15];
    const float* ln_b   = (const float*)d_in[16];
    const float* mlp_W1 = (const float*)d_in[17];
    const float* mlp_b1 = (const float*)d_in[18];
    const float* bn_g   = (const float*)d_in[19];
    const float* bn_b   = (const float*)d_in[20];
    const float* mlp_W2 = (const float*)d_in[21];
    const float* mlp_b2 = (const float*)d_in[22];

    float *pn, *pb, *aggn, *aggb, *On, *Ob, *xn0, *xn1, *xb0, *xb1, *outn, *outb, *cnt;
    float *projCatN, *projCatB, *pbCatN, *pbCatB, *l0WrCatN, *l0WrCatB, *l0blCatN, *l0blCatB;
    float *Wl1CatN, *Wl1CatB, *Wl2CatN, *Wr1SumN, *Wr1SumB, *Wr2SumN, *b1SumN, *b1SumB, *b2SumN, *bnS;
    cudaGetSymbolAddress((void**)&pn, g_pn);       cudaGetSymbolAddress((void**)&pb, g_pb);
    cudaGetSymbolAddress((void**)&aggn, g_aggn);   cudaGetSymbolAddress((void**)&aggb, g_aggb);
    cudaGetSymbolAddress((void**)&On, g_On);       cudaGetSymbolAddress((void**)&Ob, g_Ob);
    cudaGetSymbolAddress((void**)&xn0, g_xn0);     cudaGetSymbolAddress((void**)&xn1, g_xn1);
    cudaGetSymbolAddress((void**)&xb0, g_xb0);     cudaGetSymbolAddress((void**)&xb1, g_xb1);
    cudaGetSymbolAddress((void**)&outn, g_outn);   cudaGetSymbolAddress((void**)&outb, g_outb);
    cudaGetSymbolAddress((void**)&cnt, g_cnt);
    cudaGetSymbolAddress((void**)&projCatN, g_projCatN); cudaGetSymbolAddress((void**)&projCatB, g_projCatB);
    cudaGetSymbolAddress((void**)&pbCatN, g_pbCatN);     cudaGetSymbolAddress((void**)&pbCatB, g_pbCatB);
    cudaGetSymbolAddress((void**)&l0WrCatN, g_l0WrCatN); cudaGetSymbolAddress((void**)&l0WrCatB, g_l0WrCatB);
    cudaGetSymbolAddress((void**)&l0blCatN, g_l0blCatN); cudaGetSymbolAddress((void**)&l0blCatB, g_l0blCatB);
    cudaGetSymbolAddress((void**)&Wl1CatN, g_Wl1CatN);   cudaGetSymbolAddress((void**)&Wl1CatB, g_Wl1CatB);
    cudaGetSymbolAddress((void**)&Wl2CatN, g_Wl2CatN);
    cudaGetSymbolAddress((void**)&Wr1SumN, g_Wr1SumN);   cudaGetSymbolAddress((void**)&Wr1SumB, g_Wr1SumB);
    cudaGetSymbolAddress((void**)&Wr2SumN, g_Wr2SumN);
    cudaGetSymbolAddress((void**)&b1SumN, g_b1SumN);     cudaGetSymbolAddress((void**)&b1SumB, g_b1SumB);
    cudaGetSymbolAddress((void**)&b2SumN, g_b2SumN);     cudaGetSymbolAddress((void**)&bnS, g_bnS);

    const int dt[5] = {0, 0, 1, 0, 1};
    const int nsz[2] = {NN, NB};

    detect_mode_k<<<1, 1>>>(e[0]);

    // degree counts -> inverted
    for (int r = 0; r < 5; r++) {
        int dn = nsz[dt[r]];
        cudaMemsetAsync(cnt + (size_t)r * NN, 0, (size_t)dn * sizeof(float));
        count_k<<<(E[r] + 255) / 256, 256>>>(e[r], E[r], cnt + (size_t)r * NN);
        inv_k<<<(dn + 255) / 256, 256>>>(cnt + (size_t)r * NN, dn);
    }
    float* ic[5];
    for (int r = 0; r < 5; r++) ic[r] = cnt + (size_t)r * NN;

    // ---- weight prep (tiny) ----
    catW_k<<<(3 * 64 * 64 + 255) / 256, 256>>>(projCatN, proj_W, 0, 1, 2, 3, 64, 64);
    catW_k<<<(2 * 64 * 64 + 255) / 256, 256>>>(projCatB, proj_W, 3, 4, 0, 2, 64, 64);
    catW_k<<<1, 256>>>(pbCatN, proj_b, 0, 1, 2, 3, 1, 64);
    catW_k<<<1, 256>>>(pbCatB, proj_b, 3, 4, 0, 2, 1, 64);
    catW_k<<<(3 * 64 * 128 + 255) / 256, 256>>>(l0WrCatN, l0_Wr, 0, 1, 3, 3, 64, 128);
    catW_k<<<(2 * 64 * 128 + 255) / 256, 256>>>(l0WrCatB, l0_Wr, 2, 4, 0, 2, 64, 128);
    catW_k<<<2, 256>>>(l0blCatN, l0_bl, 0, 1, 3, 3, 1, 128);
    catW_k<<<1, 256>>>(l0blCatB, l0_bl, 2, 4, 0, 2, 1, 128);
    stack_k<<<(3 * 16384 + 255) / 256, 256>>>(Wl1CatN, Wl, 0, 1, 3, 3, 16384);
    stack_k<<<(2 * 16384 + 255) / 256, 256>>>(Wl1CatB, Wl, 2, 4, 0, 2, 16384);
    stack_k<<<(3 * 16384 + 255) / 256, 256>>>(Wl2CatN, Wl + 5 * 16384, 0, 1, 3, 3, 16384);
    sumW_k<<<64, 256>>>(Wr1SumN, Wr, 0, 1, 3, 3, 16384);
    sumW_k<<<64, 256>>>(Wr1SumB, Wr, 2, 4, 0, 2, 16384);
    sumW_k<<<64, 256>>>(Wr2SumN, Wr + 5 * 16384, 0, 1, 3, 3, 16384);
    sumW_k<<<1, 128>>>(b1SumN, bl, 0, 1, 3, 3, 128);
    sumW_k<<<1, 128>>>(b1SumB, bl, 2, 4, 0, 2, 128);
    sumW_k<<<1, 128>>>(b2SumN, bl + 5 * 128, 0, 1, 3, 3, 128);
    bnprep_k<<<1, 128>>>(bnS, bn_g);

    // ==================== layer 0 (64 -> 128) ====================
    // projections (N-concat over relations)
    gemm(x_note, 64, projCatN, 192, pbCatN, pn, 192, 0, NN, 192, 64, 1.f, true, false, nullptr, nullptr);
    gemm(x_beat, 64, projCatB, 128, pbCatB, pb, 128, 0, NB, 128, 64, 1.f, true, false, nullptr, nullptr);
    // seg-mean aggregation into concat buffers (C=64 per relation, shift=4)
    cudaMemsetAsync(aggn, 0, (size_t)NN * 192 * sizeof(float));
    cudaMemsetAsync(aggb, 0, (size_t)NB * 128 * sizeof(float));
    {
        long long t0 = (long long)E[0] << 4;
        agg_k<<<(unsigned)((t0 + 255) / 256), 256>>>(pn, 192, 0,   e[0], E[0], 4, ic[0], aggn, 192, 0);
        long long t1 = (long long)E[1] << 4;
        agg_k<<<(unsigned)((t1 + 255) / 256), 256>>>(pn, 192, 64,  e[1], E[1], 4, ic[1], aggn, 192, 64);
        long long t3 = (long long)E[3] << 4;
        agg_k<<<(unsigned)((t3 + 255) / 256), 256>>>(pb, 128, 0,   e[3], E[3], 4, ic[3], aggn, 192, 128);
        long long t2 = (long long)E[2] << 4;
        agg_k<<<(unsigned)((t2 + 255) / 256), 256>>>(pn, 192, 128, e[2], E[2], 4, ic[2], aggb, 128, 0);
        long long t4 = (long long)E[4] << 4;
        agg_k<<<(unsigned)((t4 + 255) / 256), 256>>>(pb, 128, 64,  e[4], E[4], 4, ic[4], aggb, 128, 64);
    }
    // o_r = xd @ Wr_r (N-concat, writes all blocks + bias) then += agg_r @ Wl_r
    gemm(x_note, 64, l0WrCatN, 384, l0blCatN, On, 384, 0, NN, 384, 64, 1.f, false, false, nullptr, nullptr);
    gemm(x_beat, 64, l0WrCatB, 256, l0blCatB, Ob, 256, 0, NB, 256, 64, 1.f, false, false, nullptr, nullptr);
    const int relN[3] = {0, 1, 3};
    for (int j = 0; j < 3; j++)
        gemm(aggn + j * 64, 192, l0_Wl + (size_t)relN[j] * 64 * 128, 128, nullptr,
             On, 384, j * 128, NN, 128, 64, 1.f, false, true, nullptr, nullptr);
    const int relB[2] = {2, 4};
    for (int j = 0; j < 2; j++)
        gemm(aggb + j * 64, 128, l0_Wl + (size_t)relB[j] * 64 * 128, 128, nullptr,
             Ob, 256, j * 128, NB, 128, 64, 1.f, false, true, nullptr, nullptr);
    // mean_r(l2norm(o_r)) -> relu -> LN
    l0post_k<3><<<(NN + 7) / 8, 256>>>(On, 384, ln_g, ln_b, xn0, NN);
    l0post_k<2><<<(NB + 7) / 8, 256>>>(Ob, 256, ln_g, ln_b, xb0, NB);

    // ==================== layer 1 (128 -> 128) ====================
    cudaMemsetAsync(aggn, 0, (size_t)NN * 384 * sizeof(float));
    cudaMemsetAsync(aggb, 0, (size_t)NB * 256 * sizeof(float));
    {
        long long t0 = (long long)E[0] << 5;
        agg_k<<<(unsigned)((t0 + 255) / 256), 256>>>(xn0, 128, 0, e[0], E[0], 5, ic[0], aggn, 384, 0);
        long long t1 = (long long)E[1] << 5;
        agg_k<<<(unsigned)((t1 + 255) / 256), 256>>>(xn0, 128, 0, e[1], E[1], 5, ic[1], aggn, 384, 128);
        long long t3 = (long long)E[3] << 5;
        agg_k<<<(unsigned)((t3 + 255) / 256), 256>>>(xb0, 128, 0, e[3], E[3], 5, ic[3], aggn, 384, 256);
        long long t2 = (long long)E[2] << 5;
        agg_k<<<(unsigned)((t2 + 255) / 256), 256>>>(xn0, 128, 0, e[2], E[2], 5, ic[2], aggb, 256, 0);
        long long t4 = (long long)E[4] << 5;
        agg_k<<<(unsigned)((t4 + 255) / 256), 256>>>(xb0, 128, 0, e[4], E[4], 5, ic[4], aggb, 256, 128);
    }
    gemm(aggn, 384, Wl1CatN, 128, b1SumN, outn, 128, 0, NN, 128, 384, 1.f, false, false, nullptr, nullptr);
    gemm(xn0, 128, Wr1SumN, 128, nullptr, outn, 128, 0, NN, 128, 128, 1.f, false, true, nullptr, nullptr);
    gemm(aggb, 256, Wl1CatB, 128, b1SumB, outb, 128, 0, NB, 128, 256, 1.f, false, false, nullptr, nullptr);
    gemm(xb0, 128, Wr1SumB, 128, nullptr, outb, 128, 0, NB, 128, 128, 1.f, false, true, nullptr, nullptr);
    relu_ln_k<<<(NN + 7) / 8, 256>>>(outn, 1.f / 3.f, ln_g + 128, ln_b + 128, xn1, NN);
    relu_ln_k<<<(NB + 7) / 8, 256>>>(outb, 1.f / 2.f, ln_g + 128, ln_b + 128, xb1, NB);

    // ==================== layer 2 (note dst only) ====================
    cudaMemsetAsync(aggn, 0, (size_t)NN * 384 * sizeof(float));
    {
        long long t0 = (long long)E[0] << 5;
        agg_k<<<(unsigned)((t0 + 255) / 256), 256>>>(xn1, 128, 0, e[0], E[0], 5, ic[0], aggn, 384, 0);
        long long t1 = (long long)E[1] << 5;
        agg_k<<<(unsigned)((t1 + 255) / 256), 256>>>(xn1, 128, 0, e[1], E[1], 5, ic[1], aggn, 384, 128);
        long long t3 = (long long)E[3] << 5;
        agg_k<<<(unsigned)((t3 + 255) / 256), 256>>>(xb1, 128, 0, e[3], E[3], 5, ic[3], aggn, 384, 256);
    }
    gemm(aggn, 384, Wl2CatN, 128, b2SumN, outn, 128, 0, NN, 128, 384, 1.f, false, false, nullptr, nullptr);
    gemm(xn1, 128, Wr2SumN, 128, nullptr, outn, 128, 0, NN, 128, 128, 1.f, false, true, nullptr, nullptr);

    // ==================== final MLP (BN folded into epilogue) ====================
    gemm(outn, 128, mlp_W1, 128, mlp_b1, On, 128, 0, NN, 128, 128, 1.f / 3.f, true, false, bnS, bn_b);
    gemm(On, 128, mlp_W2, 32, mlp_b2, (float*)d_out, 32, 0, NN, 32, 128, 1.f, false, false, nullptr, nullptr);
}

// round 3
// speedup vs baseline: 2.4909x; 1.2764x over previous
#include <cuda_runtime.h>

#define NN 100000
#define NB 20000
#define INC 64
#define HID 128
#define NBX 49            // ceil(NN / 2048) scan blocks
#define MAXE 3000000

// ---------------- scratch (device globals; no runtime allocation) ----------
__device__ float g_pn  [(size_t)NN * 192];
__device__ float g_pb  [(size_t)NB * 128];
__device__ float g_aggn[(size_t)NN * 384];
__device__ float g_aggb[(size_t)NB * 256];
__device__ float g_On  [(size_t)NN * 384];
__device__ float g_Ob  [(size_t)NB * 256];
__device__ float g_xn0 [(size_t)NN * HID];
__device__ float g_xn1 [(size_t)NN * HID];
__device__ float g_xb0 [(size_t)NB * HID];
__device__ float g_xb1 [(size_t)NB * HID];
__device__ float g_outn[(size_t)NN * HID];
__device__ float g_outb[(size_t)NB * HID];
__device__ float g_cnt [5][NN];          // 1/deg per dst
__device__ int   g_cnti[5][NN];          // int degree, then reused as fill cursor
__device__ int   g_rowp[5][NN + 1];      // CSR row pointers (per-relation local)
__device__ int   g_bsum[5][64];          // scan partials
__device__ int   g_col [MAXE];           // CSR col indices (src nodes), packed
__device__ int   g_emode;

// weight scratch
__device__ float g_projCatN[64 * 192];
__device__ float g_projCatB[64 * 128];
__device__ float g_pbCatN[192];
__device__ float g_pbCatB[128];
__device__ float g_l0WrCatN[64 * 384];
__device__ float g_l0WrCatB[64 * 256];
__device__ float g_l0blCatN[384];
__device__ float g_l0blCatB[256];
__device__ float g_Wl1CatN[384 * 128];
__device__ float g_Wl1CatB[256 * 128];
__device__ float g_Wl2CatN[384 * 128];
__device__ float g_Wr1SumN[128 * 128];
__device__ float g_Wr1SumB[128 * 128];
__device__ float g_Wr2SumN[128 * 128];
__device__ float g_b1SumN[128];
__device__ float g_b1SumB[128];
__device__ float g_b2SumN[128];
__device__ float g_bnS[128];

// ---------------- edge dtype detection -------------------------------------
__global__ void detect_mode_k(const int* e) {
    int z = 1;
    for (int i = 1; i < 64; i += 2)
        if (e[i] != 0) z = 0;
    g_emode = z;
}
__device__ __forceinline__ int edge_at(const int* e, long long i) {
    if (g_emode) return (int)((const long long*)e)[i];
    return e[i];
}

// ---------------- degree counting / inversion -------------------------------
__global__ void counti_k(const int* __restrict__ e, int E, int* __restrict__ cnt) {
    int i = blockIdx.x * 256 + threadIdx.x;
    if (i >= E) return;
    atomicAdd(&cnt[edge_at(e, (long long)E + i)], 1);
}
__global__ void inv_k(const int* __restrict__ ci, float* __restrict__ cf, int n) {
    int i = blockIdx.x * 256 + threadIdx.x;
    if (i < n) cf[i] = 1.0f / (float)max(ci[i], 1);
}

// ---------------- hierarchical exclusive scan over 5 relations --------------
__global__ void scan1_k() {
    int r = blockIdx.y;
    int n = (r == 2 || r == 4) ? NB : NN;
    int t = threadIdx.x;
    int base = blockIdx.x * 2048 + t * 8;
    int vals[8];
#pragma unroll
    for (int j = 0; j < 8; j++) {
        int idx = base + j;
        vals[j] = (idx < n) ? g_cnti[r][idx] : 0;
    }
    int tot = 0;
#pragma unroll
    for (int j = 0; j < 8; j++) tot += vals[j];
    int lane = t & 31, wid = t >> 5;
    int x = tot;
#pragma unroll
    for (int o = 1; o < 32; o <<= 1) {
        int y = __shfl_up_sync(0xffffffffu, x, o);
        if (lane >= o) x += y;
    }
    __shared__ int wsum[8];
    if (lane == 31) wsum[wid] = x;
    __syncthreads();
    if (t == 0) {
        int run = 0;
#pragma unroll
        for (int i = 0; i < 8; i++) { int v = wsum[i]; wsum[i] = run; run += v; }
        g_bsum[r][blockIdx.x] = run;
    }
    __syncthreads();
    int run = (x - tot) + wsum[wid];
#pragma unroll
    for (int j = 0; j < 8; j++) {
        int idx = base + j;
        if (idx < n) g_rowp[r][idx] = run;
        run += vals[j];
    }
}
__global__ void scan2_k() {
    int r = threadIdx.x;
    if (r >= 5) return;
    int n = (r == 2 || r == 4) ? NB : NN;
    int run = 0;
    for (int i = 0; i < NBX; i++) { int v = g_bsum[r][i]; g_bsum[r][i] = run; run += v; }
    g_rowp[r][n] = run;
}
__global__ void scan3_k() {
    int r = blockIdx.y;
    int n = (r == 2 || r == 4) ? NB : NN;
    int add = g_bsum[r][blockIdx.x];
    int base = blockIdx.x * 2048 + threadIdx.x * 8;
#pragma unroll
    for (int j = 0; j < 8; j++) {
        int idx = base + j;
        if (idx < n) {
            int v = g_rowp[r][idx] + add;
            g_rowp[r][idx] = v;
            g_cnti[r][idx] = v;   // cursor for fill
        }
    }
}
__global__ void fill_k(const int* __restrict__ e, int E, int r, int ebase) {
    int i = blockIdx.x * 256 + threadIdx.x;
    if (i >= E) return;
    int s = edge_at(e, i);
    int d = edge_at(e, (long long)E + i);
    int pos = atomicAdd(&g_cnti[r][d], 1);
    g_col[ebase + pos] = s;
}

// ---------------- CSR seg-mean aggregation (warp per dst row) ---------------
// V floats per lane (V=4 -> 128 channels, V=2 -> 64 channels)
template <int V>
__global__ void aggcsr_k(const float* __restrict__ xf, int lds, int soff,
                         const int* __restrict__ rowp, const int* __restrict__ col,
                         const float* __restrict__ invc,
                         float* __restrict__ agg, int ldd, int doff, int n) {
    int row = blockIdx.x * 8 + (threadIdx.x >> 5);
    if (row >= n) return;
    int lane = threadIdx.x & 31;
    int beg = rowp[row], end = rowp[row + 1];
    float acc[V];
#pragma unroll
    for (int j = 0; j < V; j++) acc[j] = 0.0f;
    int e = beg;
    for (; e + 1 < end; e += 2) {
        int s0 = __ldg(&col[e]);
        int s1 = __ldg(&col[e + 1]);
        const float* p0 = xf + (size_t)s0 * lds + soff + lane * V;
        const float* p1 = xf + (size_t)s1 * lds + soff + lane * V;
        if (V == 4) {
            float4 a = *(const float4*)p0;
            float4 b = *(const float4*)p1;
            acc[0] += a.x + b.x; acc[1] += a.y + b.y;
            acc[2] += a.z + b.z; acc[3] += a.w + b.w;
        } else {
            float2 a = *(const float2*)p0;
            float2 b = *(const float2*)p1;
            acc[0] += a.x + b.x; acc[1] += a.y + b.y;
        }
    }
    if (e < end) {
        int s0 = __ldg(&col[e]);
        const float* p0 = xf + (size_t)s0 * lds + soff + lane * V;
        if (V == 4) {
            float4 a = *(const float4*)p0;
            acc[0] += a.x; acc[1] += a.y; acc[2] += a.z; acc[3] += a.w;
        } else {
            float2 a = *(const float2*)p0;
            acc[0] += a.x; acc[1] += a.y;
        }
    }
    float inv = invc[row];
    float* q = agg + (size_t)row * ldd + doff + lane * V;
    if (V == 4) {
        float4 o = make_float4(acc[0] * inv, acc[1] * inv, acc[2] * inv, acc[3] * inv);
        *(float4*)q = o;
    } else {
        float2 o = make_float2(acc[0] * inv, acc[1] * inv);
        *(float2*)q = o;
    }
}

// ---------------- register-blocked 128x128 GEMM ------------------------------
template <bool RELU, bool ACCUM, bool BN>
__global__ __launch_bounds__(256, 2) void gemm128_k(
    const float* __restrict__ A, int lda,
    const float* __restrict__ B, int ldb,
    const float* __restrict__ bias,
    float* __restrict__ C, int ldc, int coff,
    int M, int N, int K, float alpha,
    const float* __restrict__ bnS, const float* __restrict__ bnB)
{
    __shared__ float As[16][136];
    __shared__ float Bs[16][132];
    int tid = threadIdx.x;
    int tx = tid & 15, ty = tid >> 4;
    int m0 = blockIdx.x * 128;
    int n0 = blockIdx.y * 128;
    float acc[8][8];
#pragma unroll
    for (int i = 0; i < 8; i++)
#pragma unroll
        for (int j = 0; j < 8; j++) acc[i][j] = 0.0f;

    int arow = tid >> 2, ac4 = tid & 3;
    int brow = tid >> 5, bcol = (tid & 31) * 4;

    for (int k0 = 0; k0 < K; k0 += 16) {
#pragma unroll
        for (int h = 0; h < 2; h++) {
            int r = arow + h * 64;
            int m = m0 + r;
            float4 v = make_float4(0.f, 0.f, 0.f, 0.f);
            if (m < M) v = *(const float4*)(A + (size_t)m * lda + k0 + ac4 * 4);
            As[ac4 * 4 + 0][r] = v.x;
            As[ac4 * 4 + 1][r] = v.y;
            As[ac4 * 4 + 2][r] = v.z;
            As[ac4 * 4 + 3][r] = v.w;
        }
#pragma unroll
        for (int h = 0; h < 2; h++) {
            int r = brow + h * 8;
            float4 v = make_float4(0.f, 0.f, 0.f, 0.f);
            if (n0 + bcol < N) v = *(const float4*)(B + (size_t)(k0 + r) * ldb + n0 + bcol);
            *(float4*)&Bs[r][bcol] = v;
        }
        __syncthreads();
#pragma unroll
        for (int kk = 0; kk < 16; kk++) {
            float a[8], b[8];
            *(float4*)&a[0] = *(const float4*)&As[kk][ty * 8];
            *(float4*)&a[4] = *(const float4*)&As[kk][ty * 8 + 4];
            *(float4*)&b[0] = *(const float4*)&Bs[kk][tx * 8];
            *(float4*)&b[4] = *(const float4*)&Bs[kk][tx * 8 + 4];
#pragma unroll
            for (int i = 0; i < 8; i++)
#pragma unroll
                for (int j = 0; j < 8; j++)
                    acc[i][j] += a[i] * b[j];
        }
        __syncthreads();
    }
#pragma unroll
    for (int i = 0; i < 8; i++) {
        int m = m0 + ty * 8 + i;
        if (m < M) {
#pragma unroll
            for (int j = 0; j < 8; j++) {
                int n = n0 + tx * 8 + j;
                if (n < N) {
                    float v = acc[i][j] * alpha;
                    if (bias) v += bias[n];
                    size_t o = (size_t)m * ldc + coff + n;
                    if (ACCUM) v += C[o];
                    if (RELU) v = fmaxf(v, 0.0f);
                    if (BN) v = v * bnS[n] + bnB[n];
                    C[o] = v;
                }
            }
        }
    }
}

// ---------------- layer0 post: mean_r(l2norm(o_r)) -> relu -> LN ------------
template <int R>
__global__ void l0post_k(const float* __restrict__ O, int ldo,
                         const float* __restrict__ gg, const float* __restrict__ bb,
                         float* __restrict__ xout, int M) {
    int row = blockIdx.x * 8 + (threadIdx.x >> 5);
    if (row >= M) return;
    int lane = threadIdx.x & 31;
    float acc[4] = {0.f, 0.f, 0.f, 0.f};
#pragma unroll
    for (int rb = 0; rb < R; rb++) {
        const float* p = O + (size_t)row * ldo + rb * 128;
        float v[4]; float ss = 0.f;
#pragma unroll
        for (int j = 0; j < 4; j++) { v[j] = p[lane + 32 * j]; ss += v[j] * v[j]; }
#pragma unroll
        for (int s = 16; s; s >>= 1) ss += __shfl_xor_sync(0xffffffffu, ss, s);
        float inv = 1.0f / fmaxf(sqrtf(ss), 1e-12f);
#pragma unroll
        for (int j = 0; j < 4; j++) acc[j] += v[j] * inv;
    }
    const float invR = 1.0f / R;
    float s = 0.f;
#pragma unroll
    for (int j = 0; j < 4; j++) { acc[j] = fmaxf(acc[j] * invR, 0.f); s += acc[j]; }
#pragma unroll
    for (int o = 16; o; o >>= 1) s += __shfl_xor_sync(0xffffffffu, s, o);
    float m = s * (1.0f / 128.0f);
    float ss = 0.f;
#pragma unroll
    for (int j = 0; j < 4; j++) { float d = acc[j] - m; ss += d * d; }
#pragma unroll
    for (int o = 16; o; o >>= 1) ss += __shfl_xor_sync(0xffffffffu, ss, o);
    float inv = rsqrtf(ss * (1.0f / 128.0f) + 1e-5f);
    float* q = xout + (size_t)row * 128;
#pragma unroll
    for (int j = 0; j < 4; j++) {
        int c = lane + 32 * j;
        q[c] = (acc[j] - m) * inv * gg[c] + bb[c];
    }
}

// ---------------- x = LN(relu(acc*invr)) * g + b ----------------------------
__global__ void relu_ln_k(const float* __restrict__ acc, float invr,
                          const float* __restrict__ gg, const float* __restrict__ bb,
                          float* __restrict__ xout, int M) {
    int row = blockIdx.x * 8 + (threadIdx.x >> 5);
    if (row >= M) return;
    int lane = threadIdx.x & 31;
    const float* p = acc + (size_t)row * 128;
    float v[4]; float s = 0.f;
#pragma unroll
    for (int j = 0; j < 4; j++) { v[j] = fmaxf(p[lane + 32 * j] * invr, 0.f); s += v[j]; }
#pragma unroll
    for (int o = 16; o; o >>= 1) s += __shfl_xor_sync(0xffffffffu, s, o);
    float m = s * (1.0f / 128.0f);
    float ss = 0.f;
#pragma unroll
    for (int j = 0; j < 4; j++) { float d = v[j] - m; ss += d * d; }
#pragma unroll
    for (int o = 16; o; o >>= 1) ss += __shfl_xor_sync(0xffffffffu, ss, o);
    float inv = rsqrtf(ss * (1.0f / 128.0f) + 1e-5f);
    float* q = xout + (size_t)row * 128;
#pragma unroll
    for (int j = 0; j < 4; j++) {
        int c = lane + 32 * j;
        q[c] = (v[j] - m) * inv * gg[c] + bb[c];
    }
}

// ---------------- weight prep kernels ---------------------------------------
__global__ void catW_k(float* __restrict__ dst, const float* __restrict__ src,
                       int r0, int r1, int r2, int nrel, int K, int C) {
    int idx = blockIdx.x * 256 + threadIdx.x;
    int tot = nrel * K * C;
    if (idx >= tot) return;
    int j = idx / (K * C);
    int rem = idx - j * K * C;
    int k = rem / C, c = rem - (rem / C) * C;
    int r = (j == 0) ? r0 : (j == 1) ? r1 : r2;
    dst[(size_t)k * (nrel * C) + j * C + c] = src[(size_t)r * K * C + (size_t)k * C + c];
}
__global__ void stack_k(float* __restrict__ dst, const float* __restrict__ src,
                        int r0, int r1, int r2, int nrel, int blk) {
    int idx = blockIdx.x * 256 + threadIdx.x;
    if (idx >= nrel * blk) return;
    int j = idx / blk, i = idx - j * blk;
    int r = (j == 0) ? r0 : (j == 1) ? r1 : r2;
    dst[idx] = src[(size_t)r * blk + i];
}
__global__ void sumW_k(float* __restrict__ dst, const float* __restrict__ src,
                       int r0, int r1, int r2, int nrel, int blk) {
    int idx = blockIdx.x * 256 + threadIdx.x;
    if (idx >= blk) return;
    float v = src[(size_t)r0 * blk + idx] + src[(size_t)r1 * blk + idx];
    if (nrel == 3) v += src[(size_t)r2 * blk + idx];
    dst[idx] = v;
}
__global__ void bnprep_k(float* __restrict__ sc, const float* __restrict__ g) {
    int i = threadIdx.x;
    sc[i] = g[i] * rsqrtf(1.0f + 1e-5f);
}

// ---------------- host dispatch ---------------------------------------------
static void gemm(const float* A, int lda, const float* B, int ldb, const float* bias,
                 float* C, int ldc, int coff, int M, int N, int K, float alpha,
                 bool relu, bool accum, const float* bnS, const float* bnB) {
    dim3 grid((M + 127) / 128, (N + 127) / 128);
    if (bnS)
        gemm128_k<true, false, true><<<grid, 256>>>(A, lda, B, ldb, bias, C, ldc, coff, M, N, K, alpha, bnS, bnB);
    else if (relu && !accum)
        gemm128_k<true, false, false><<<grid, 256>>>(A, lda, B, ldb, bias, C, ldc, coff, M, N, K, alpha, nullptr, nullptr);
    else if (accum)
        gemm128_k<false, true, false><<<grid, 256>>>(A, lda, B, ldb, bias, C, ldc, coff, M, N, K, alpha, nullptr, nullptr);
    else
        gemm128_k<false, false, false><<<grid, 256>>>(A, lda, B, ldb, bias, C, ldc, coff, M, N, K, alpha, nullptr, nullptr);
}

extern "C" void kernel_launch(void* const* d_in, const int* in_sizes, int n_in,
                              void* d_out, int out_size) {
    const float* x_note = (const float*)d_in[0];
    const float* x_beat = (const float*)d_in[1];
    const int* e[5] = {(const int*)d_in[2], (const int*)d_in[3], (const int*)d_in[4],
                       (const int*)d_in[5], (const int*)d_in[6]};
    int E[5];
    for (int r = 0; r < 5; r++) E[r] = in_sizes[2 + r] / 2;
    const float* proj_W = (const float*)d_in[7];
    const float* proj_b = (const float*)d_in[8];
    const float* l0_Wl  = (const float*)d_in[9];
    const float* l0_bl  = (const float*)d_in[10];
    const float* l0_Wr  = (const float*)d_in[11];
    const float* Wl     = (const float*)d_in[12];
    const float* bl     = (const float*)d_in[13];
    const float* Wr     = (const float*)d_in[14];
    const float* ln_g   = (const float*)d_in[15];
    const float* ln_b   = (const float*)d_in[16];
    const float* mlp_W1 = (const float*)d_in[17];
    const float* mlp_b1 = (const float*)d_in[18];
    const float* bn_g   = (const float*)d_in[19];
    const float* bn_b   = (const float*)d_in[20];
    const float* mlp_W2 = (const float*)d_in[21];
    const float* mlp_b2 = (const float*)d_in[22];

    float *pn, *pb, *aggn, *aggb, *On, *Ob, *xn0, *xn1, *xb0, *xb1, *outn, *outb, *cntf;
    int *cnti, *rowp, *colx;
    float *projCatN, *projCatB, *pbCatN, *pbCatB, *l0WrCatN, *l0WrCatB, *l0blCatN, *l0blCatB;
    float *Wl1CatN, *Wl1CatB, *Wl2CatN, *Wr1SumN, *Wr1SumB, *Wr2SumN, *b1SumN, *b1SumB, *b2SumN, *bnS;
    cudaGetSymbolAddress((void**)&pn, g_pn);       cudaGetSymbolAddress((void**)&pb, g_pb);
    cudaGetSymbolAddress((void**)&aggn, g_aggn);   cudaGetSymbolAddress((void**)&aggb, g_aggb);
    cudaGetSymbolAddress((void**)&On, g_On);       cudaGetSymbolAddress((void**)&Ob, g_Ob);
    cudaGetSymbolAddress((void**)&xn0, g_xn0);     cudaGetSymbolAddress((void**)&xn1, g_xn1);
    cudaGetSymbolAddress((void**)&xb0, g_xb0);     cudaGetSymbolAddress((void**)&xb1, g_xb1);
    cudaGetSymbolAddress((void**)&outn, g_outn);   cudaGetSymbolAddress((void**)&outb, g_outb);
    cudaGetSymbolAddress((void**)&cntf, g_cnt);    cudaGetSymbolAddress((void**)&cnti, g_cnti);
    cudaGetSymbolAddress((void**)&rowp, g_rowp);   cudaGetSymbolAddress((void**)&colx, g_col);
    cudaGetSymbolAddress((void**)&projCatN, g_projCatN); cudaGetSymbolAddress((void**)&projCatB, g_projCatB);
    cudaGetSymbolAddress((void**)&pbCatN, g_pbCatN);     cudaGetSymbolAddress((void**)&pbCatB, g_pbCatB);
    cudaGetSymbolAddress((void**)&l0WrCatN, g_l0WrCatN); cudaGetSymbolAddress((void**)&l0WrCatB, g_l0WrCatB);
    cudaGetSymbolAddress((void**)&l0blCatN, g_l0blCatN); cudaGetSymbolAddress((void**)&l0blCatB, g_l0blCatB);
    cudaGetSymbolAddress((void**)&Wl1CatN, g_Wl1CatN);   cudaGetSymbolAddress((void**)&Wl1CatB, g_Wl1CatB);
    cudaGetSymbolAddress((void**)&Wl2CatN, g_Wl2CatN);
    cudaGetSymbolAddress((void**)&Wr1SumN, g_Wr1SumN);   cudaGetSymbolAddress((void**)&Wr1SumB, g_Wr1SumB);
    cudaGetSymbolAddress((void**)&Wr2SumN, g_Wr2SumN);
    cudaGetSymbolAddress((void**)&b1SumN, g_b1SumN);     cudaGetSymbolAddress((void**)&b1SumB, g_b1SumB);
    cudaGetSymbolAddress((void**)&b2SumN, g_b2SumN);     cudaGetSymbolAddress((void**)&bnS, g_bnS);

    const int dt[5] = {0, 0, 1, 0, 1};
    const int nsz[2] = {NN, NB};
    int ebase[5];
    { int acc = 0; for (int r = 0; r < 5; r++) { ebase[r] = acc; acc += E[r]; } }

    detect_mode_k<<<1, 1>>>(e[0]);

    // ---- CSR build: counts -> inv -> scans -> fill ----
    cudaMemsetAsync(cnti, 0, 5 * NN * sizeof(int));
    for (int r = 0; r < 5; r++)
        counti_k<<<(E[r] + 255) / 256, 256>>>(e[r], E[r], cnti + r * NN);
    for (int r = 0; r < 5; r++) {
        int dn = nsz[dt[r]];
        inv_k<<<(dn + 255) / 256, 256>>>(cnti + r * NN, cntf + r * NN, dn);
    }
    scan1_k<<<dim3(NBX, 5), 256>>>();
    scan2_k<<<1, 32>>>();
    scan3_k<<<dim3(NBX, 5), 256>>>();
    for (int r = 0; r < 5; r++)
        fill_k<<<(E[r] + 255) / 256, 256>>>(e[r], E[r], r, ebase[r]);

    const int* rp[5]; const int* cx[5]; const float* ic[5];
    for (int r = 0; r < 5; r++) {
        rp[r] = rowp + r * (NN + 1);
        cx[r] = colx + ebase[r];
        ic[r] = cntf + r * NN;
    }

    // ---- weight prep (tiny) ----
    catW_k<<<(3 * 64 * 64 + 255) / 256, 256>>>(projCatN, proj_W, 0, 1, 2, 3, 64, 64);
    catW_k<<<(2 * 64 * 64 + 255) / 256, 256>>>(projCatB, proj_W, 3, 4, 0, 2, 64, 64);
    catW_k<<<1, 256>>>(pbCatN, proj_b, 0, 1, 2, 3, 1, 64);
    catW_k<<<1, 256>>>(pbCatB, proj_b, 3, 4, 0, 2, 1, 64);
    catW_k<<<(3 * 64 * 128 + 255) / 256, 256>>>(l0WrCatN, l0_Wr, 0, 1, 3, 3, 64, 128);
    catW_k<<<(2 * 64 * 128 + 255) / 256, 256>>>(l0WrCatB, l0_Wr, 2, 4, 0, 2, 64, 128);
    catW_k<<<2, 256>>>(l0blCatN, l0_bl, 0, 1, 3, 3, 1, 128);
    catW_k<<<1, 256>>>(l0blCatB, l0_bl, 2, 4, 0, 2, 1, 128);
    stack_k<<<(3 * 16384 + 255) / 256, 256>>>(Wl1CatN, Wl, 0, 1, 3, 3, 16384);
    stack_k<<<(2 * 16384 + 255) / 256, 256>>>(Wl1CatB, Wl, 2, 4, 0, 2, 16384);
    stack_k<<<(3 * 16384 + 255) / 256, 256>>>(Wl2CatN, Wl + 5 * 16384, 0, 1, 3, 3, 16384);
    sumW_k<<<64, 256>>>(Wr1SumN, Wr, 0, 1, 3, 3, 16384);
    sumW_k<<<64, 256>>>(Wr1SumB, Wr, 2, 4, 0, 2, 16384);
    sumW_k<<<64, 256>>>(Wr2SumN, Wr + 5 * 16384, 0, 1, 3, 3, 16384);
    sumW_k<<<1, 128>>>(b1SumN, bl, 0, 1, 3, 3, 128);
    sumW_k<<<1, 128>>>(b1SumB, bl, 2, 4, 0, 2, 128);
    sumW_k<<<1, 128>>>(b2SumN, bl + 5 * 128, 0, 1, 3, 3, 128);
    bnprep_k<<<1, 128>>>(bnS, bn_g);

    // ==================== layer 0 (64 -> 128) ====================
    gemm(x_note, 64, projCatN, 192, pbCatN, pn, 192, 0, NN, 192, 64, 1.f, true, false, nullptr, nullptr);
    gemm(x_beat, 64, projCatB, 128, pbCatB, pb, 128, 0, NB, 128, 64, 1.f, true, false, nullptr, nullptr);
    // CSR seg-mean (C=64 per relation, V=2)
    aggcsr_k<2><<<(NN + 7) / 8, 256>>>(pn, 192, 0,   rp[0], cx[0], ic[0], aggn, 192, 0,   NN);
    aggcsr_k<2><<<(NN + 7) / 8, 256>>>(pn, 192, 64,  rp[1], cx[1], ic[1], aggn, 192, 64,  NN);
    aggcsr_k<2><<<(NN + 7) / 8, 256>>>(pb, 128, 0,   rp[3], cx[3], ic[3], aggn, 192, 128, NN);
    aggcsr_k<2><<<(NB + 7) / 8, 256>>>(pn, 192, 128, rp[2], cx[2], ic[2], aggb, 128, 0,   NB);
    aggcsr_k<2><<<(NB + 7) / 8, 256>>>(pb, 128, 64,  rp[4], cx[4], ic[4], aggb, 128, 64,  NB);
    // o_r = xd @ Wr_r (N-concat) then += agg_r @ Wl_r
    gemm(x_note, 64, l0WrCatN, 384, l0blCatN, On, 384, 0, NN, 384, 64, 1.f, false, false, nullptr, nullptr);
    gemm(x_beat, 64, l0WrCatB, 256, l0blCatB, Ob, 256, 0, NB, 256, 64, 1.f, false, false, nullptr, nullptr);
    const int relN[3] = {0, 1, 3};
    for (int j = 0; j < 3; j++)
        gemm(aggn + j * 64, 192, l0_Wl + (size_t)relN[j] * 64 * 128, 128, nullptr,
             On, 384, j * 128, NN, 128, 64, 1.f, false, true, nullptr, nullptr);
    const int relB[2] = {2, 4};
    for (int j = 0; j < 2; j++)
        gemm(aggb + j * 64, 128, l0_Wl + (size_t)relB[j] * 64 * 128, 128, nullptr,
             Ob, 256, j * 128, NB, 128, 64, 1.f, false, true, nullptr, nullptr);
    l0post_k<3><<<(NN + 7) / 8, 256>>>(On, 384, ln_g, ln_b, xn0, NN);
    l0post_k<2><<<(NB + 7) / 8, 256>>>(Ob, 256, ln_g, ln_b, xb0, NB);

    // ==================== layer 1 (128 -> 128) ====================
    aggcsr_k<4><<<(NN + 7) / 8, 256>>>(xn0, 128, 0, rp[0], cx[0], ic[0], aggn, 384, 0,   NN);
    aggcsr_k<4><<<(NN + 7) / 8, 256>>>(xn0, 128, 0, rp[1], cx[1], ic[1], aggn, 384, 128, NN);
    aggcsr_k<4><<<(NN + 7) / 8, 256>>>(xb0, 128, 0, rp[3], cx[3], ic[3], aggn, 384, 256, NN);
    aggcsr_k<4><<<(NB + 7) / 8, 256>>>(xn0, 128, 0, rp[2], cx[2], ic[2], aggb, 256, 0,   NB);
    aggcsr_k<4><<<(NB + 7) / 8, 256>>>(xb0, 128, 0, rp[4], cx[4], ic[4], aggb, 256, 128, NB);
    gemm(aggn, 384, Wl1CatN, 128, b1SumN, outn, 128, 0, NN, 128, 384, 1.f, false, false, nullptr, nullptr);
    gemm(xn0, 128, Wr1SumN, 128, nullptr, outn, 128, 0, NN, 128, 128, 1.f, false, true, nullptr, nullptr);
    gemm(aggb, 256, Wl1CatB, 128, b1SumB, outb, 128, 0, NB, 128, 256, 1.f, false, false, nullptr, nullptr);
    gemm(xb0, 128, Wr1SumB, 128, nullptr, outb, 128, 0, NB, 128, 128, 1.f, false, true, nullptr, nullptr);
    relu_ln_k<<<(NN + 7) / 8, 256>>>(outn, 1.f / 3.f, ln_g + 128, ln_b + 128, xn1, NN);
    relu_ln_k<<<(NB + 7) / 8, 256>>>(outb, 1.f / 2.f, ln_g + 128, ln_b + 128, xb1, NB);

    // ==================== layer 2 (note dst only) ====================
    aggcsr_k<4><<<(NN + 7) / 8, 256>>>(xn1, 128, 0, rp[0], cx[0], ic[0], aggn, 384, 0,   NN);
    aggcsr_k<4><<<(NN + 7) / 8, 256>>>(xn1, 128, 0, rp[1], cx[1], ic[1], aggn, 384, 128, NN);
    aggcsr_k<4><<<(NN + 7) / 8, 256>>>(xb1, 128, 0, rp[3], cx[3], ic[3], aggn, 384, 256, NN);
    gemm(aggn, 384, Wl2CatN, 128, b2SumN, outn, 128, 0, NN, 128, 384, 1.f, false, false, nullptr, nullptr);
    gemm(xn1, 128, Wr2SumN, 128, nullptr, outn, 128, 0, NN, 128, 128, 1.f, false, true, nullptr, nullptr);

    // ==================== final MLP (BN folded) ====================
    gemm(outn, 128, mlp_W1, 128, mlp_b1, On, 128, 0, NN, 128, 128, 1.f / 3.f, true, false, bnS, bn_b);
    gemm(On, 128, mlp_W2, 32, mlp_b2, (float*)d_out, 32, 0, NN, 32, 128, 1.f, false, false, nullptr, nullptr);
}

// round 5
// speedup vs baseline: 3.0632x; 1.2298x over previous
#include <cuda_runtime.h>
#include <cuda_bf16.h>
#include <mma.h>
#include <cstdint>

using namespace nvcuda;

#define NN 100000
#define NB 20000
#define INC 64
#define HID 128
#define NBX 49
#define MAXE 3000000

// ================= scratch (device globals; no runtime allocation) ==========
__device__ float g_pn  [(size_t)NN * 192];
__device__ float g_pb  [(size_t)NB * 128];
__device__ float g_aggn[(size_t)NN * 384];
__device__ float g_aggb[(size_t)NB * 256];
__device__ float g_On  [(size_t)NN * 384];
__device__ float g_Ob  [(size_t)NB * 256];
__device__ float g_xn0 [(size_t)NN * HID];
__device__ float g_xn1 [(size_t)NN * HID];
__device__ float g_xb0 [(size_t)NB * HID];
__device__ float g_xb1 [(size_t)NB * HID];
__device__ float g_outn[(size_t)NN * HID];
__device__ float g_outb[(size_t)NB * HID];
__device__ float g_cnt [5][NN];
__device__ int   g_cnti[5][NN];
__device__ int   g_rowp[5][NN + 1];
__device__ int   g_bsum[5][64];
__device__ int   g_col [MAXE];
__device__ int   g_emode;

// weight scratch (f32 K-major intermediates)
__device__ float g_projCatN[64 * 192];
__device__ float g_projCatB[64 * 128];
__device__ float g_pbCatN[192];
__device__ float g_pbCatB[128];
__device__ float g_Wl1CatN[384 * 128];
__device__ float g_Wl1CatB[256 * 128];
__device__ float g_Wl2CatN[384 * 128];
__device__ float g_Wr1SumN[128 * 128];
__device__ float g_Wr1SumB[128 * 128];
__device__ float g_Wr2SumN[128 * 128];
__device__ float g_b1SumN[128];
__device__ float g_b1SumB[128];
__device__ float g_b2SumN[128];
__device__ float g_bnS[128];
// bf16 transposed+split weights [Npad x K], hi/lo
__device__ __nv_bfloat16 g_BtProjN[2][256 * 64];    // N=192 pad 256
__device__ __nv_bfloat16 g_BtProjB[2][128 * 64];
__device__ __nv_bfloat16 g_BtL0  [2][5][128 * 128];
__device__ __nv_bfloat16 g_BtL1N [2][128 * 512];
__device__ __nv_bfloat16 g_BtL1B [2][128 * 384];
__device__ __nv_bfloat16 g_BtL2N [2][128 * 512];
__device__ __nv_bfloat16 g_BtM1  [2][128 * 128];
__device__ __nv_bfloat16 g_BtM2  [2][128 * 128];    // N=32 pad 128

// ================= edge handling / CSR ======================================
__global__ void detect_mode_k(const int* e) {
    int z = 1;
    for (int i = 1; i < 64; i += 2)
        if (e[i] != 0) z = 0;
    g_emode = z;
}
__device__ __forceinline__ int edge_at(const int* e, long long i) {
    if (g_emode) return (int)((const long long*)e)[i];
    return e[i];
}
__global__ void counti_k(const int* __restrict__ e, int E, int* __restrict__ cnt) {
    int i = blockIdx.x * 256 + threadIdx.x;
    if (i >= E) return;
    atomicAdd(&cnt[edge_at(e, (long long)E + i)], 1);
}
__global__ void inv_k(const int* __restrict__ ci, float* __restrict__ cf, int n) {
    int i = blockIdx.x * 256 + threadIdx.x;
    if (i < n) cf[i] = 1.0f / (float)max(ci[i], 1);
}
__global__ void scan1_k() {
    int r = blockIdx.y;
    int n = (r == 2 || r == 4) ? NB : NN;
    int t = threadIdx.x;
    int base = blockIdx.x * 2048 + t * 8;
    int vals[8];
#pragma unroll
    for (int j = 0; j < 8; j++) {
        int idx = base + j;
        vals[j] = (idx < n) ? g_cnti[r][idx] : 0;
    }
    int tot = 0;
#pragma unroll
    for (int j = 0; j < 8; j++) tot += vals[j];
    int lane = t & 31, wid = t >> 5;
    int x = tot;
#pragma unroll
    for (int o = 1; o < 32; o <<= 1) {
        int y = __shfl_up_sync(0xffffffffu, x, o);
        if (lane >= o) x += y;
    }
    __shared__ int wsum[8];
    if (lane == 31) wsum[wid] = x;
    __syncthreads();
    if (t == 0) {
        int run = 0;
#pragma unroll
        for (int i = 0; i < 8; i++) { int v = wsum[i]; wsum[i] = run; run += v; }
        g_bsum[r][blockIdx.x] = run;
    }
    __syncthreads();
    int run = (x - tot) + wsum[wid];
#pragma unroll
    for (int j = 0; j < 8; j++) {
        int idx = base + j;
        if (idx < n) g_rowp[r][idx] = run;
        run += vals[j];
    }
}
__global__ void scan2_k() {
    int r = threadIdx.x;
    if (r >= 5) return;
    int n = (r == 2 || r == 4) ? NB : NN;
    int run = 0;
    for (int i = 0; i < NBX; i++) { int v = g_bsum[r][i]; g_bsum[r][i] = run; run += v; }
    g_rowp[r][n] = run;
}
__global__ void scan3_k() {
    int r = blockIdx.y;
    int n = (r == 2 || r == 4) ? NB : NN;
    int add = g_bsum[r][blockIdx.x];
    int base = blockIdx.x * 2048 + threadIdx.x * 8;
#pragma unroll
    for (int j = 0; j < 8; j++) {
        int idx = base + j;
        if (idx < n) {
            int v = g_rowp[r][idx] + add;
            g_rowp[r][idx] = v;
            g_cnti[r][idx] = v;
        }
    }
}
__global__ void fill_k(const int* __restrict__ e, int E, int r, int ebase) {
    int i = blockIdx.x * 256 + threadIdx.x;
    if (i >= E) return;
    int s = edge_at(e, i);
    int d = edge_at(e, (long long)E + i);
    int pos = atomicAdd(&g_cnti[r][d], 1);
    g_col[ebase + pos] = s;
}

template <int V>
__global__ void aggcsr_k(const float* __restrict__ xf, int lds, int soff,
                         const int* __restrict__ rowp, const int* __restrict__ col,
                         const float* __restrict__ invc,
                         float* __restrict__ agg, int ldd, int doff, int n) {
    int row = blockIdx.x * 8 + (threadIdx.x >> 5);
    if (row >= n) return;
    int lane = threadIdx.x & 31;
    int beg = rowp[row], end = rowp[row + 1];
    float acc[V];
#pragma unroll
    for (int j = 0; j < V; j++) acc[j] = 0.0f;
    int e = beg;
    for (; e + 1 < end; e += 2) {
        int s0 = __ldg(&col[e]);
        int s1 = __ldg(&col[e + 1]);
        const float* p0 = xf + (size_t)s0 * lds + soff + lane * V;
        const float* p1 = xf + (size_t)s1 * lds + soff + lane * V;
        if (V == 4) {
            float4 a = *(const float4*)p0;
            float4 b = *(const float4*)p1;
            acc[0] += a.x + b.x; acc[1] += a.y + b.y;
            acc[2] += a.z + b.z; acc[3] += a.w + b.w;
        } else {
            float2 a = *(const float2*)p0;
            float2 b = *(const float2*)p1;
            acc[0] += a.x + b.x; acc[1] += a.y + b.y;
        }
    }
    if (e < end) {
        int s0 = __ldg(&col[e]);
        const float* p0 = xf + (size_t)s0 * lds + soff + lane * V;
        if (V == 4) {
            float4 a = *(const float4*)p0;
            acc[0] += a.x; acc[1] += a.y; acc[2] += a.z; acc[3] += a.w;
        } else {
            float2 a = *(const float2*)p0;
            acc[0] += a.x; acc[1] += a.y;
        }
    }
    float inv = invc[row];
    float* q = agg + (size_t)row * ldd + doff + lane * V;
    if (V == 4) {
        *(float4*)q = make_float4(acc[0] * inv, acc[1] * inv, acc[2] * inv, acc[3] * inv);
    } else {
        *(float2*)q = make_float2(acc[0] * inv, acc[1] * inv);
    }
}

// ================= wmma bf16 split GEMM ======================================
// C[m, coff+n] = epi(alpha*(A@W) + bias[n]); A = [A1(K1) | A2(K2)] f32 row-major.
// W given pre-transposed+split bf16: Bhi/Blo [Npad x K] (row n holds W[:,n]).
// Computes hi*hi + hi*lo + lo*hi (error-free split, ~fp32 accuracy).
// EPI: 0 plain, 1 relu, 2 relu+bn
template <int EPI>
__global__ __launch_bounds__(256) void tgemm_k(
    const float* __restrict__ A1, int lda1, int K1,
    const float* __restrict__ A2, int lda2, int K2,
    const __nv_bfloat16* __restrict__ Bhi, const __nv_bfloat16* __restrict__ Blo,
    int ldK, const float* __restrict__ bias,
    float* __restrict__ C, int ldc, int coff,
    int M, int Nfull, float alpha,
    const float* __restrict__ bnS, const float* __restrict__ bnB)
{
    __shared__ __align__(16) __nv_bfloat16 Ahi[128][40];
    __shared__ __align__(16) __nv_bfloat16 Alo[128][40];
    __shared__ __align__(16) float patch[8][16 * 20];

    int tid = threadIdx.x;
    int wid = tid >> 5, lane = tid & 31;
    int wm = wid >> 2, wn = wid & 3;           // 2 x 4 warp grid
    int m0 = blockIdx.x * 128, n0 = blockIdx.y * 128;
    int mw = m0 + wm * 64;
    int nw = n0 + wn * 32;
    bool active = (nw < Nfull);
    int K = K1 + K2;

    wmma::fragment<wmma::accumulator, 16, 16, 16, float> acc[4][2];
#pragma unroll
    for (int i = 0; i < 4; i++)
#pragma unroll
        for (int j = 0; j < 2; j++) wmma::fill_fragment(acc[i][j], 0.0f);

    int row = tid >> 1, half = tid & 1;
    int m = m0 + row;

    for (int k0 = 0; k0 < K; k0 += 32) {
        // ---- stage A tile 128x32 f32 -> bf16 hi/lo smem ----
        {
            const float* Ap; int ld, kl;
            if (k0 < K1) { Ap = A1; ld = lda1; kl = k0; }
            else         { Ap = A2; ld = lda2; kl = k0 - K1; }
            const float* src = Ap + (size_t)m * ld + kl + half * 16;
#pragma unroll
            for (int i = 0; i < 4; i++) {
                float4 v = make_float4(0.f, 0.f, 0.f, 0.f);
                if (m < M) v = *(const float4*)(src + i * 4);
                int col = half * 16 + i * 4;
                __nv_bfloat16 hx = __float2bfloat16_rn(v.x);
                __nv_bfloat16 hy = __float2bfloat16_rn(v.y);
                __nv_bfloat16 hz = __float2bfloat16_rn(v.z);
                __nv_bfloat16 hw = __float2bfloat16_rn(v.w);
                __nv_bfloat16 lx = __float2bfloat16_rn(v.x - __bfloat162float(hx));
                __nv_bfloat16 ly = __float2bfloat16_rn(v.y - __bfloat162float(hy));
                __nv_bfloat16 lz = __float2bfloat16_rn(v.z - __bfloat162float(hz));
                __nv_bfloat16 lw = __float2bfloat16_rn(v.w - __bfloat162float(hw));
                Ahi[row][col + 0] = hx; Ahi[row][col + 1] = hy;
                Ahi[row][col + 2] = hz; Ahi[row][col + 3] = hw;
                Alo[row][col + 0] = lx; Alo[row][col + 1] = ly;
                Alo[row][col + 2] = lz; Alo[row][col + 3] = lw;
            }
        }
        __syncthreads();
        if (active) {
#pragma unroll
            for (int pass = 0; pass < 3; pass++) {
                const __nv_bfloat16 (*As)[40] = (pass < 2) ? Ahi : Alo;
                const __nv_bfloat16* Bs = (pass == 1) ? Blo : Bhi;
#pragma unroll
                for (int kk = 0; kk < 32; kk += 16) {
                    wmma::fragment<wmma::matrix_b, 16, 16, 16, __nv_bfloat16, wmma::col_major> bf[2];
#pragma unroll
                    for (int j = 0; j < 2; j++)
                        wmma::load_matrix_sync(bf[j], Bs + (size_t)(nw + j * 16) * ldK + (k0 + kk), (unsigned)ldK);
#pragma unroll
                    for (int i = 0; i < 4; i++) {
                        wmma::fragment<wmma::matrix_a, 16, 16, 16, __nv_bfloat16, wmma::row_major> af;
                        wmma::load_matrix_sync(af, &As[wm * 64 + i * 16][0] + kk, 40u);
#pragma unroll
                        for (int j = 0; j < 2; j++)
                            wmma::mma_sync(acc[i][j], af, bf[j], acc[i][j]);
                    }
                }
            }
        }
        __syncthreads();
    }

    // ---- epilogue: per-frag via smem patch ----
    if (active) {
        float* myp = patch[wid];
        int base = lane * 8;
        int pr = base >> 4, pc = base & 15;
#pragma unroll
        for (int i = 0; i < 4; i++) {
#pragma unroll
            for (int j = 0; j < 2; j++) {
                wmma::store_matrix_sync(myp, acc[i][j], 20u, wmma::mem_row_major);
                __syncwarp();
                int mb = mw + i * 16, nb = nw + j * 16;
                if (mb + pr < M) {
                    float out[8];
#pragma unroll
                    for (int t = 0; t < 8; t++) {
                        int n = nb + pc + t;
                        float v = myp[pr * 20 + pc + t] * alpha + bias[n];
                        if (EPI >= 1) v = fmaxf(v, 0.0f);
                        if (EPI == 2) v = v * bnS[n] + bnB[n];
                        out[t] = v;
                    }
                    float* dst = C + (size_t)(mb + pr) * ldc + coff + nb + pc;
                    *(float4*)dst = *(float4*)&out[0];
                    *(float4*)(dst + 4) = *(float4*)&out[4];
                }
                __syncwarp();
            }
        }
    }
}

// ================= elementwise kernels =======================================
template <int R>
__global__ void l0post_k(const float* __restrict__ O, int ldo,
                         const float* __restrict__ gg, const float* __restrict__ bb,
                         float* __restrict__ xout, int M) {
    int row = blockIdx.x * 8 + (threadIdx.x >> 5);
    if (row >= M) return;
    int lane = threadIdx.x & 31;
    float acc[4] = {0.f, 0.f, 0.f, 0.f};
#pragma unroll
    for (int rb = 0; rb < R; rb++) {
        const float* p = O + (size_t)row * ldo + rb * 128;
        float v[4]; float ss = 0.f;
#pragma unroll
        for (int j = 0; j < 4; j++) { v[j] = p[lane + 32 * j]; ss += v[j] * v[j]; }
#pragma unroll
        for (int s = 16; s; s >>= 1) ss += __shfl_xor_sync(0xffffffffu, ss, s);
        float inv = 1.0f / fmaxf(sqrtf(ss), 1e-12f);
#pragma unroll
        for (int j = 0; j < 4; j++) acc[j] += v[j] * inv;
    }
    const float invR = 1.0f / R;
    float s = 0.f;
#pragma unroll
    for (int j = 0; j < 4; j++) { acc[j] = fmaxf(acc[j] * invR, 0.f); s += acc[j]; }
#pragma unroll
    for (int o = 16; o; o >>= 1) s += __shfl_xor_sync(0xffffffffu, s, o);
    float m = s * (1.0f / 128.0f);
    float ss = 0.f;
#pragma unroll
    for (int j = 0; j < 4; j++) { float d = acc[j] - m; ss += d * d; }
#pragma unroll
    for (int o = 16; o; o >>= 1) ss += __shfl_xor_sync(0xffffffffu, ss, o);
    float inv = rsqrtf(ss * (1.0f / 128.0f) + 1e-5f);
    float* q = xout + (size_t)row * 128;
#pragma unroll
    for (int j = 0; j < 4; j++) {
        int c = lane + 32 * j;
        q[c] = (acc[j] - m) * inv * gg[c] + bb[c];
    }
}
__global__ void relu_ln_k(const float* __restrict__ acc, float invr,
                          const float* __restrict__ gg, const float* __restrict__ bb,
                          float* __restrict__ xout, int M) {
    int row = blockIdx.x * 8 + (threadIdx.x >> 5);
    if (row >= M) return;
    int lane = threadIdx.x & 31;
    const float* p = acc + (size_t)row * 128;
    float v[4]; float s = 0.f;
#pragma unroll
    for (int j = 0; j < 4; j++) { v[j] = fmaxf(p[lane + 32 * j] * invr, 0.f); s += v[j]; }
#pragma unroll
    for (int o = 16; o; o >>= 1) s += __shfl_xor_sync(0xffffffffu, s, o);
    float m = s * (1.0f / 128.0f);
    float ss = 0.f;
#pragma unroll
    for (int j = 0; j < 4; j++) { float d = v[j] - m; ss += d * d; }
#pragma unroll
    for (int o = 16; o; o >>= 1) ss += __shfl_xor_sync(0xffffffffu, ss, o);
    float inv = rsqrtf(ss * (1.0f / 128.0f) + 1e-5f);
    float* q = xout + (size_t)row * 128;
#pragma unroll
    for (int j = 0; j < 4; j++) {
        int c = lane + 32 * j;
        q[c] = (v[j] - m) * inv * gg[c] + bb[c];
    }
}

// ================= weight prep ===============================================
__global__ void catW_k(float* __restrict__ dst, const float* __restrict__ src,
                       int r0, int r1, int r2, int nrel, int K, int C) {
    int idx = blockIdx.x * 256 + threadIdx.x;
    int tot = nrel * K * C;
    if (idx >= tot) return;
    int j = idx / (K * C);
    int rem = idx - j * K * C;
    int k = rem / C, c = rem - (rem / C) * C;
    int r = (j == 0) ? r0 : (j == 1) ? r1 : r2;
    dst[(size_t)k * (nrel * C) + j * C + c] = src[(size_t)r * K * C + (size_t)k * C + c];
}
__global__ void stack_k(float* __restrict__ dst, const float* __restrict__ src,
                        int r0, int r1, int r2, int nrel, int blk) {
    int idx = blockIdx.x * 256 + threadIdx.x;
    if (idx >= nrel * blk) return;
    int j = idx / blk, i = idx - j * blk;
    int r = (j == 0) ? r0 : (j == 1) ? r1 : r2;
    dst[idx] = src[(size_t)r * blk + i];
}
__global__ void sumW_k(float* __restrict__ dst, const float* __restrict__ src,
                       int r0, int r1, int r2, int nrel, int blk) {
    int idx = blockIdx.x * 256 + threadIdx.x;
    if (idx >= blk) return;
    float v = src[(size_t)r0 * blk + idx] + src[(size_t)r1 * blk + idx];
    if (nrel == 3) v += src[(size_t)r2 * blk + idx];
    dst[idx] = v;
}
__global__ void bnprep_k(float* __restrict__ sc, const float* __restrict__ g) {
    int i = threadIdx.x;
    sc[i] = g[i] * rsqrtf(1.0f + 1e-5f);
}
// transpose + bf16 hi/lo split: src [K x N] f32 row-major -> dst[n*ldK + koff + k]
__global__ void tsplb_k(__nv_bfloat16* __restrict__ hi, __nv_bfloat16* __restrict__ lo,
                        const float* __restrict__ src, int K, int N, int ldK, int koff) {
    int idx = blockIdx.x * 256 + threadIdx.x;
    if (idx >= K * N) return;
    int k = idx / N, n = idx - (idx / N) * N;
    float x = src[idx];
    __nv_bfloat16 h = __float2bfloat16_rn(x);
    __nv_bfloat16 l = __float2bfloat16_rn(x - __bfloat162float(h));
    hi[(size_t)n * ldK + koff + k] = h;
    lo[(size_t)n * ldK + koff + k] = l;
}

// ================= host dispatch =============================================
static void tgemm(int epi, const float* A1, int lda1, int K1,
                  const float* A2, int lda2, int K2,
                  const __nv_bfloat16* Bh, const __nv_bfloat16* Bl, int ldK,
                  const float* bias, float* C, int ldc, int coff,
                  int M, int Nfull, float alpha,
                  const float* bnS, const float* bnB) {
    dim3 g((M + 127) / 128, (Nfull + 127) / 128);
    if (epi == 0)
        tgemm_k<0><<<g, 256>>>(A1, lda1, K1, A2, lda2, K2, Bh, Bl, ldK, bias, C, ldc, coff, M, Nfull, alpha, bnS, bnB);
    else if (epi == 1)
        tgemm_k<1><<<g, 256>>>(A1, lda1, K1, A2, lda2, K2, Bh, Bl, ldK, bias, C, ldc, coff, M, Nfull, alpha, bnS, bnB);
    else
        tgemm_k<2><<<g, 256>>>(A1, lda1, K1, A2, lda2, K2, Bh, Bl, ldK, bias, C, ldc, coff, M, Nfull, alpha, bnS, bnB);
}

extern "C" void kernel_launch(void* const* d_in, const int* in_sizes, int n_in,
                              void* d_out, int out_size) {
    const float* x_note = (const float*)d_in[0];
    const float* x_beat = (const float*)d_in[1];
    const int* e[5] = {(const int*)d_in[2], (const int*)d_in[3], (const int*)d_in[4],
                       (const int*)d_in[5], (const int*)d_in[6]};
    int E[5];
    for (int r = 0; r < 5; r++) E[r] = in_sizes[2 + r] / 2;
    const float* proj_W = (const float*)d_in[7];
    const float* proj_b = (const float*)d_in[8];
    const float* l0_Wl  = (const float*)d_in[9];
    const float* l0_bl  = (const float*)d_in[10];
    const float* l0_Wr  = (const float*)d_in[11];
    const float* Wl     = (const float*)d_in[12];
    const float* bl     = (const float*)d_in[13];
    const float* Wr     = (const float*)d_in[14];
    const float* ln_g   = (const float*)d_in[15];
    const float* ln_b   = (const float*)d_in[16];
    const float* mlp_W1 = (const float*)d_in[17];
    const float* mlp_b1 = (const float*)d_in[18];
    const float* bn_g   = (const float*)d_in[19];
    const float* bn_b   = (const float*)d_in[20];
    const float* mlp_W2 = (const float*)d_in[21];
    const float* mlp_b2 = (const float*)d_in[22];

    float *pn, *pb, *aggn, *aggb, *On, *Ob, *xn0, *xn1, *xb0, *xb1, *outn, *outb, *cntf;
    int *cnti, *rowp, *colx;
    cudaGetSymbolAddress((void**)&pn, g_pn);       cudaGetSymbolAddress((void**)&pb, g_pb);
    cudaGetSymbolAddress((void**)&aggn, g_aggn);   cudaGetSymbolAddress((void**)&aggb, g_aggb);
    cudaGetSymbolAddress((void**)&On, g_On);       cudaGetSymbolAddress((void**)&Ob, g_Ob);
    cudaGetSymbolAddress((void**)&xn0, g_xn0);     cudaGetSymbolAddress((void**)&xn1, g_xn1);
    cudaGetSymbolAddress((void**)&xb0, g_xb0);     cudaGetSymbolAddress((void**)&xb1, g_xb1);
    cudaGetSymbolAddress((void**)&outn, g_outn);   cudaGetSymbolAddress((void**)&outb, g_outb);
    cudaGetSymbolAddress((void**)&cntf, g_cnt);    cudaGetSymbolAddress((void**)&cnti, g_cnti);
    cudaGetSymbolAddress((void**)&rowp, g_rowp);   cudaGetSymbolAddress((void**)&colx, g_col);

    float *projCatN, *projCatB, *pbCatN, *pbCatB;
    float *Wl1CatN, *Wl1CatB, *Wl2CatN, *Wr1SumN, *Wr1SumB, *Wr2SumN;
    float *b1SumN, *b1SumB, *b2SumN, *bnS;
    cudaGetSymbolAddress((void**)&projCatN, g_projCatN); cudaGetSymbolAddress((void**)&projCatB, g_projCatB);
    cudaGetSymbolAddress((void**)&pbCatN, g_pbCatN);     cudaGetSymbolAddress((void**)&pbCatB, g_pbCatB);
    cudaGetSymbolAddress((void**)&Wl1CatN, g_Wl1CatN);   cudaGetSymbolAddress((void**)&Wl1CatB, g_Wl1CatB);
    cudaGetSymbolAddress((void**)&Wl2CatN, g_Wl2CatN);
    cudaGetSymbolAddress((void**)&Wr1SumN, g_Wr1SumN);   cudaGetSymbolAddress((void**)&Wr1SumB, g_Wr1SumB);
    cudaGetSymbolAddress((void**)&Wr2SumN, g_Wr2SumN);
    cudaGetSymbolAddress((void**)&b1SumN, g_b1SumN);     cudaGetSymbolAddress((void**)&b1SumB, g_b1SumB);
    cudaGetSymbolAddress((void**)&b2SumN, g_b2SumN);     cudaGetSymbolAddress((void**)&bnS, g_bnS);

    __nv_bfloat16 *BtProjN[2], *BtProjB[2], *BtL0[2], *BtL1N[2], *BtL1B[2], *BtL2N[2], *BtM1[2], *BtM2[2];
    {
        __nv_bfloat16* p;
        cudaGetSymbolAddress((void**)&p, g_BtProjN); BtProjN[0] = p; BtProjN[1] = p + 256 * 64;
        cudaGetSymbolAddress((void**)&p, g_BtProjB); BtProjB[0] = p; BtProjB[1] = p + 128 * 64;
        cudaGetSymbolAddress((void**)&p, g_BtL0);    BtL0[0] = p;    BtL0[1] = p + 5 * 128 * 128;
        cudaGetSymbolAddress((void**)&p, g_BtL1N);   BtL1N[0] = p;   BtL1N[1] = p + 128 * 512;
        cudaGetSymbolAddress((void**)&p, g_BtL1B);   BtL1B[0] = p;   BtL1B[1] = p + 128 * 384;
        cudaGetSymbolAddress((void**)&p, g_BtL2N);   BtL2N[0] = p;   BtL2N[1] = p + 128 * 512;
        cudaGetSymbolAddress((void**)&p, g_BtM1);    BtM1[0] = p;    BtM1[1] = p + 128 * 128;
        cudaGetSymbolAddress((void**)&p, g_BtM2);    BtM2[0] = p;    BtM2[1] = p + 128 * 128;
    }

    const int dt[5] = {0, 0, 1, 0, 1};
    const int nsz[2] = {NN, NB};
    int ebase[5];
    { int acc = 0; for (int r = 0; r < 5; r++) { ebase[r] = acc; acc += E[r]; } }

    detect_mode_k<<<1, 1>>>(e[0]);

    // ---- CSR build ----
    cudaMemsetAsync(cnti, 0, 5 * NN * sizeof(int));
    for (int r = 0; r < 5; r++)
        counti_k<<<(E[r] + 255) / 256, 256>>>(e[r], E[r], cnti + r * NN);
    for (int r = 0; r < 5; r++) {
        int dn = nsz[dt[r]];
        inv_k<<<(dn + 255) / 256, 256>>>(cnti + r * NN, cntf + r * NN, dn);
    }
    scan1_k<<<dim3(NBX, 5), 256>>>();
    scan2_k<<<1, 32>>>();
    scan3_k<<<dim3(NBX, 5), 256>>>();
    for (int r = 0; r < 5; r++)
        fill_k<<<(E[r] + 255) / 256, 256>>>(e[r], E[r], r, ebase[r]);
    const int* rp[5]; const int* cx[5]; const float* ic[5];
    for (int r = 0; r < 5; r++) {
        rp[r] = rowp + r * (NN + 1);
        cx[r] = colx + ebase[r];
        ic[r] = cntf + r * NN;
    }

    // ---- weight prep (f32 intermediates) ----
    catW_k<<<(3 * 64 * 64 + 255) / 256, 256>>>(projCatN, proj_W, 0, 1, 2, 3, 64, 64);
    catW_k<<<(2 * 64 * 64 + 255) / 256, 256>>>(projCatB, proj_W, 3, 4, 0, 2, 64, 64);
    catW_k<<<1, 256>>>(pbCatN, proj_b, 0, 1, 2, 3, 1, 64);
    catW_k<<<1, 256>>>(pbCatB, proj_b, 3, 4, 0, 2, 1, 64);
    stack_k<<<(3 * 16384 + 255) / 256, 256>>>(Wl1CatN, Wl, 0, 1, 3, 3, 16384);
    stack_k<<<(2 * 16384 + 255) / 256, 256>>>(Wl1CatB, Wl, 2, 4, 0, 2, 16384);
    stack_k<<<(3 * 16384 + 255) / 256, 256>>>(Wl2CatN, Wl + 5 * 16384, 0, 1, 3, 3, 16384);
    sumW_k<<<64, 256>>>(Wr1SumN, Wr, 0, 1, 3, 3, 16384);
    sumW_k<<<64, 256>>>(Wr1SumB, Wr, 2, 4, 0, 2, 16384);
    sumW_k<<<64, 256>>>(Wr2SumN, Wr + 5 * 16384, 0, 1, 3, 3, 16384);
    sumW_k<<<1, 128>>>(b1SumN, bl, 0, 1, 3, 3, 128);
    sumW_k<<<1, 128>>>(b1SumB, bl, 2, 4, 0, 2, 128);
    sumW_k<<<1, 128>>>(b2SumN, bl + 5 * 128, 0, 1, 3, 3, 128);
    bnprep_k<<<1, 128>>>(bnS, bn_g);

    // ---- bf16 transpose+split (zero padded buffers first) ----
    cudaMemsetAsync(BtProjN[0], 0, 2 * 256 * 64 * sizeof(__nv_bfloat16));
    cudaMemsetAsync(BtM2[0],    0, 2 * 128 * 128 * sizeof(__nv_bfloat16));
    tsplb_k<<<(64 * 192 + 255) / 256, 256>>>(BtProjN[0], BtProjN[1], projCatN, 64, 192, 64, 0);
    tsplb_k<<<(64 * 128 + 255) / 256, 256>>>(BtProjB[0], BtProjB[1], projCatB, 64, 128, 64, 0);
    const int l0rel[5] = {0, 1, 3, 2, 4};
    for (int s = 0; s < 5; s++) {
        int r = l0rel[s];
        tsplb_k<<<(64 * 128 + 255) / 256, 256>>>(BtL0[0] + s * 16384, BtL0[1] + s * 16384,
                                                 l0_Wr + (size_t)r * 8192, 64, 128, 128, 0);
        tsplb_k<<<(64 * 128 + 255) / 256, 256>>>(BtL0[0] + s * 16384, BtL0[1] + s * 16384,
                                                 l0_Wl + (size_t)r * 8192, 64, 128, 128, 64);
    }
    tsplb_k<<<(384 * 128 + 255) / 256, 256>>>(BtL1N[0], BtL1N[1], Wl1CatN, 384, 128, 512, 0);
    tsplb_k<<<(128 * 128 + 255) / 256, 256>>>(BtL1N[0], BtL1N[1], Wr1SumN, 128, 128, 512, 384);
    tsplb_k<<<(256 * 128 + 255) / 256, 256>>>(BtL1B[0], BtL1B[1], Wl1CatB, 256, 128, 384, 0);
    tsplb_k<<<(128 * 128 + 255) / 256, 256>>>(BtL1B[0], BtL1B[1], Wr1SumB, 128, 128, 384, 256);
    tsplb_k<<<(384 * 128 + 255) / 256, 256>>>(BtL2N[0], BtL2N[1], Wl2CatN, 384, 128, 512, 0);
    tsplb_k<<<(128 * 128 + 255) / 256, 256>>>(BtL2N[0], BtL2N[1], Wr2SumN, 128, 128, 512, 384);
    tsplb_k<<<(128 * 128 + 255) / 256, 256>>>(BtM1[0], BtM1[1], mlp_W1, 128, 128, 128, 0);
    tsplb_k<<<(128 * 32 + 255) / 256, 256>>>(BtM2[0], BtM2[1], mlp_W2, 128, 32, 128, 0);

    // ==================== layer 0 ====================
    tgemm(1, x_note, 64, 64, nullptr, 0, 0, BtProjN[0], BtProjN[1], 64, pbCatN,
          pn, 192, 0, NN, 192, 1.f, nullptr, nullptr);
    tgemm(1, x_beat, 64, 64, nullptr, 0, 0, BtProjB[0], BtProjB[1], 64, pbCatB,
          pb, 128, 0, NB, 128, 1.f, nullptr, nullptr);
    aggcsr_k<2><<<(NN + 7) / 8, 256>>>(pn, 192, 0,   rp[0], cx[0], ic[0], aggn, 192, 0,   NN);
    aggcsr_k<2><<<(NN + 7) / 8, 256>>>(pn, 192, 64,  rp[1], cx[1], ic[1], aggn, 192, 64,  NN);
    aggcsr_k<2><<<(NN + 7) / 8, 256>>>(pb, 128, 0,   rp[3], cx[3], ic[3], aggn, 192, 128, NN);
    aggcsr_k<2><<<(NB + 7) / 8, 256>>>(pn, 192, 128, rp[2], cx[2], ic[2], aggb, 128, 0,   NB);
    aggcsr_k<2><<<(NB + 7) / 8, 256>>>(pb, 128, 64,  rp[4], cx[4], ic[4], aggb, 128, 64,  NB);
    // per-relation o = [xd | agg_r] @ [Wr_r; Wl_r] + bl_r
    for (int j = 0; j < 3; j++) {
        int r = l0rel[j];
        tgemm(0, x_note, 64, 64, aggn + j * 64, 192, 64,
              BtL0[0] + j * 16384, BtL0[1] + j * 16384, 128, l0_bl + (size_t)r * 128,
              On, 384, j * 128, NN, 128, 1.f, nullptr, nullptr);
    }
    for (int j = 0; j < 2; j++) {
        int s = 3 + j;
        int r = l0rel[s];
        tgemm(0, x_beat, 64, 64, aggb + j * 64, 128, 64,
              BtL0[0] + s * 16384, BtL0[1] + s * 16384, 128, l0_bl + (size_t)r * 128,
              Ob, 256, j * 128, NB, 128, 1.f, nullptr, nullptr);
    }
    l0post_k<3><<<(NN + 7) / 8, 256>>>(On, 384, ln_g, ln_b, xn0, NN);
    l0post_k<2><<<(NB + 7) / 8, 256>>>(Ob, 256, ln_g, ln_b, xb0, NB);

    // ==================== layer 1 ====================
    aggcsr_k<4><<<(NN + 7) / 8, 256>>>(xn0, 128, 0, rp[0], cx[0], ic[0], aggn, 384, 0,   NN);
    aggcsr_k<4><<<(NN + 7) / 8, 256>>>(xn0, 128, 0, rp[1], cx[1], ic[1], aggn, 384, 128, NN);
    aggcsr_k<4><<<(NN + 7) / 8, 256>>>(xb0, 128, 0, rp[3], cx[3], ic[3], aggn, 384, 256, NN);
    aggcsr_k<4><<<(NB + 7) / 8, 256>>>(xn0, 128, 0, rp[2], cx[2], ic[2], aggb, 256, 0,   NB);
    aggcsr_k<4><<<(NB + 7) / 8, 256>>>(xb0, 128, 0, rp[4], cx[4], ic[4], aggb, 256, 128, NB);
    tgemm(0, aggn, 384, 384, xn0, 128, 128, BtL1N[0], BtL1N[1], 512, b1SumN,
          outn, 128, 0, NN, 128, 1.f, nullptr, nullptr);
    tgemm(0, aggb, 256, 256, xb0, 128, 128, BtL1B[0], BtL1B[1], 384, b1SumB,
          outb, 128, 0, NB, 128, 1.f, nullptr, nullptr);
    relu_ln_k<<<(NN + 7) / 8, 256>>>(outn, 1.f / 3.f, ln_g + 128, ln_b + 128, xn1, NN);
    relu_ln_k<<<(NB + 7) / 8, 256>>>(outb, 1.f / 2.f, ln_g + 128, ln_b + 128, xb1, NB);

    // ==================== layer 2 (note dst only) ====================
    aggcsr_k<4><<<(NN + 7) / 8, 256>>>(xn1, 128, 0, rp[0], cx[0], ic[0], aggn, 384, 0,   NN);
    aggcsr_k<4><<<(NN + 7) / 8, 256>>>(xn1, 128, 0, rp[1], cx[1], ic[1], aggn, 384, 128, NN);
    aggcsr_k<4><<<(NN + 7) / 8, 256>>>(xb1, 128, 0, rp[3], cx[3], ic[3], aggn, 384, 256, NN);
    tgemm(0, aggn, 384, 384, xn1, 128, 128, BtL2N[0], BtL2N[1], 512, b2SumN,
          outn, 128, 0, NN, 128, 1.f, nullptr, nullptr);

    // ==================== final MLP ====================
    tgemm(2, outn, 128, 128, nullptr, 0, 0, BtM1[0], BtM1[1], 128, mlp_b1,
          On, 128, 0, NN, 128, 1.f / 3.f, bnS, bn_b);
    tgemm(0, On, 128, 128, nullptr, 0, 0, BtM2[0], BtM2[1], 128, mlp_b2,
          (float*)d_out, 32, 0, NN, 32, 1.f, nullptr, nullptr);
}

// round 6
// speedup vs baseline: 3.4588x; 1.1291x over previous
#include <cuda_runtime.h>
#include <cuda_bf16.h>
#include <mma.h>
#include <cstdint>

using namespace nvcuda;

#define NN 100000
#define NB 20000
#define INC 64
#define HID 128
#define NBX 49
#define MAXE 3000000

// ================= scratch (device globals; no runtime allocation) ==========
__device__ float g_pn  [(size_t)NN * 192];
__device__ float g_pb  [(size_t)NB * 128];
__device__ float g_aggn[(size_t)NN * 384];
__device__ float g_aggb[(size_t)NB * 256];
__device__ float g_On  [(size_t)NN * 384];
__device__ float g_Ob  [(size_t)NB * 256];
__device__ float g_xn0 [(size_t)NN * HID];
__device__ float g_xn1 [(size_t)NN * HID];
__device__ float g_xb0 [(size_t)NB * HID];
__device__ float g_xb1 [(size_t)NB * HID];
__device__ float g_outn[(size_t)NN * HID];
__device__ float g_outb[(size_t)NB * HID];
__device__ float g_cnt [5][NN];
__device__ int   g_cnti[5][NN];
__device__ int   g_rowp[5][NN + 1];
__device__ int   g_bsum[5][64];
__device__ int   g_col [MAXE];
__device__ int   g_emode;

// bias scratch
__device__ float g_pbCatN[192];
__device__ float g_pbCatB[128];
__device__ float g_b1SumN[128];
__device__ float g_b1SumB[128];
__device__ float g_b2SumN[128];
__device__ float g_bnS[128];
// bf16 transposed+split weights [Npad x K], hi/lo
__device__ __nv_bfloat16 g_BtProjN[2][256 * 64];
__device__ __nv_bfloat16 g_BtProjB[2][128 * 64];
__device__ __nv_bfloat16 g_BtL0  [2][5][128 * 128];
__device__ __nv_bfloat16 g_BtL1N [2][128 * 512];
__device__ __nv_bfloat16 g_BtL1B [2][128 * 384];
__device__ __nv_bfloat16 g_BtL2N [2][128 * 512];
__device__ __nv_bfloat16 g_BtM1  [2][128 * 128];
__device__ __nv_bfloat16 g_BtM2  [2][128 * 128];

// ================= edge handling / CSR ======================================
__global__ void detect_mode_k(const int* e) {
    int z = 1;
    for (int i = 1; i < 64; i += 2)
        if (e[i] != 0) z = 0;
    g_emode = z;
}
__device__ __forceinline__ int edge_at(const int* e, long long i) {
    if (g_emode) return (int)((const long long*)e)[i];
    return e[i];
}
// fused degree count over all 5 relations (grid.y = relation)
__global__ void counti5_k(const int* e0, const int* e1, const int* e2,
                          const int* e3, const int* e4,
                          int E0, int E1, int E2, int E3, int E4) {
    int r = blockIdx.y;
    const int* e; int E;
    switch (r) {
        case 0: e = e0; E = E0; break;
        case 1: e = e1; E = E1; break;
        case 2: e = e2; E = E2; break;
        case 3: e = e3; E = E3; break;
        default: e = e4; E = E4; break;
    }
    int i = blockIdx.x * 256 + threadIdx.x;
    if (i >= E) return;
    atomicAdd(&g_cnti[r][edge_at(e, (long long)E + i)], 1);
}
// scan pass 1 (also emits 1/deg float)
__global__ void scan1_k() {
    int r = blockIdx.y;
    int n = (r == 2 || r == 4) ? NB : NN;
    int t = threadIdx.x;
    int base = blockIdx.x * 2048 + t * 8;
    int vals[8];
#pragma unroll
    for (int j = 0; j < 8; j++) {
        int idx = base + j;
        vals[j] = (idx < n) ? g_cnti[r][idx] : 0;
        if (idx < n) g_cnt[r][idx] = 1.0f / (float)max(vals[j], 1);
    }
    int tot = 0;
#pragma unroll
    for (int j = 0; j < 8; j++) tot += vals[j];
    int lane = t & 31, wid = t >> 5;
    int x = tot;
#pragma unroll
    for (int o = 1; o < 32; o <<= 1) {
        int y = __shfl_up_sync(0xffffffffu, x, o);
        if (lane >= o) x += y;
    }
    __shared__ int wsum[8];
    if (lane == 31) wsum[wid] = x;
    __syncthreads();
    if (t == 0) {
        int run = 0;
#pragma unroll
        for (int i = 0; i < 8; i++) { int v = wsum[i]; wsum[i] = run; run += v; }
        g_bsum[r][blockIdx.x] = run;
    }
    __syncthreads();
    int run = (x - tot) + wsum[wid];
#pragma unroll
    for (int j = 0; j < 8; j++) {
        int idx = base + j;
        if (idx < n) g_rowp[r][idx] = run;
        run += vals[j];
    }
}
__global__ void scan2_k() {
    int r = threadIdx.x;
    if (r >= 5) return;
    int n = (r == 2 || r == 4) ? NB : NN;
    int run = 0;
    for (int i = 0; i < NBX; i++) { int v = g_bsum[r][i]; g_bsum[r][i] = run; run += v; }
    g_rowp[r][n] = run;
}
__global__ void scan3_k() {
    int r = blockIdx.y;
    int n = (r == 2 || r == 4) ? NB : NN;
    int add = g_bsum[r][blockIdx.x];
    int base = blockIdx.x * 2048 + threadIdx.x * 8;
#pragma unroll
    for (int j = 0; j < 8; j++) {
        int idx = base + j;
        if (idx < n) {
            int v = g_rowp[r][idx] + add;
            g_rowp[r][idx] = v;
            g_cnti[r][idx] = v;
        }
    }
}
__global__ void fill5_k(const int* e0, const int* e1, const int* e2,
                        const int* e3, const int* e4,
                        int E0, int E1, int E2, int E3, int E4,
                        int b0, int b1, int b2, int b3, int b4) {
    int r = blockIdx.y;
    const int* e; int E; int eb;
    switch (r) {
        case 0: e = e0; E = E0; eb = b0; break;
        case 1: e = e1; E = E1; eb = b1; break;
        case 2: e = e2; E = E2; eb = b2; break;
        case 3: e = e3; E = E3; eb = b3; break;
        default: e = e4; E = E4; eb = b4; break;
    }
    int i = blockIdx.x * 256 + threadIdx.x;
    if (i >= E) return;
    int s = edge_at(e, i);
    int d = edge_at(e, (long long)E + i);
    int pos = atomicAdd(&g_cnti[r][d], 1);
    g_col[eb + pos] = s;
}

// ---- CSR seg-mean aggregation (warp per dst row, 4-edge unroll) ------------
template <int V>
__global__ void aggcsr_k(const float* __restrict__ xf, int lds, int soff,
                         const int* __restrict__ rowp, const int* __restrict__ col,
                         const float* __restrict__ invc,
                         float* __restrict__ agg, int ldd, int doff, int n) {
    int row = blockIdx.x * 8 + (threadIdx.x >> 5);
    if (row >= n) return;
    int lane = threadIdx.x & 31;
    int beg = rowp[row], end = rowp[row + 1];
    float acc[V];
#pragma unroll
    for (int j = 0; j < V; j++) acc[j] = 0.0f;
    int e = beg;
    for (; e + 3 < end; e += 4) {
        int s0 = __ldg(&col[e]);
        int s1 = __ldg(&col[e + 1]);
        int s2 = __ldg(&col[e + 2]);
        int s3 = __ldg(&col[e + 3]);
        const float* p0 = xf + (size_t)s0 * lds + soff + lane * V;
        const float* p1 = xf + (size_t)s1 * lds + soff + lane * V;
        const float* p2 = xf + (size_t)s2 * lds + soff + lane * V;
        const float* p3 = xf + (size_t)s3 * lds + soff + lane * V;
        if (V == 4) {
            float4 a = *(const float4*)p0;
            float4 b = *(const float4*)p1;
            float4 c = *(const float4*)p2;
            float4 d = *(const float4*)p3;
            acc[0] += (a.x + b.x) + (c.x + d.x);
            acc[1] += (a.y + b.y) + (c.y + d.y);
            acc[2] += (a.z + b.z) + (c.z + d.z);
            acc[3] += (a.w + b.w) + (c.w + d.w);
        } else {
            float2 a = *(const float2*)p0;
            float2 b = *(const float2*)p1;
            float2 c = *(const float2*)p2;
            float2 d = *(const float2*)p3;
            acc[0] += (a.x + b.x) + (c.x + d.x);
            acc[1] += (a.y + b.y) + (c.y + d.y);
        }
    }
    for (; e < end; e++) {
        int s0 = __ldg(&col[e]);
        const float* p0 = xf + (size_t)s0 * lds + soff + lane * V;
        if (V == 4) {
            float4 a = *(const float4*)p0;
            acc[0] += a.x; acc[1] += a.y; acc[2] += a.z; acc[3] += a.w;
        } else {
            float2 a = *(const float2*)p0;
            acc[0] += a.x; acc[1] += a.y;
        }
    }
    float inv = invc[row];
    float* q = agg + (size_t)row * ldd + doff + lane * V;
    if (V == 4) {
        *(float4*)q = make_float4(acc[0] * inv, acc[1] * inv, acc[2] * inv, acc[3] * inv);
    } else {
        *(float2*)q = make_float2(acc[0] * inv, acc[1] * inv);
    }
}

// ================= wmma bf16 split GEMM (pipelined) ==========================
// C[m, coff+n] = epi(alpha*(A@W) + bias[n]); A = [A1(K1)|A2(K2)] f32 row-major.
// W pre-transposed+split bf16 [Npad x K]. Computes hi*hi + hi*lo + lo*hi.
template <int EPI>
__global__ __launch_bounds__(256) void tgemm_k(
    const float* __restrict__ A1, int lda1, int K1,
    const float* __restrict__ A2, int lda2, int K2,
    const __nv_bfloat16* __restrict__ Bhi, const __nv_bfloat16* __restrict__ Blo,
    int ldK, const float* __restrict__ bias,
    float* __restrict__ C, int ldc, int coff,
    int M, int Nfull, float alpha,
    const float* __restrict__ bnS, const float* __restrict__ bnB)
{
    __shared__ __align__(16) __nv_bfloat16 Abuf[2][2][128][40];  // [buf][hi/lo]

    int tid = threadIdx.x;
    int wid = tid >> 5, lane = tid & 31;
    int wm = wid >> 2, wn = wid & 3;
    int m0 = blockIdx.x * 128, n0 = blockIdx.y * 128;
    int mw = m0 + wm * 64;
    int nw = n0 + wn * 32;
    bool active = (nw < Nfull);
    int K = K1 + K2;
    int nkt = K >> 5;

    wmma::fragment<wmma::accumulator, 16, 16, 16, float> acc[4][2];
#pragma unroll
    for (int i = 0; i < 4; i++)
#pragma unroll
        for (int j = 0; j < 2; j++) wmma::fill_fragment(acc[i][j], 0.0f);

    int row = tid >> 1, half = tid & 1;
    int m = m0 + row;
    bool mok = (m < M);

    float4 v[4];
    {
        const float* Ap; int ld, kl;
        if (0 < K1) { Ap = A1; ld = lda1; kl = 0; }
        else        { Ap = A2; ld = lda2; kl = -K1; }
        const float* src = Ap + (size_t)m * ld + kl + half * 16;
#pragma unroll
        for (int i = 0; i < 4; i++)
            v[i] = mok ? *(const float4*)(src + i * 4) : make_float4(0.f, 0.f, 0.f, 0.f);
    }

    int buf = 0;
    for (int kt = 0; kt < nkt; kt++) {
        // convert prefetched regs -> smem hi/lo
#pragma unroll
        for (int i = 0; i < 4; i++) {
            int col = half * 16 + i * 4;
            float4 x = v[i];
            __nv_bfloat16 hx = __float2bfloat16_rn(x.x);
            __nv_bfloat16 hy = __float2bfloat16_rn(x.y);
            __nv_bfloat16 hz = __float2bfloat16_rn(x.z);
            __nv_bfloat16 hw = __float2bfloat16_rn(x.w);
            Abuf[buf][0][row][col + 0] = hx;
            Abuf[buf][0][row][col + 1] = hy;
            Abuf[buf][0][row][col + 2] = hz;
            Abuf[buf][0][row][col + 3] = hw;
            Abuf[buf][1][row][col + 0] = __float2bfloat16_rn(x.x - __bfloat162float(hx));
            Abuf[buf][1][row][col + 1] = __float2bfloat16_rn(x.y - __bfloat162float(hy));
            Abuf[buf][1][row][col + 2] = __float2bfloat16_rn(x.z - __bfloat162float(hz));
            Abuf[buf][1][row][col + 3] = __float2bfloat16_rn(x.w - __bfloat162float(hw));
        }
        __syncthreads();
        // prefetch next tile (overlaps with MMA below)
        if (kt + 1 < nkt) {
            int k0 = (kt + 1) << 5;
            const float* Ap; int ld, kl;
            if (k0 < K1) { Ap = A1; ld = lda1; kl = k0; }
            else         { Ap = A2; ld = lda2; kl = k0 - K1; }
            const float* src = Ap + (size_t)m * ld + kl + half * 16;
#pragma unroll
            for (int i = 0; i < 4; i++)
                v[i] = mok ? *(const float4*)(src + i * 4) : make_float4(0.f, 0.f, 0.f, 0.f);
        }
        if (active) {
            int k0g = kt << 5;
#pragma unroll
            for (int kk = 0; kk < 32; kk += 16) {
                wmma::fragment<wmma::matrix_b, 16, 16, 16, __nv_bfloat16, wmma::col_major> bh[2], bl2[2];
#pragma unroll
                for (int j = 0; j < 2; j++) {
                    const __nv_bfloat16* bp = Bhi + (size_t)(nw + j * 16) * ldK + (k0g + kk);
                    const __nv_bfloat16* lp = Blo + (size_t)(nw + j * 16) * ldK + (k0g + kk);
                    wmma::load_matrix_sync(bh[j],  bp, (unsigned)ldK);
                    wmma::load_matrix_sync(bl2[j], lp, (unsigned)ldK);
                }
#pragma unroll
                for (int i = 0; i < 4; i++) {
                    wmma::fragment<wmma::matrix_a, 16, 16, 16, __nv_bfloat16, wmma::row_major> ah, al;
                    wmma::load_matrix_sync(ah, &Abuf[buf][0][wm * 64 + i * 16][0] + kk, 40u);
                    wmma::load_matrix_sync(al, &Abuf[buf][1][wm * 64 + i * 16][0] + kk, 40u);
#pragma unroll
                    for (int j = 0; j < 2; j++) {
                        wmma::mma_sync(acc[i][j], ah, bh[j],  acc[i][j]);
                        wmma::mma_sync(acc[i][j], ah, bl2[j], acc[i][j]);
                        wmma::mma_sync(acc[i][j], al, bh[j],  acc[i][j]);
                    }
                }
            }
        }
        buf ^= 1;
    }
    __syncthreads();

    // epilogue: per-warp patch aliased on A buffers
    if (active) {
        float* myp = reinterpret_cast<float*>(&Abuf[0][0][0][0]) + wid * 320;
        int base = lane * 8;
        int pr = base >> 4, pc = base & 15;
#pragma unroll
        for (int i = 0; i < 4; i++) {
#pragma unroll
            for (int j = 0; j < 2; j++) {
                wmma::store_matrix_sync(myp, acc[i][j], 20u, wmma::mem_row_major);
                __syncwarp();
                int mb = mw + i * 16, nb = nw + j * 16;
                if (mb + pr < M) {
                    float out[8];
#pragma unroll
                    for (int t = 0; t < 8; t++) {
                        int n = nb + pc + t;
                        float val = myp[pr * 20 + pc + t] * alpha + bias[n];
                        if (EPI >= 1) val = fmaxf(val, 0.0f);
                        if (EPI == 2) val = val * bnS[n] + bnB[n];
                        out[t] = val;
                    }
                    float* dst = C + (size_t)(mb + pr) * ldc + coff + nb + pc;
                    *(float4*)dst = *(float4*)&out[0];
                    *(float4*)(dst + 4) = *(float4*)&out[4];
                }
                __syncwarp();
            }
        }
    }
}

// ================= elementwise kernels =======================================
template <int R>
__global__ void l0post_k(const float* __restrict__ O, int ldo,
                         const float* __restrict__ gg, const float* __restrict__ bb,
                         float* __restrict__ xout, int M) {
    int row = blockIdx.x * 8 + (threadIdx.x >> 5);
    if (row >= M) return;
    int lane = threadIdx.x & 31;
    float acc[4] = {0.f, 0.f, 0.f, 0.f};
#pragma unroll
    for (int rb = 0; rb < R; rb++) {
        const float* p = O + (size_t)row * ldo + rb * 128;
        float v[4]; float ss = 0.f;
#pragma unroll
        for (int j = 0; j < 4; j++) { v[j] = p[lane + 32 * j]; ss += v[j] * v[j]; }
#pragma unroll
        for (int s = 16; s; s >>= 1) ss += __shfl_xor_sync(0xffffffffu, ss, s);
        float inv = 1.0f / fmaxf(sqrtf(ss), 1e-12f);
#pragma unroll
        for (int j = 0; j < 4; j++) acc[j] += v[j] * inv;
    }
    const float invR = 1.0f / R;
    float s = 0.f;
#pragma unroll
    for (int j = 0; j < 4; j++) { acc[j] = fmaxf(acc[j] * invR, 0.f); s += acc[j]; }
#pragma unroll
    for (int o = 16; o; o >>= 1) s += __shfl_xor_sync(0xffffffffu, s, o);
    float m = s * (1.0f / 128.0f);
    float ss = 0.f;
#pragma unroll
    for (int j = 0; j < 4; j++) { float d = acc[j] - m; ss += d * d; }
#pragma unroll
    for (int o = 16; o; o >>= 1) ss += __shfl_xor_sync(0xffffffffu, ss, o);
    float inv = rsqrtf(ss * (1.0f / 128.0f) + 1e-5f);
    float* q = xout + (size_t)row * 128;
#pragma unroll
    for (int j = 0; j < 4; j++) {
        int c = lane + 32 * j;
        q[c] = (acc[j] - m) * inv * gg[c] + bb[c];
    }
}
__global__ void relu_ln_k(const float* __restrict__ acc, float invr,
                          const float* __restrict__ gg, const float* __restrict__ bb,
                          float* __restrict__ xout, int M) {
    int row = blockIdx.x * 8 + (threadIdx.x >> 5);
    if (row >= M) return;
    int lane = threadIdx.x & 31;
    const float* p = acc + (size_t)row * 128;
    float v[4]; float s = 0.f;
#pragma unroll
    for (int j = 0; j < 4; j++) { v[j] = fmaxf(p[lane + 32 * j] * invr, 0.f); s += v[j]; }
#pragma unroll
    for (int o = 16; o; o >>= 1) s += __shfl_xor_sync(0xffffffffu, s, o);
    float m = s * (1.0f / 128.0f);
    float ss = 0.f;
#pragma unroll
    for (int j = 0; j < 4; j++) { float d = v[j] - m; ss += d * d; }
#pragma unroll
    for (int o = 16; o; o >>= 1) ss += __shfl_xor_sync(0xffffffffu, ss, o);
    float inv = rsqrtf(ss * (1.0f / 128.0f) + 1e-5f);
    float* q = xout + (size_t)row * 128;
#pragma unroll
    for (int j = 0; j < 4; j++) {
        int c = lane + 32 * j;
        q[c] = (v[j] - m) * inv * gg[c] + bb[c];
    }
}

// ================= fused weight prep =========================================
__device__ __forceinline__ void bsplit(float x, __nv_bfloat16& h, __nv_bfloat16& l) {
    h = __float2bfloat16_rn(x);
    l = __float2bfloat16_rn(x - __bfloat162float(h));
}
// proj: dst[NxK=64] hi/lo from proj_W rels
__global__ void psplit_k(__nv_bfloat16* __restrict__ hi, __nv_bfloat16* __restrict__ lo,
                         const float* __restrict__ proj_W, int r0, int r1, int r2, int nrel) {
    int tot = nrel * 4096;
    int idx = blockIdx.x * 256 + threadIdx.x;
    if (idx >= tot) return;
    int j = idx >> 12, rem = idx & 4095;
    int k = rem >> 6, c = rem & 63;
    int r = (j == 0) ? r0 : (j == 1) ? r1 : r2;
    float x = proj_W[(size_t)r * 4096 + k * 64 + c];
    int n = j * 64 + c;
    __nv_bfloat16 h, l;
    bsplit(x, h, l);
    hi[n * 64 + k] = h;
    lo[n * 64 + k] = l;
}
// layer0: all 5 slots, dst[s][n][k], k<64 from Wr, else Wl
__global__ void l0split_k(__nv_bfloat16* __restrict__ hi, __nv_bfloat16* __restrict__ lo,
                          const float* __restrict__ l0_Wr, const float* __restrict__ l0_Wl) {
    int idx = blockIdx.x * 256 + threadIdx.x;
    if (idx >= 5 * 16384) return;
    int s = idx >> 14, rem = idx & 16383;
    int n = rem >> 7, k = rem & 127;
    const int rels[5] = {0, 1, 3, 2, 4};
    int r = rels[s];
    float x = (k < 64) ? l0_Wr[(size_t)r * 8192 + k * 128 + n]
                       : l0_Wl[(size_t)r * 8192 + (k - 64) * 128 + n];
    __nv_bfloat16 h, l;
    bsplit(x, h, l);
    hi[idx] = h;
    lo[idx] = l;
}
// layers 1/2: dst[n][k], k<nrel*128 -> Wl concat, else sum of Wr
__global__ void lsplit_k(__nv_bfloat16* __restrict__ hi, __nv_bfloat16* __restrict__ lo,
                         const float* __restrict__ WlL, const float* __restrict__ WrL,
                         int r0, int r1, int r2, int nrel) {
    int K = nrel * 128 + 128;
    int tot = 128 * K;
    int idx = blockIdx.x * 256 + threadIdx.x;
    if (idx >= tot) return;
    int n = idx / K, k = idx - n * K;
    float x;
    if (k < nrel * 128) {
        int j = k >> 7, kk = k & 127;
        int r = (j == 0) ? r0 : (j == 1) ? r1 : r2;
        x = WlL[(size_t)r * 16384 + kk * 128 + n];
    } else {
        int kk = k - nrel * 128;
        x = WrL[(size_t)r0 * 16384 + kk * 128 + n] + WrL[(size_t)r1 * 16384 + kk * 128 + n];
        if (nrel == 3) x += WrL[(size_t)r2 * 16384 + kk * 128 + n];
    }
    __nv_bfloat16 h, l;
    bsplit(x, h, l);
    hi[idx] = h;
    lo[idx] = l;
}
// plain transpose+split (MLP weights)
__global__ void tsplb_k(__nv_bfloat16* __restrict__ hi, __nv_bfloat16* __restrict__ lo,
                        const float* __restrict__ src, int K, int N, int ldK) {
    int idx = blockIdx.x * 256 + threadIdx.x;
    if (idx >= K * N) return;
    int k = idx / N, n = idx - (idx / N) * N;
    __nv_bfloat16 h, l;
    bsplit(src[idx], h, l);
    hi[(size_t)n * ldK + k] = h;
    lo[(size_t)n * ldK + k] = l;
}
// bias prep
__global__ void catB_k(float* __restrict__ dst, const float* __restrict__ src,
                       int r0, int r1, int r2, int nrel, int C) {
    int idx = blockIdx.x * 256 + threadIdx.x;
    if (idx >= nrel * C) return;
    int j = idx / C, c = idx - j * C;
    int r = (j == 0) ? r0 : (j == 1) ? r1 : r2;
    dst[idx] = src[(size_t)r * C + c];
}
__global__ void sumB_k(float* __restrict__ dst, const float* __restrict__ src,
                       int r0, int r1, int r2, int nrel) {
    int idx = threadIdx.x;
    float v = src[(size_t)r0 * 128 + idx] + src[(size_t)r1 * 128 + idx];
    if (nrel == 3) v += src[(size_t)r2 * 128 + idx];
    dst[idx] = v;
}
__global__ void bnprep_k(float* __restrict__ sc, const float* __restrict__ g) {
    int i = threadIdx.x;
    sc[i] = g[i] * rsqrtf(1.0f + 1e-5f);
}

// ================= host dispatch =============================================
static void tgemm(int epi, const float* A1, int lda1, int K1,
                  const float* A2, int lda2, int K2,
                  const __nv_bfloat16* Bh, const __nv_bfloat16* Bl, int ldK,
                  const float* bias, float* C, int ldc, int coff,
                  int M, int Nfull, float alpha,
                  const float* bnS, const float* bnB) {
    dim3 g((M + 127) / 128, (Nfull + 127) / 128);
    if (epi == 0)
        tgemm_k<0><<<g, 256>>>(A1, lda1, K1, A2, lda2, K2, Bh, Bl, ldK, bias, C, ldc, coff, M, Nfull, alpha, bnS, bnB);
    else if (epi == 1)
        tgemm_k<1><<<g, 256>>>(A1, lda1, K1, A2, lda2, K2, Bh, Bl, ldK, bias, C, ldc, coff, M, Nfull, alpha, bnS, bnB);
    else
        tgemm_k<2><<<g, 256>>>(A1, lda1, K1, A2, lda2, K2, Bh, Bl, ldK, bias, C, ldc, coff, M, Nfull, alpha, bnS, bnB);
}

extern "C" void kernel_launch(void* const* d_in, const int* in_sizes, int n_in,
                              void* d_out, int out_size) {
    const float* x_note = (const float*)d_in[0];
    const float* x_beat = (const float*)d_in[1];
    const int* e[5] = {(const int*)d_in[2], (const int*)d_in[3], (const int*)d_in[4],
                       (const int*)d_in[5], (const int*)d_in[6]};
    int E[5];
    for (int r = 0; r < 5; r++) E[r] = in_sizes[2 + r] / 2;
    const float* proj_W = (const float*)d_in[7];
    const float* proj_b = (const float*)d_in[8];
    const float* l0_Wl  = (const float*)d_in[9];
    const float* l0_bl  = (const float*)d_in[10];
    const float* l0_Wr  = (const float*)d_in[11];
    const float* Wl     = (const float*)d_in[12];
    const float* bl     = (const float*)d_in[13];
    const float* Wr     = (const float*)d_in[14];
    const float* ln_g   = (const float*)d_in[15];
    const float* ln_b   = (const float*)d_in[16];
    const float* mlp_W1 = (const float*)d_in[17];
    const float* mlp_b1 = (const float*)d_in[18];
    const float* bn_g   = (const float*)d_in[19];
    const float* bn_b   = (const float*)d_in[20];
    const float* mlp_W2 = (const float*)d_in[21];
    const float* mlp_b2 = (const float*)d_in[22];

    float *pn, *pb, *aggn, *aggb, *On, *Ob, *xn0, *xn1, *xb0, *xb1, *outn, *outb, *cntf;
    int *cnti, *rowp, *colx;
    cudaGetSymbolAddress((void**)&pn, g_pn);       cudaGetSymbolAddress((void**)&pb, g_pb);
    cudaGetSymbolAddress((void**)&aggn, g_aggn);   cudaGetSymbolAddress((void**)&aggb, g_aggb);
    cudaGetSymbolAddress((void**)&On, g_On);       cudaGetSymbolAddress((void**)&Ob, g_Ob);
    cudaGetSymbolAddress((void**)&xn0, g_xn0);     cudaGetSymbolAddress((void**)&xn1, g_xn1);
    cudaGetSymbolAddress((void**)&xb0, g_xb0);     cudaGetSymbolAddress((void**)&xb1, g_xb1);
    cudaGetSymbolAddress((void**)&outn, g_outn);   cudaGetSymbolAddress((void**)&outb, g_outb);
    cudaGetSymbolAddress((void**)&cntf, g_cnt);    cudaGetSymbolAddress((void**)&cnti, g_cnti);
    cudaGetSymbolAddress((void**)&rowp, g_rowp);   cudaGetSymbolAddress((void**)&colx, g_col);

    float *pbCatN, *pbCatB, *b1SumN, *b1SumB, *b2SumN, *bnS;
    cudaGetSymbolAddress((void**)&pbCatN, g_pbCatN); cudaGetSymbolAddress((void**)&pbCatB, g_pbCatB);
    cudaGetSymbolAddress((void**)&b1SumN, g_b1SumN); cudaGetSymbolAddress((void**)&b1SumB, g_b1SumB);
    cudaGetSymbolAddress((void**)&b2SumN, g_b2SumN); cudaGetSymbolAddress((void**)&bnS, g_bnS);

    __nv_bfloat16 *BtProjN[2], *BtProjB[2], *BtL0[2], *BtL1N[2], *BtL1B[2], *BtL2N[2], *BtM1[2], *BtM2[2];
    {
        __nv_bfloat16* p;
        cudaGetSymbolAddress((void**)&p, g_BtProjN); BtProjN[0] = p; BtProjN[1] = p + 256 * 64;
        cudaGetSymbolAddress((void**)&p, g_BtProjB); BtProjB[0] = p; BtProjB[1] = p + 128 * 64;
        cudaGetSymbolAddress((void**)&p, g_BtL0);    BtL0[0] = p;    BtL0[1] = p + 5 * 128 * 128;
        cudaGetSymbolAddress((void**)&p, g_BtL1N);   BtL1N[0] = p;   BtL1N[1] = p + 128 * 512;
        cudaGetSymbolAddress((void**)&p, g_BtL1B);   BtL1B[0] = p;   BtL1B[1] = p + 128 * 384;
        cudaGetSymbolAddress((void**)&p, g_BtL2N);   BtL2N[0] = p;   BtL2N[1] = p + 128 * 512;
        cudaGetSymbolAddress((void**)&p, g_BtM1);    BtM1[0] = p;    BtM1[1] = p + 128 * 128;
        cudaGetSymbolAddress((void**)&p, g_BtM2);    BtM2[0] = p;    BtM2[1] = p + 128 * 128;
    }

    int ebase[5];
    { int acc = 0; for (int r = 0; r < 5; r++) { ebase[r] = acc; acc += E[r]; } }
    int maxE = 0;
    for (int r = 0; r < 5; r++) maxE = (E[r] > maxE) ? E[r] : maxE;

    detect_mode_k<<<1, 1>>>(e[0]);

    // ---- CSR build (fused) ----
    cudaMemsetAsync(cnti, 0, 5 * NN * sizeof(int));
    counti5_k<<<dim3((maxE + 255) / 256, 5), 256>>>(e[0], e[1], e[2], e[3], e[4],
                                                    E[0], E[1], E[2], E[3], E[4]);
    scan1_k<<<dim3(NBX, 5), 256>>>();
    scan2_k<<<1, 32>>>();
    scan3_k<<<dim3(NBX, 5), 256>>>();
    fill5_k<<<dim3((maxE + 255) / 256, 5), 256>>>(e[0], e[1], e[2], e[3], e[4],
                                                  E[0], E[1], E[2], E[3], E[4],
                                                  ebase[0], ebase[1], ebase[2], ebase[3], ebase[4]);
    const int* rp[5]; const int* cx[5]; const float* ic[5];
    for (int r = 0; r < 5; r++) {
        rp[r] = rowp + r * (NN + 1);
        cx[r] = colx + ebase[r];
        ic[r] = cntf + r * NN;
    }

    // ---- fused weight prep ----
    psplit_k<<<(3 * 4096 + 255) / 256, 256>>>(BtProjN[0], BtProjN[1], proj_W, 0, 1, 2, 3);
    psplit_k<<<(2 * 4096 + 255) / 256, 256>>>(BtProjB[0], BtProjB[1], proj_W, 3, 4, 0, 2);
    l0split_k<<<(5 * 16384 + 255) / 256, 256>>>(BtL0[0], BtL0[1], l0_Wr, l0_Wl);
    lsplit_k<<<(128 * 512 + 255) / 256, 256>>>(BtL1N[0], BtL1N[1], Wl, Wr, 0, 1, 3, 3);
    lsplit_k<<<(128 * 384 + 255) / 256, 256>>>(BtL1B[0], BtL1B[1], Wl, Wr, 2, 4, 0, 2);
    lsplit_k<<<(128 * 512 + 255) / 256, 256>>>(BtL2N[0], BtL2N[1], Wl + 5 * 16384, Wr + 5 * 16384, 0, 1, 3, 3);
    tsplb_k<<<(128 * 128 + 255) / 256, 256>>>(BtM1[0], BtM1[1], mlp_W1, 128, 128, 128);
    tsplb_k<<<(128 * 32 + 255) / 256, 256>>>(BtM2[0], BtM2[1], mlp_W2, 128, 32, 128);
    catB_k<<<1, 256>>>(pbCatN, proj_b, 0, 1, 2, 3, 64);
    catB_k<<<1, 256>>>(pbCatB, proj_b, 3, 4, 0, 2, 64);
    sumB_k<<<1, 128>>>(b1SumN, bl, 0, 1, 3, 3);
    sumB_k<<<1, 128>>>(b1SumB, bl, 2, 4, 0, 2);
    sumB_k<<<1, 128>>>(b2SumN, bl + 5 * 128, 0, 1, 3, 3);
    bnprep_k<<<1, 128>>>(bnS, bn_g);

    // ==================== layer 0 ====================
    tgemm(1, x_note, 64, 64, nullptr, 0, 0, BtProjN[0], BtProjN[1], 64, pbCatN,
          pn, 192, 0, NN, 192, 1.f, nullptr, nullptr);
    tgemm(1, x_beat, 64, 64, nullptr, 0, 0, BtProjB[0], BtProjB[1], 64, pbCatB,
          pb, 128, 0, NB, 128, 1.f, nullptr, nullptr);
    aggcsr_k<2><<<(NN + 7) / 8, 256>>>(pn, 192, 0,   rp[0], cx[0], ic[0], aggn, 192, 0,   NN);
    aggcsr_k<2><<<(NN + 7) / 8, 256>>>(pn, 192, 64,  rp[1], cx[1], ic[1], aggn, 192, 64,  NN);
    aggcsr_k<2><<<(NN + 7) / 8, 256>>>(pb, 128, 0,   rp[3], cx[3], ic[3], aggn, 192, 128, NN);
    aggcsr_k<2><<<(NB + 7) / 8, 256>>>(pn, 192, 128, rp[2], cx[2], ic[2], aggb, 128, 0,   NB);
    aggcsr_k<2><<<(NB + 7) / 8, 256>>>(pb, 128, 64,  rp[4], cx[4], ic[4], aggb, 128, 64,  NB);
    const int l0rel[5] = {0, 1, 3, 2, 4};
    for (int j = 0; j < 3; j++) {
        int r = l0rel[j];
        tgemm(0, x_note, 64, 64, aggn + j * 64, 192, 64,
              BtL0[0] + j * 16384, BtL0[1] + j * 16384, 128, l0_bl + (size_t)r * 128,
              On, 384, j * 128, NN, 128, 1.f, nullptr, nullptr);
    }
    for (int j = 0; j < 2; j++) {
        int s = 3 + j;
        int r = l0rel[s];
        tgemm(0, x_beat, 64, 64, aggb + j * 64, 128, 64,
              BtL0[0] + s * 16384, BtL0[1] + s * 16384, 128, l0_bl + (size_t)r * 128,
              Ob, 256, j * 128, NB, 128, 1.f, nullptr, nullptr);
    }
    l0post_k<3><<<(NN + 7) / 8, 256>>>(On, 384, ln_g, ln_b, xn0, NN);
    l0post_k<2><<<(NB + 7) / 8, 256>>>(Ob, 256, ln_g, ln_b, xb0, NB);

    // ==================== layer 1 ====================
    aggcsr_k<4><<<(NN + 7) / 8, 256>>>(xn0, 128, 0, rp[0], cx[0], ic[0], aggn, 384, 0,   NN);
    aggcsr_k<4><<<(NN + 7) / 8, 256>>>(xn0, 128, 0, rp[1], cx[1], ic[1], aggn, 384, 128, NN);
    aggcsr_k<4><<<(NN + 7) / 8, 256>>>(xb0, 128, 0, rp[3], cx[3], ic[3], aggn, 384, 256, NN);
    aggcsr_k<4><<<(NB + 7) / 8, 256>>>(xn0, 128, 0, rp[2], cx[2], ic[2], aggb, 256, 0,   NB);
    aggcsr_k<4><<<(NB + 7) / 8, 256>>>(xb0, 128, 0, rp[4], cx[4], ic[4], aggb, 256, 128, NB);
    tgemm(0, aggn, 384, 384, xn0, 128, 128, BtL1N[0], BtL1N[1], 512, b1SumN,
          outn, 128, 0, NN, 128, 1.f, nullptr, nullptr);
    tgemm(0, aggb, 256, 256, xb0, 128, 128, BtL1B[0], BtL1B[1], 384, b1SumB,
          outb, 128, 0, NB, 128, 1.f, nullptr, nullptr);
    relu_ln_k<<<(NN + 7) / 8, 256>>>(outn, 1.f / 3.f, ln_g + 128, ln_b + 128, xn1, NN);
    relu_ln_k<<<(NB + 7) / 8, 256>>>(outb, 1.f / 2.f, ln_g + 128, ln_b + 128, xb1, NB);

    // ==================== layer 2 (note dst only) ====================
    aggcsr_k<4><<<(NN + 7) / 8, 256>>>(xn1, 128, 0, rp[0], cx[0], ic[0], aggn, 384, 0,   NN);
    aggcsr_k<4><<<(NN + 7) / 8, 256>>>(xn1, 128, 0, rp[1], cx[1], ic[1], aggn, 384, 128, NN);
    aggcsr_k<4><<<(NN + 7) / 8, 256>>>(xb1, 128, 0, rp[3], cx[3], ic[3], aggn, 384, 256, NN);
    tgemm(0, aggn, 384, 384, xn1, 128, 128, BtL2N[0], BtL2N[1], 512, b2SumN,
          outn, 128, 0, NN, 128, 1.f, nullptr, nullptr);

    // ==================== final MLP ====================
    tgemm(2, outn, 128, 128, nullptr, 0, 0, BtM1[0], BtM1[1], 128, mlp_b1,
          On, 128, 0, NN, 128, 1.f / 3.f, bnS, bn_b);
    tgemm(0, On, 128, 128, nullptr, 0, 0, BtM2[0], BtM2[1], 128, mlp_b2,
          (float*)d_out, 32, 0, NN, 32, 1.f, nullptr, nullptr);
}

// round 7
// speedup vs baseline: 3.7545x; 1.0855x over previous
#include <cuda_runtime.h>
#include <cuda_bf16.h>
#include <mma.h>
#include <cstdint>

using namespace nvcuda;

#define NN 100000
#define NB 20000
#define INC 64
#define HID 128
#define NBX 49
#define MAXE 3000000

// ================= scratch (device globals; no runtime allocation) ==========
__device__ float g_pn  [(size_t)NN * 192];
__device__ float g_pb  [(size_t)NB * 128];
__device__ float g_aggn[(size_t)NN * 384];
__device__ float g_aggb[(size_t)NB * 256];
__device__ float g_On  [(size_t)NN * 384];
__device__ float g_Ob  [(size_t)NB * 256];
__device__ float g_xn0 [(size_t)NN * HID];
__device__ float g_xn1 [(size_t)NN * HID];
__device__ float g_xb0 [(size_t)NB * HID];
__device__ float g_xb1 [(size_t)NB * HID];
__device__ float g_outn[(size_t)NN * HID];
__device__ float g_outb[(size_t)NB * HID];
__device__ float g_cnt [5][NN];
__device__ int   g_cnti[5][NN];
__device__ int   g_rowp[5][NN + 1];
__device__ int   g_bsum[5][64];
__device__ int   g_col [MAXE];
__device__ int   g_emode;

// bias scratch
__device__ float g_pbCatN[192];
__device__ float g_pbCatB[128];
__device__ float g_l0blCatN[384];
__device__ float g_l0blCatB[256];
__device__ float g_b1SumN[128];
__device__ float g_b1SumB[128];
__device__ float g_b2SumN[128];
__device__ float g_bnS[128];
// bf16 transposed+split weights [Npad x K], hi/lo
__device__ __nv_bfloat16 g_BtProjN[2][256 * 64];
__device__ __nv_bfloat16 g_BtProjB[2][128 * 64];
__device__ __nv_bfloat16 g_BtL0  [2][5][128 * 128];
__device__ __nv_bfloat16 g_BtL1N [2][128 * 512];
__device__ __nv_bfloat16 g_BtL1B [2][128 * 384];
__device__ __nv_bfloat16 g_BtL2N [2][128 * 512];
__device__ __nv_bfloat16 g_BtM1  [2][128 * 128];
__device__ __nv_bfloat16 g_BtM2  [2][128 * 128];

// ================= edge handling / CSR ======================================
__global__ void detect_mode_k(const int* e) {
    int z = 1;
    for (int i = 1; i < 64; i += 2)
        if (e[i] != 0) z = 0;
    g_emode = z;
}
__device__ __forceinline__ int edge_at(const int* e, long long i) {
    if (g_emode) return (int)((const long long*)e)[i];
    return e[i];
}
__global__ void counti5_k(const int* e0, const int* e1, const int* e2,
                          const int* e3, const int* e4,
                          int E0, int E1, int E2, int E3, int E4) {
    int r = blockIdx.y;
    const int* e; int E;
    switch (r) {
        case 0: e = e0; E = E0; break;
        case 1: e = e1; E = E1; break;
        case 2: e = e2; E = E2; break;
        case 3: e = e3; E = E3; break;
        default: e = e4; E = E4; break;
    }
    int i = blockIdx.x * 256 + threadIdx.x;
    if (i >= E) return;
    atomicAdd(&g_cnti[r][edge_at(e, (long long)E + i)], 1);
}
__global__ void scan1_k() {
    int r = blockIdx.y;
    int n = (r == 2 || r == 4) ? NB : NN;
    int t = threadIdx.x;
    int base = blockIdx.x * 2048 + t * 8;
    int vals[8];
#pragma unroll
    for (int j = 0; j < 8; j++) {
        int idx = base + j;
        vals[j] = (idx < n) ? g_cnti[r][idx] : 0;
        if (idx < n) g_cnt[r][idx] = 1.0f / (float)max(vals[j], 1);
    }
    int tot = 0;
#pragma unroll
    for (int j = 0; j < 8; j++) tot += vals[j];
    int lane = t & 31, wid = t >> 5;
    int x = tot;
#pragma unroll
    for (int o = 1; o < 32; o <<= 1) {
        int y = __shfl_up_sync(0xffffffffu, x, o);
        if (lane >= o) x += y;
    }
    __shared__ int wsum[8];
    if (lane == 31) wsum[wid] = x;
    __syncthreads();
    if (t == 0) {
        int run = 0;
#pragma unroll
        for (int i = 0; i < 8; i++) { int v = wsum[i]; wsum[i] = run; run += v; }
        g_bsum[r][blockIdx.x] = run;
    }
    __syncthreads();
    int run = (x - tot) + wsum[wid];
#pragma unroll
    for (int j = 0; j < 8; j++) {
        int idx = base + j;
        if (idx < n) g_rowp[r][idx] = run;
        run += vals[j];
    }
}
__global__ void scan2_k() {
    int r = threadIdx.x;
    if (r >= 5) return;
    int n = (r == 2 || r == 4) ? NB : NN;
    int run = 0;
    for (int i = 0; i < NBX; i++) { int v = g_bsum[r][i]; g_bsum[r][i] = run; run += v; }
    g_rowp[r][n] = run;
}
__global__ void scan3_k() {
    int r = blockIdx.y;
    int n = (r == 2 || r == 4) ? NB : NN;
    int add = g_bsum[r][blockIdx.x];
    int base = blockIdx.x * 2048 + threadIdx.x * 8;
#pragma unroll
    for (int j = 0; j < 8; j++) {
        int idx = base + j;
        if (idx < n) {
            int v = g_rowp[r][idx] + add;
            g_rowp[r][idx] = v;
            g_cnti[r][idx] = v;
        }
    }
}
__global__ void fill5_k(const int* e0, const int* e1, const int* e2,
                        const int* e3, const int* e4,
                        int E0, int E1, int E2, int E3, int E4,
                        int b0, int b1, int b2, int b3, int b4) {
    int r = blockIdx.y;
    const int* e; int E; int eb;
    switch (r) {
        case 0: e = e0; E = E0; eb = b0; break;
        case 1: e = e1; E = E1; eb = b1; break;
        case 2: e = e2; E = E2; eb = b2; break;
        case 3: e = e3; E = E3; eb = b3; break;
        default: e = e4; E = E4; eb = b4; break;
    }
    int i = blockIdx.x * 256 + threadIdx.x;
    if (i >= E) return;
    int s = edge_at(e, i);
    int d = edge_at(e, (long long)E + i);
    int pos = atomicAdd(&g_cnti[r][d], 1);
    g_col[eb + pos] = s;
}

// ---- merged CSR seg-mean aggregation (job table, warp per dst row) ---------
struct Agg5 {
    const float* xf[5];
    const int* rowp[5];
    const int* col[5];
    const float* invc[5];
    float* agg[5];
    int lds[5], soff[5], ldd[5], doff[5], n[5];
    int boff[6];
    int nslots;
};

template <int V>
__global__ void aggmulti_k(Agg5 J) {
    int b = blockIdx.x;
    int s = 0;
    while (s + 1 < J.nslots && b >= J.boff[s + 1]) s++;
    int row = (b - J.boff[s]) * 8 + (threadIdx.x >> 5);
    if (row >= J.n[s]) return;
    int lane = threadIdx.x & 31;
    const float* xf = J.xf[s];
    const int* col = J.col[s];
    int lds = J.lds[s], soff = J.soff[s];
    int beg = J.rowp[s][row], end = J.rowp[s][row + 1];
    float acc[V];
#pragma unroll
    for (int j = 0; j < V; j++) acc[j] = 0.0f;
    int e = beg;
    for (; e + 3 < end; e += 4) {
        int s0 = __ldg(&col[e]);
        int s1 = __ldg(&col[e + 1]);
        int s2 = __ldg(&col[e + 2]);
        int s3 = __ldg(&col[e + 3]);
        const float* p0 = xf + (size_t)s0 * lds + soff + lane * V;
        const float* p1 = xf + (size_t)s1 * lds + soff + lane * V;
        const float* p2 = xf + (size_t)s2 * lds + soff + lane * V;
        const float* p3 = xf + (size_t)s3 * lds + soff + lane * V;
        if (V == 4) {
            float4 a = *(const float4*)p0;
            float4 b2 = *(const float4*)p1;
            float4 c = *(const float4*)p2;
            float4 d = *(const float4*)p3;
            acc[0] += (a.x + b2.x) + (c.x + d.x);
            acc[1] += (a.y + b2.y) + (c.y + d.y);
            acc[2] += (a.z + b2.z) + (c.z + d.z);
            acc[3] += (a.w + b2.w) + (c.w + d.w);
        } else {
            float2 a = *(const float2*)p0;
            float2 b2 = *(const float2*)p1;
            float2 c = *(const float2*)p2;
            float2 d = *(const float2*)p3;
            acc[0] += (a.x + b2.x) + (c.x + d.x);
            acc[1] += (a.y + b2.y) + (c.y + d.y);
        }
    }
    for (; e < end; e++) {
        int s0 = __ldg(&col[e]);
        const float* p0 = xf + (size_t)s0 * lds + soff + lane * V;
        if (V == 4) {
            float4 a = *(const float4*)p0;
            acc[0] += a.x; acc[1] += a.y; acc[2] += a.z; acc[3] += a.w;
        } else {
            float2 a = *(const float2*)p0;
            acc[0] += a.x; acc[1] += a.y;
        }
    }
    float inv = J.invc[s][row];
    float* q = J.agg[s] + (size_t)row * J.ldd[s] + J.doff[s] + lane * V;
    if (V == 4) {
        *(float4*)q = make_float4(acc[0] * inv, acc[1] * inv, acc[2] * inv, acc[3] * inv);
    } else {
        *(float2*)q = make_float2(acc[0] * inv, acc[1] * inv);
    }
}

// ================= wmma bf16 split GEMM (pipelined, z-slotted) ==============
template <int EPI>
__global__ __launch_bounds__(256) void tgemm_k(
    const float* __restrict__ A1, int lda1, int K1,
    const float* __restrict__ A2, int lda2, int K2,
    const __nv_bfloat16* __restrict__ Bhi, const __nv_bfloat16* __restrict__ Blo,
    int ldK, const float* __restrict__ bias,
    float* __restrict__ C, int ldc, int coff,
    int M, int Nfull, float alpha,
    const float* __restrict__ bnS, const float* __restrict__ bnB,
    int bStrideZ, int a2StrideZ, int coffStrideZ, int biasStrideZ)
{
    __shared__ __align__(16) __nv_bfloat16 Abuf[2][2][128][40];

    int zslot = blockIdx.z;
    Bhi += (size_t)zslot * bStrideZ;
    Blo += (size_t)zslot * bStrideZ;
    if (A2) A2 += (size_t)zslot * a2StrideZ;
    bias += (size_t)zslot * biasStrideZ;
    coff += zslot * coffStrideZ;

    int tid = threadIdx.x;
    int wid = tid >> 5, lane = tid & 31;
    int wm = wid >> 2, wn = wid & 3;
    int m0 = blockIdx.x * 128, n0 = blockIdx.y * 128;
    int mw = m0 + wm * 64;
    int nw = n0 + wn * 32;
    bool active = (nw < Nfull);
    int K = K1 + K2;
    int nkt = K >> 5;

    wmma::fragment<wmma::accumulator, 16, 16, 16, float> acc[4][2];
#pragma unroll
    for (int i = 0; i < 4; i++)
#pragma unroll
        for (int j = 0; j < 2; j++) wmma::fill_fragment(acc[i][j], 0.0f);

    int row = tid >> 1, half = tid & 1;
    int m = m0 + row;
    bool mok = (m < M);

    float4 v[4];
    {
        const float* Ap; int ld, kl;
        if (0 < K1) { Ap = A1; ld = lda1; kl = 0; }
        else        { Ap = A2; ld = lda2; kl = -K1; }
        const float* src = Ap + (size_t)m * ld + kl + half * 16;
#pragma unroll
        for (int i = 0; i < 4; i++)
            v[i] = mok ? *(const float4*)(src + i * 4) : make_float4(0.f, 0.f, 0.f, 0.f);
    }

    int buf = 0;
    for (int kt = 0; kt < nkt; kt++) {
#pragma unroll
        for (int i = 0; i < 4; i++) {
            int col = half * 16 + i * 4;
            float4 x = v[i];
            __nv_bfloat16 hx = __float2bfloat16_rn(x.x);
            __nv_bfloat16 hy = __float2bfloat16_rn(x.y);
            __nv_bfloat16 hz = __float2bfloat16_rn(x.z);
            __nv_bfloat16 hw = __float2bfloat16_rn(x.w);
            Abuf[buf][0][row][col + 0] = hx;
            Abuf[buf][0][row][col + 1] = hy;
            Abuf[buf][0][row][col + 2] = hz;
            Abuf[buf][0][row][col + 3] = hw;
            Abuf[buf][1][row][col + 0] = __float2bfloat16_rn(x.x - __bfloat162float(hx));
            Abuf[buf][1][row][col + 1] = __float2bfloat16_rn(x.y - __bfloat162float(hy));
            Abuf[buf][1][row][col + 2] = __float2bfloat16_rn(x.z - __bfloat162float(hz));
            Abuf[buf][1][row][col + 3] = __float2bfloat16_rn(x.w - __bfloat162float(hw));
        }
        __syncthreads();
        if (kt + 1 < nkt) {
            int k0 = (kt + 1) << 5;
            const float* Ap; int ld, kl;
            if (k0 < K1) { Ap = A1; ld = lda1; kl = k0; }
            else         { Ap = A2; ld = lda2; kl = k0 - K1; }
            const float* src = Ap + (size_t)m * ld + kl + half * 16;
#pragma unroll
            for (int i = 0; i < 4; i++)
                v[i] = mok ? *(const float4*)(src + i * 4) : make_float4(0.f, 0.f, 0.f, 0.f);
        }
        if (active) {
            int k0g = kt << 5;
#pragma unroll
            for (int kk = 0; kk < 32; kk += 16) {
                wmma::fragment<wmma::matrix_b, 16, 16, 16, __nv_bfloat16, wmma::col_major> bh[2], bl2[2];
#pragma unroll
                for (int j = 0; j < 2; j++) {
                    const __nv_bfloat16* bp = Bhi + (size_t)(nw + j * 16) * ldK + (k0g + kk);
                    const __nv_bfloat16* lp = Blo + (size_t)(nw + j * 16) * ldK + (k0g + kk);
                    wmma::load_matrix_sync(bh[j],  bp, (unsigned)ldK);
                    wmma::load_matrix_sync(bl2[j], lp, (unsigned)ldK);
                }
#pragma unroll
                for (int i = 0; i < 4; i++) {
                    wmma::fragment<wmma::matrix_a, 16, 16, 16, __nv_bfloat16, wmma::row_major> ah, al;
                    wmma::load_matrix_sync(ah, &Abuf[buf][0][wm * 64 + i * 16][0] + kk, 40u);
                    wmma::load_matrix_sync(al, &Abuf[buf][1][wm * 64 + i * 16][0] + kk, 40u);
#pragma unroll
                    for (int j = 0; j < 2; j++) {
                        wmma::mma_sync(acc[i][j], ah, bh[j],  acc[i][j]);
                        wmma::mma_sync(acc[i][j], ah, bl2[j], acc[i][j]);
                        wmma::mma_sync(acc[i][j], al, bh[j],  acc[i][j]);
                    }
                }
            }
        }
        buf ^= 1;
    }
    __syncthreads();

    if (active) {
        float* myp = reinterpret_cast<float*>(&Abuf[0][0][0][0]) + wid * 320;
        int base = lane * 8;
        int pr = base >> 4, pc = base & 15;
#pragma unroll
        for (int i = 0; i < 4; i++) {
#pragma unroll
            for (int j = 0; j < 2; j++) {
                wmma::store_matrix_sync(myp, acc[i][j], 20u, wmma::mem_row_major);
                __syncwarp();
                int mb = mw + i * 16, nb = nw + j * 16;
                if (mb + pr < M) {
                    float out[8];
#pragma unroll
                    for (int t = 0; t < 8; t++) {
                        int n = nb + pc + t;
                        float val = myp[pr * 20 + pc + t] * alpha + bias[n];
                        if (EPI >= 1) val = fmaxf(val, 0.0f);
                        if (EPI == 2) val = val * bnS[n] + bnB[n];
                        out[t] = val;
                    }
                    float* dst = C + (size_t)(mb + pr) * ldc + coff + nb + pc;
                    *(float4*)dst = *(float4*)&out[0];
                    *(float4*)(dst + 4) = *(float4*)&out[4];
                }
                __syncwarp();
            }
        }
    }
}

// ================= elementwise kernels =======================================
template <int R>
__global__ void l0post_k(const float* __restrict__ O, int ldo,
                         const float* __restrict__ gg, const float* __restrict__ bb,
                         float* __restrict__ xout, int M) {
    int row = blockIdx.x * 8 + (threadIdx.x >> 5);
    if (row >= M) return;
    int lane = threadIdx.x & 31;
    float acc[4] = {0.f, 0.f, 0.f, 0.f};
#pragma unroll
    for (int rb = 0; rb < R; rb++) {
        const float* p = O + (size_t)row * ldo + rb * 128;
        float v[4]; float ss = 0.f;
#pragma unroll
        for (int j = 0; j < 4; j++) { v[j] = p[lane + 32 * j]; ss += v[j] * v[j]; }
#pragma unroll
        for (int s = 16; s; s >>= 1) ss += __shfl_xor_sync(0xffffffffu, ss, s);
        float inv = 1.0f / fmaxf(sqrtf(ss), 1e-12f);
#pragma unroll
        for (int j = 0; j < 4; j++) acc[j] += v[j] * inv;
    }
    const float invR = 1.0f / R;
    float s = 0.f;
#pragma unroll
    for (int j = 0; j < 4; j++) { acc[j] = fmaxf(acc[j] * invR, 0.f); s += acc[j]; }
#pragma unroll
    for (int o = 16; o; o >>= 1) s += __shfl_xor_sync(0xffffffffu, s, o);
    float m = s * (1.0f / 128.0f);
    float ss = 0.f;
#pragma unroll
    for (int j = 0; j < 4; j++) { float d = acc[j] - m; ss += d * d; }
#pragma unroll
    for (int o = 16; o; o >>= 1) ss += __shfl_xor_sync(0xffffffffu, ss, o);
    float inv = rsqrtf(ss * (1.0f / 128.0f) + 1e-5f);
    float* q = xout + (size_t)row * 128;
#pragma unroll
    for (int j = 0; j < 4; j++) {
        int c = lane + 32 * j;
        q[c] = (acc[j] - m) * inv * gg[c] + bb[c];
    }
}
__global__ void relu_ln_k(const float* __restrict__ acc, float invr,
                          const float* __restrict__ gg, const float* __restrict__ bb,
                          float* __restrict__ xout, int M) {
    int row = blockIdx.x * 8 + (threadIdx.x >> 5);
    if (row >= M) return;
    int lane = threadIdx.x & 31;
    const float* p = acc + (size_t)row * 128;
    float v[4]; float s = 0.f;
#pragma unroll
    for (int j = 0; j < 4; j++) { v[j] = fmaxf(p[lane + 32 * j] * invr, 0.f); s += v[j]; }
#pragma unroll
    for (int o = 16; o; o >>= 1) s += __shfl_xor_sync(0xffffffffu, s, o);
    float m = s * (1.0f / 128.0f);
    float ss = 0.f;
#pragma unroll
    for (int j = 0; j < 4; j++) { float d = v[j] - m; ss += d * d; }
#pragma unroll
    for (int o = 16; o; o >>= 1) ss += __shfl_xor_sync(0xffffffffu, ss, o);
    float inv = rsqrtf(ss * (1.0f / 128.0f) + 1e-5f);
    float* q = xout + (size_t)row * 128;
#pragma unroll
    for (int j = 0; j < 4; j++) {
        int c = lane + 32 * j;
        q[c] = (v[j] - m) * inv * gg[c] + bb[c];
    }
}

// ================= single fused weight-prep kernel ===========================
__device__ __forceinline__ void bsplit(float x, __nv_bfloat16& h, __nv_bfloat16& l) {
    h = __float2bfloat16_rn(x);
    l = __float2bfloat16_rn(x - __bfloat162float(h));
}
__device__ __forceinline__ void lsplit_body(__nv_bfloat16* hi, __nv_bfloat16* lo,
                                            const float* WlL, const float* WrL,
                                            int r0, int r1, int r2, int nrel, int idx) {
    int K = nrel * 128 + 128;
    int n = idx / K, k = idx - n * K;
    float x;
    if (k < nrel * 128) {
        int j = k >> 7, kk = k & 127;
        int r = (j == 0) ? r0 : (j == 1) ? r1 : r2;
        x = WlL[(size_t)r * 16384 + kk * 128 + n];
    } else {
        int kk = k - nrel * 128;
        x = WrL[(size_t)r0 * 16384 + kk * 128 + n] + WrL[(size_t)r1 * 16384 + kk * 128 + n];
        if (nrel == 3) x += WrL[(size_t)r2 * 16384 + kk * 128 + n];
    }
    __nv_bfloat16 h, l;
    bsplit(x, h, l);
    hi[idx] = h;
    lo[idx] = l;
}
#define PREP_TOTAL 305152
__global__ void prep_k(const float* __restrict__ proj_W, const float* __restrict__ proj_b,
                       const float* __restrict__ l0_Wl, const float* __restrict__ l0_bl,
                       const float* __restrict__ l0_Wr,
                       const float* __restrict__ Wl, const float* __restrict__ bl,
                       const float* __restrict__ Wr,
                       const float* __restrict__ mlp_W1, const float* __restrict__ mlp_W2,
                       const float* __restrict__ bn_g) {
    int idx = blockIdx.x * 256 + threadIdx.x;
    __nv_bfloat16 h, l;
    if (idx < 12288) {                                 // projCatN split (rels 0,1,2)
        int j = idx >> 12, rem = idx & 4095;
        int k = rem >> 6, c = rem & 63;
        float x = proj_W[(size_t)j * 4096 + k * 64 + c];
        int n = j * 64 + c;
        bsplit(x, h, l);
        g_BtProjN[0][n * 64 + k] = h; g_BtProjN[1][n * 64 + k] = l;
        return;
    }
    idx -= 12288;
    if (idx < 8192) {                                  // projCatB split (rels 3,4)
        int j = idx >> 12, rem = idx & 4095;
        int k = rem >> 6, c = rem & 63;
        int r = (j == 0) ? 3 : 4;
        float x = proj_W[(size_t)r * 4096 + k * 64 + c];
        int n = j * 64 + c;
        bsplit(x, h, l);
        g_BtProjB[0][n * 64 + k] = h; g_BtProjB[1][n * 64 + k] = l;
        return;
    }
    idx -= 8192;
    if (idx < 81920) {                                 // layer0 [Wr | Wl] per slot
        int s = idx >> 14, rem = idx & 16383;
        int n = rem >> 7, k = rem & 127;
        const int rels[5] = {0, 1, 3, 2, 4};
        int r = rels[s];
        float x = (k < 64) ? l0_Wr[(size_t)r * 8192 + k * 128 + n]
                           : l0_Wl[(size_t)r * 8192 + (k - 64) * 128 + n];
        bsplit(x, h, l);
        g_BtL0[0][s][rem] = h; g_BtL0[1][s][rem] = l;
        return;
    }
    idx -= 81920;
    if (idx < 65536) { lsplit_body(g_BtL1N[0], g_BtL1N[1], Wl, Wr, 0, 1, 3, 3, idx); return; }
    idx -= 65536;
    if (idx < 49152) { lsplit_body(g_BtL1B[0], g_BtL1B[1], Wl, Wr, 2, 4, 0, 2, idx); return; }
    idx -= 49152;
    if (idx < 65536) { lsplit_body(g_BtL2N[0], g_BtL2N[1], Wl + 5 * 16384, Wr + 5 * 16384, 0, 1, 3, 3, idx); return; }
    idx -= 65536;
    if (idx < 16384) {                                 // mlp_W1 transpose split
        int k = idx >> 7, n = idx & 127;
        bsplit(mlp_W1[idx], h, l);
        g_BtM1[0][n * 128 + k] = h; g_BtM1[1][n * 128 + k] = l;
        return;
    }
    idx -= 16384;
    if (idx < 4096) {                                  // mlp_W2 transpose split
        int k = idx / 32, n = idx - (idx / 32) * 32;
        bsplit(mlp_W2[idx], h, l);
        g_BtM2[0][n * 128 + k] = h; g_BtM2[1][n * 128 + k] = l;
        return;
    }
    idx -= 4096;
    // bias segment (t in [0, 2048))
    int t = idx;
    if (t < 192) {
        int j = t / 64;
        g_pbCatN[t] = proj_b[(size_t)j * 64 + (t - j * 64)];      // rels 0,1,2
    } else if (t < 320) {
        int local = t - 192; int j = local / 64;
        int r = (j == 0) ? 3 : 4;
        g_pbCatB[local] = proj_b[(size_t)r * 64 + (local - j * 64)];
    } else if (t < 704) {
        int local = t - 320; int j = local / 128;
        int r = (j == 0) ? 0 : (j == 1) ? 1 : 3;
        g_l0blCatN[local] = l0_bl[(size_t)r * 128 + (local - j * 128)];
    } else if (t < 960) {
        int local = t - 704; int j = local / 128;
        int r = (j == 0) ? 2 : 4;
        g_l0blCatB[local] = l0_bl[(size_t)r * 128 + (local - j * 128)];
    } else if (t < 1088) {
        int i = t - 960;
        g_b1SumN[i] = bl[i] + bl[128 + i] + bl[3 * 128 + i];
    } else if (t < 1216) {
        int i = t - 1088;
        g_b1SumB[i] = bl[2 * 128 + i] + bl[4 * 128 + i];
    } else if (t < 1344) {
        int i = t - 1216;
        g_b2SumN[i] = bl[(5 + 0) * 128 + i] + bl[(5 + 1) * 128 + i] + bl[(5 + 3) * 128 + i];
    } else if (t < 1472) {
        int i = t - 1344;
        g_bnS[i] = bn_g[i] * rsqrtf(1.0f + 1e-5f);
    }
}

// ================= host dispatch =============================================
static void tgemm(int epi, const float* A1, int lda1, int K1,
                  const float* A2, int lda2, int K2,
                  const __nv_bfloat16* Bh, const __nv_bfloat16* Bl, int ldK,
                  const float* bias, float* C, int ldc, int coff,
                  int M, int Nfull, float alpha,
                  const float* bnS, const float* bnB,
                  int gz = 1, int bStrideZ = 0, int a2StrideZ = 0,
                  int coffStrideZ = 0, int biasStrideZ = 0) {
    dim3 g((M + 127) / 128, (Nfull + 127) / 128, gz);
    if (epi == 0)
        tgemm_k<0><<<g, 256>>>(A1, lda1, K1, A2, lda2, K2, Bh, Bl, ldK, bias, C, ldc, coff, M, Nfull, alpha, bnS, bnB, bStrideZ, a2StrideZ, coffStrideZ, biasStrideZ);
    else if (epi == 1)
        tgemm_k<1><<<g, 256>>>(A1, lda1, K1, A2, lda2, K2, Bh, Bl, ldK, bias, C, ldc, coff, M, Nfull, alpha, bnS, bnB, bStrideZ, a2StrideZ, coffStrideZ, biasStrideZ);
    else
        tgemm_k<2><<<g, 256>>>(A1, lda1, K1, A2, lda2, K2, Bh, Bl, ldK, bias, C, ldc, coff, M, Nfull, alpha, bnS, bnB, bStrideZ, a2StrideZ, coffStrideZ, biasStrideZ);
}

extern "C" void kernel_launch(void* const* d_in, const int* in_sizes, int n_in,
                              void* d_out, int out_size) {
    const float* x_note = (const float*)d_in[0];
    const float* x_beat = (const float*)d_in[1];
    const int* e[5] = {(const int*)d_in[2], (const int*)d_in[3], (const int*)d_in[4],
                       (const int*)d_in[5], (const int*)d_in[6]};
    int E[5];
    for (int r = 0; r < 5; r++) E[r] = in_sizes[2 + r] / 2;
    const float* proj_W = (const float*)d_in[7];
    const float* proj_b = (const float*)d_in[8];
    const float* l0_Wl  = (const float*)d_in[9];
    const float* l0_bl  = (const float*)d_in[10];
    const float* l0_Wr  = (const float*)d_in[11];
    const float* Wl     = (const float*)d_in[12];
    const float* bl     = (const float*)d_in[13];
    const float* Wr     = (const float*)d_in[14];
    const float* ln_g   = (const float*)d_in[15];
    const float* ln_b   = (const float*)d_in[16];
    const float* mlp_W1 = (const float*)d_in[17];
    const float* mlp_b1 = (const float*)d_in[18];
    const float* bn_g   = (const float*)d_in[19];
    const float* bn_b   = (const float*)d_in[20];
    const float* mlp_W2 = (const float*)d_in[21];
    const float* mlp_b2 = (const float*)d_in[22];

    float *pn, *pb, *aggn, *aggb, *On, *Ob, *xn0, *xn1, *xb0, *xb1, *outn, *outb, *cntf;
    int *cnti, *rowp, *colx;
    cudaGetSymbolAddress((void**)&pn, g_pn);       cudaGetSymbolAddress((void**)&pb, g_pb);
    cudaGetSymbolAddress((void**)&aggn, g_aggn);   cudaGetSymbolAddress((void**)&aggb, g_aggb);
    cudaGetSymbolAddress((void**)&On, g_On);       cudaGetSymbolAddress((void**)&Ob, g_Ob);
    cudaGetSymbolAddress((void**)&xn0, g_xn0);     cudaGetSymbolAddress((void**)&xn1, g_xn1);
    cudaGetSymbolAddress((void**)&xb0, g_xb0);     cudaGetSymbolAddress((void**)&xb1, g_xb1);
    cudaGetSymbolAddress((void**)&outn, g_outn);   cudaGetSymbolAddress((void**)&outb, g_outb);
    cudaGetSymbolAddress((void**)&cntf, g_cnt);    cudaGetSymbolAddress((void**)&cnti, g_cnti);
    cudaGetSymbolAddress((void**)&rowp, g_rowp);   cudaGetSymbolAddress((void**)&colx, g_col);

    float *pbCatN, *pbCatB, *l0blCatN, *l0blCatB, *b1SumN, *b1SumB, *b2SumN, *bnS;
    cudaGetSymbolAddress((void**)&pbCatN, g_pbCatN);     cudaGetSymbolAddress((void**)&pbCatB, g_pbCatB);
    cudaGetSymbolAddress((void**)&l0blCatN, g_l0blCatN); cudaGetSymbolAddress((void**)&l0blCatB, g_l0blCatB);
    cudaGetSymbolAddress((void**)&b1SumN, g_b1SumN);     cudaGetSymbolAddress((void**)&b1SumB, g_b1SumB);
    cudaGetSymbolAddress((void**)&b2SumN, g_b2SumN);     cudaGetSymbolAddress((void**)&bnS, g_bnS);

    __nv_bfloat16 *BtProjN[2], *BtProjB[2], *BtL0[2], *BtL1N[2], *BtL1B[2], *BtL2N[2], *BtM1[2], *BtM2[2];
    {
        __nv_bfloat16* p;
        cudaGetSymbolAddress((void**)&p, g_BtProjN); BtProjN[0] = p; BtProjN[1] = p + 256 * 64;
        cudaGetSymbolAddress((void**)&p, g_BtProjB); BtProjB[0] = p; BtProjB[1] = p + 128 * 64;
        cudaGetSymbolAddress((void**)&p, g_BtL0);    BtL0[0] = p;    BtL0[1] = p + 5 * 128 * 128;
        cudaGetSymbolAddress((void**)&p, g_BtL1N);   BtL1N[0] = p;   BtL1N[1] = p + 128 * 512;
        cudaGetSymbolAddress((void**)&p, g_BtL1B);   BtL1B[0] = p;   BtL1B[1] = p + 128 * 384;
        cudaGetSymbolAddress((void**)&p, g_BtL2N);   BtL2N[0] = p;   BtL2N[1] = p + 128 * 512;
        cudaGetSymbolAddress((void**)&p, g_BtM1);    BtM1[0] = p;    BtM1[1] = p + 128 * 128;
        cudaGetSymbolAddress((void**)&p, g_BtM2);    BtM2[0] = p;    BtM2[1] = p + 128 * 128;
    }

    int ebase[5];
    { int acc = 0; for (int r = 0; r < 5; r++) { ebase[r] = acc; acc += E[r]; } }
    int maxE = 0;
    for (int r = 0; r < 5; r++) maxE = (E[r] > maxE) ? E[r] : maxE;

    detect_mode_k<<<1, 1>>>(e[0]);

    // ---- CSR build ----
    cudaMemsetAsync(cnti, 0, 5 * NN * sizeof(int));
    counti5_k<<<dim3((maxE + 255) / 256, 5), 256>>>(e[0], e[1], e[2], e[3], e[4],
                                                    E[0], E[1], E[2], E[3], E[4]);
    scan1_k<<<dim3(NBX, 5), 256>>>();
    scan2_k<<<1, 32>>>();
    scan3_k<<<dim3(NBX, 5), 256>>>();
    fill5_k<<<dim3((maxE + 255) / 256, 5), 256>>>(e[0], e[1], e[2], e[3], e[4],
                                                  E[0], E[1], E[2], E[3], E[4],
                                                  ebase[0], ebase[1], ebase[2], ebase[3], ebase[4]);
    const int* rp[5]; const int* cx[5]; const float* ic[5];
    for (int r = 0; r < 5; r++) {
        rp[r] = rowp + r * (NN + 1);
        cx[r] = colx + ebase[r];
        ic[r] = cntf + r * NN;
    }

    // ---- fused weight prep (single launch) ----
    prep_k<<<(PREP_TOTAL + 255) / 256, 256>>>(proj_W, proj_b, l0_Wl, l0_bl, l0_Wr,
                                              Wl, bl, Wr, mlp_W1, mlp_W2, bn_g);

    const int NBLK_N = (NN + 7) / 8;      // 12500
    const int NBLK_B = (NB + 7) / 8;      // 2500

    // helper to fill agg job tables
    auto mkjob = [&](Agg5& J, int s, const float* xf, int lds, int soff, int rel,
                     float* agg, int ldd, int doff, int n) {
        J.xf[s] = xf; J.lds[s] = lds; J.soff[s] = soff;
        J.rowp[s] = rp[rel]; J.col[s] = cx[rel]; J.invc[s] = ic[rel];
        J.agg[s] = agg; J.ldd[s] = ldd; J.doff[s] = doff; J.n[s] = n;
    };

    // ==================== layer 0 ====================
    tgemm(1, x_note, 64, 64, nullptr, 0, 0, BtProjN[0], BtProjN[1], 64, pbCatN,
          pn, 192, 0, NN, 192, 1.f, nullptr, nullptr);
    tgemm(1, x_beat, 64, 64, nullptr, 0, 0, BtProjB[0], BtProjB[1], 64, pbCatB,
          pb, 128, 0, NB, 128, 1.f, nullptr, nullptr);
    {
        Agg5 J; J.nslots = 5;
        mkjob(J, 0, pn, 192, 0,   0, aggn, 192, 0,   NN);
        mkjob(J, 1, pn, 192, 64,  1, aggn, 192, 64,  NN);
        mkjob(J, 2, pb, 128, 0,   3, aggn, 192, 128, NN);
        mkjob(J, 3, pn, 192, 128, 2, aggb, 128, 0,   NB);
        mkjob(J, 4, pb, 128, 64,  4, aggb, 128, 64,  NB);
        J.boff[0] = 0; J.boff[1] = NBLK_N; J.boff[2] = 2 * NBLK_N; J.boff[3] = 3 * NBLK_N;
        J.boff[4] = 3 * NBLK_N + NBLK_B; J.boff[5] = 3 * NBLK_N + 2 * NBLK_B;
        aggmulti_k<2><<<J.boff[5], 256>>>(J);
    }
    // slotted per-relation o GEMMs: note (3 slots), beat (2 slots)
    tgemm(0, x_note, 64, 64, aggn, 192, 64, BtL0[0], BtL0[1], 128, l0blCatN,
          On, 384, 0, NN, 128, 1.f, nullptr, nullptr,
          3, 16384, 64, 128, 128);
    tgemm(0, x_beat, 64, 64, aggb, 128, 64, BtL0[0] + 3 * 16384, BtL0[1] + 3 * 16384, 128, l0blCatB,
          Ob, 256, 0, NB, 128, 1.f, nullptr, nullptr,
          2, 16384, 64, 128, 128);
    l0post_k<3><<<NBLK_N, 256>>>(On, 384, ln_g, ln_b, xn0, NN);
    l0post_k<2><<<NBLK_B, 256>>>(Ob, 256, ln_g, ln_b, xb0, NB);

    // ==================== layer 1 ====================
    {
        Agg5 J; J.nslots = 5;
        mkjob(J, 0, xn0, 128, 0, 0, aggn, 384, 0,   NN);
        mkjob(J, 1, xn0, 128, 0, 1, aggn, 384, 128, NN);
        mkjob(J, 2, xb0, 128, 0, 3, aggn, 384, 256, NN);
        mkjob(J, 3, xn0, 128, 0, 2, aggb, 256, 0,   NB);
        mkjob(J, 4, xb0, 128, 0, 4, aggb, 256, 128, NB);
        J.boff[0] = 0; J.boff[1] = NBLK_N; J.boff[2] = 2 * NBLK_N; J.boff[3] = 3 * NBLK_N;
        J.boff[4] = 3 * NBLK_N + NBLK_B; J.boff[5] = 3 * NBLK_N + 2 * NBLK_B;
        aggmulti_k<4><<<J.boff[5], 256>>>(J);
    }
    tgemm(0, aggn, 384, 384, xn0, 128, 128, BtL1N[0], BtL1N[1], 512, b1SumN,
          outn, 128, 0, NN, 128, 1.f, nullptr, nullptr);
    tgemm(0, aggb, 256, 256, xb0, 128, 128, BtL1B[0], BtL1B[1], 384, b1SumB,
          outb, 128, 0, NB, 128, 1.f, nullptr, nullptr);
    relu_ln_k<<<NBLK_N, 256>>>(outn, 1.f / 3.f, ln_g + 128, ln_b + 128, xn1, NN);
    relu_ln_k<<<NBLK_B, 256>>>(outb, 1.f / 2.f, ln_g + 128, ln_b + 128, xb1, NB);

    // ==================== layer 2 (note dst only) ====================
    {
        Agg5 J; J.nslots = 3;
        mkjob(J, 0, xn1, 128, 0, 0, aggn, 384, 0,   NN);
        mkjob(J, 1, xn1, 128, 0, 1, aggn, 384, 128, NN);
        mkjob(J, 2, xb1, 128, 0, 3, aggn, 384, 256, NN);
        J.boff[0] = 0; J.boff[1] = NBLK_N; J.boff[2] = 2 * NBLK_N; J.boff[3] = 3 * NBLK_N;
        J.boff[4] = 3 * NBLK_N; J.boff[5] = 3 * NBLK_N;
        aggmulti_k<4><<<J.boff[3], 256>>>(J);
    }
    tgemm(0, aggn, 384, 384, xn1, 128, 128, BtL2N[0], BtL2N[1], 512, b2SumN,
          outn, 128, 0, NN, 128, 1.f, nullptr, nullptr);

    // ==================== final MLP ====================
    tgemm(2, outn, 128, 128, nullptr, 0, 0, BtM1[0], BtM1[1], 128, mlp_b1,
          On, 128, 0, NN, 128, 1.f / 3.f, bnS, bn_b);
    tgemm(0, On, 128, 128, nullptr, 0, 0, BtM2[0], BtM2[1], 128, mlp_b2,
          (float*)d_out, 32, 0, NN, 32, 1.f, nullptr, nullptr);
}

// round 8
// speedup vs baseline: 4.4620x; 1.1884x over previous
#include <cuda_runtime.h>
#include <cuda_bf16.h>
#include <mma.h>
#include <cstdint>

using namespace nvcuda;

#define NN 100000
#define NB 20000
#define INC 64
#define HID 128
#define NBX 49
#define MAXE 3000000

// ================= scratch (device globals; no runtime allocation) ==========
__device__ float g_pn  [(size_t)NN * 192];
__device__ float g_pb  [(size_t)NB * 128];
__device__ float g_aggn[(size_t)NN * 384];
__device__ float g_aggb[(size_t)NB * 256];
__device__ float g_On  [(size_t)NN * 384];
__device__ float g_Ob  [(size_t)NB * 256];
__device__ float g_xn0 [(size_t)NN * HID];
__device__ float g_xn1 [(size_t)NN * HID];
__device__ float g_xb0 [(size_t)NB * HID];
__device__ float g_xb1 [(size_t)NB * HID];
__device__ float g_outn[(size_t)NN * HID];
__device__ float g_outb[(size_t)NB * HID];
__device__ float g_cnt [5][NN];
__device__ int   g_cnti[5][NN];
__device__ int   g_rowp[5][NN + 1];
__device__ int   g_bsum[5][64];
__device__ int   g_col [MAXE];
__device__ int   g_emode;

// bias scratch
__device__ float g_pbCatN[192];
__device__ float g_pbCatB[128];
__device__ float g_l0blCatN[384];
__device__ float g_l0blCatB[256];
__device__ float g_b1SumN[128];
__device__ float g_b1SumB[128];
__device__ float g_b2SumN[128];
__device__ float g_bnS[128];
// bf16 transposed+split weights [Npad x K], hi/lo
__device__ __nv_bfloat16 g_BtProjN[2][256 * 64];
__device__ __nv_bfloat16 g_BtProjB[2][128 * 64];
__device__ __nv_bfloat16 g_BtL0  [2][5][128 * 128];
__device__ __nv_bfloat16 g_BtL1N [2][128 * 512];
__device__ __nv_bfloat16 g_BtL1B [2][128 * 384];
__device__ __nv_bfloat16 g_BtL2N [2][128 * 512];
__device__ __nv_bfloat16 g_BtM1  [2][128 * 128];
__device__ __nv_bfloat16 g_BtM2  [2][128 * 128];

// ================= edge handling / CSR ======================================
__global__ void detect_mode_k(const int* e) {
    int z = 1;
    for (int i = 1; i < 64; i += 2)
        if (e[i] != 0) z = 0;
    g_emode = z;
}
__device__ __forceinline__ int edge_at(const int* e, long long i) {
    if (g_emode) return (int)((const long long*)e)[i];
    return e[i];
}
__global__ void counti5_k(const int* e0, const int* e1, const int* e2,
                          const int* e3, const int* e4,
                          int E0, int E1, int E2, int E3, int E4) {
    int r = blockIdx.y;
    const int* e; int E;
    switch (r) {
        case 0: e = e0; E = E0; break;
        case 1: e = e1; E = E1; break;
        case 2: e = e2; E = E2; break;
        case 3: e = e3; E = E3; break;
        default: e = e4; E = E4; break;
    }
    int i = blockIdx.x * 256 + threadIdx.x;
    if (i >= E) return;
    atomicAdd(&g_cnti[r][edge_at(e, (long long)E + i)], 1);
}
__global__ void scan1_k() {
    int r = blockIdx.y;
    int n = (r == 2 || r == 4) ? NB : NN;
    int t = threadIdx.x;
    int base = blockIdx.x * 2048 + t * 8;
    int vals[8];
#pragma unroll
    for (int j = 0; j < 8; j++) {
        int idx = base + j;
        vals[j] = (idx < n) ? g_cnti[r][idx] : 0;
        if (idx < n) g_cnt[r][idx] = 1.0f / (float)max(vals[j], 1);
    }
    int tot = 0;
#pragma unroll
    for (int j = 0; j < 8; j++) tot += vals[j];
    int lane = t & 31, wid = t >> 5;
    int x = tot;
#pragma unroll
    for (int o = 1; o < 32; o <<= 1) {
        int y = __shfl_up_sync(0xffffffffu, x, o);
        if (lane >= o) x += y;
    }
    __shared__ int wsum[8];
    if (lane == 31) wsum[wid] = x;
    __syncthreads();
    if (t == 0) {
        int run = 0;
#pragma unroll
        for (int i = 0; i < 8; i++) { int v = wsum[i]; wsum[i] = run; run += v; }
        g_bsum[r][blockIdx.x] = run;
    }
    __syncthreads();
    int run = (x - tot) + wsum[wid];
#pragma unroll
    for (int j = 0; j < 8; j++) {
        int idx = base + j;
        if (idx < n) g_rowp[r][idx] = run;
        run += vals[j];
    }
}
__global__ void scan2_k() {
    int r = threadIdx.x;
    if (r >= 5) return;
    int n = (r == 2 || r == 4) ? NB : NN;
    int run = 0;
    for (int i = 0; i < NBX; i++) { int v = g_bsum[r][i]; g_bsum[r][i] = run; run += v; }
    g_rowp[r][n] = run;
}
__global__ void scan3_k() {
    int r = blockIdx.y;
    int n = (r == 2 || r == 4) ? NB : NN;
    int add = g_bsum[r][blockIdx.x];
    int base = blockIdx.x * 2048 + threadIdx.x * 8;
#pragma unroll
    for (int j = 0; j < 8; j++) {
        int idx = base + j;
        if (idx < n) {
            int v = g_rowp[r][idx] + add;
            g_rowp[r][idx] = v;
            g_cnti[r][idx] = v;
        }
    }
}
__global__ void fill5_k(const int* e0, const int* e1, const int* e2,
                        const int* e3, const int* e4,
                        int E0, int E1, int E2, int E3, int E4,
                        int b0, int b1, int b2, int b3, int b4) {
    int r = blockIdx.y;
    const int* e; int E; int eb;
    switch (r) {
        case 0: e = e0; E = E0; eb = b0; break;
        case 1: e = e1; E = E1; eb = b1; break;
        case 2: e = e2; E = E2; eb = b2; break;
        case 3: e = e3; E = E3; eb = b3; break;
        default: e = e4; E = E4; eb = b4; break;
    }
    int i = blockIdx.x * 256 + threadIdx.x;
    if (i >= E) return;
    int s = edge_at(e, i);
    int d = edge_at(e, (long long)E + i);
    int pos = atomicAdd(&g_cnti[r][d], 1);
    g_col[eb + pos] = s;
}

// ---- merged CSR seg-mean aggregation (job table, warp per dst row) ---------
struct Agg5 {
    const float* xf[5];
    const int* rowp[5];
    const int* col[5];
    const float* invc[5];
    float* agg[5];
    int lds[5], soff[5], ldd[5], doff[5], n[5];
    int boff[6];
    int nslots;
};

template <int V>
__global__ void aggmulti_k(Agg5 J) {
    int b = blockIdx.x;
    int s = 0;
    while (s + 1 < J.nslots && b >= J.boff[s + 1]) s++;
    int row = (b - J.boff[s]) * 8 + (threadIdx.x >> 5);
    if (row >= J.n[s]) return;
    int lane = threadIdx.x & 31;
    const float* xf = J.xf[s];
    const int* col = J.col[s];
    int lds = J.lds[s], soff = J.soff[s];
    int beg = J.rowp[s][row], end = J.rowp[s][row + 1];
    float acc[V];
#pragma unroll
    for (int j = 0; j < V; j++) acc[j] = 0.0f;
    int e = beg;
    for (; e + 7 < end; e += 8) {
        int si[8];
#pragma unroll
        for (int u = 0; u < 8; u++) si[u] = __ldg(&col[e + u]);
        if (V == 4) {
            float4 vv[8];
#pragma unroll
            for (int u = 0; u < 8; u++)
                vv[u] = *(const float4*)(xf + (size_t)si[u] * lds + soff + lane * V);
#pragma unroll
            for (int u = 0; u < 8; u++) {
                acc[0] += vv[u].x; acc[1] += vv[u].y;
                acc[2] += vv[u].z; acc[3] += vv[u].w;
            }
        } else {
            float2 vv[8];
#pragma unroll
            for (int u = 0; u < 8; u++)
                vv[u] = *(const float2*)(xf + (size_t)si[u] * lds + soff + lane * V);
#pragma unroll
            for (int u = 0; u < 8; u++) {
                acc[0] += vv[u].x; acc[1] += vv[u].y;
            }
        }
    }
    for (; e < end; e++) {
        int s0 = __ldg(&col[e]);
        const float* p0 = xf + (size_t)s0 * lds + soff + lane * V;
        if (V == 4) {
            float4 a = *(const float4*)p0;
            acc[0] += a.x; acc[1] += a.y; acc[2] += a.z; acc[3] += a.w;
        } else {
            float2 a = *(const float2*)p0;
            acc[0] += a.x; acc[1] += a.y;
        }
    }
    float inv = J.invc[s][row];
    float* q = J.agg[s] + (size_t)row * J.ldd[s] + J.doff[s] + lane * V;
    if (V == 4) {
        *(float4*)q = make_float4(acc[0] * inv, acc[1] * inv, acc[2] * inv, acc[3] * inv);
    } else {
        *(float2*)q = make_float2(acc[0] * inv, acc[1] * inv);
    }
}

// ================= cp.async helpers =========================================
__device__ __forceinline__ void cp16(uint32_t dst, const void* src) {
    asm volatile("cp.async.ca.shared.global [%0], [%1], 16;" :: "r"(dst), "l"(src));
}
__device__ __forceinline__ void cp_commit() {
    asm volatile("cp.async.commit_group;");
}
__device__ __forceinline__ void cp_wait0() {
    asm volatile("cp.async.wait_group 0;" ::: "memory");
}

// ================= wmma bf16 split GEMM (cp.async B staging) ================
// dyn smem layout: A [2 buf][2 hi/lo][128][40] bf16 = 40960 B
//                  B [2 buf][2 hi/lo][128][40] bf16 = 40960 B  (offset 40960)
#define TG_DSM 81920
template <int EPI>
__global__ __launch_bounds__(256) void tgemm_k(
    const float* __restrict__ A1, int lda1, int K1,
    const float* __restrict__ A2, int lda2, int K2,
    const __nv_bfloat16* __restrict__ Bhi, const __nv_bfloat16* __restrict__ Blo,
    int ldK, const float* __restrict__ bias,
    float* __restrict__ C, int ldc, int coff,
    int M, int Nfull, float alpha,
    const float* __restrict__ bnS, const float* __restrict__ bnB,
    int bStrideZ, int a2StrideZ, int coffStrideZ, int biasStrideZ)
{
    extern __shared__ char dynsmem[];
    __nv_bfloat16* Asm = reinterpret_cast<__nv_bfloat16*>(dynsmem);
    __nv_bfloat16* Bsm = reinterpret_cast<__nv_bfloat16*>(dynsmem + 40960);
    uint32_t Bu32 = (uint32_t)__cvta_generic_to_shared(Bsm);

    int zslot = blockIdx.z;
    Bhi += (size_t)zslot * bStrideZ;
    Blo += (size_t)zslot * bStrideZ;
    if (A2) A2 += (size_t)zslot * a2StrideZ;
    bias += (size_t)zslot * biasStrideZ;
    coff += zslot * coffStrideZ;

    int tid = threadIdx.x;
    int wid = tid >> 5, lane = tid & 31;
    int wm = wid >> 2, wn = wid & 3;
    int m0 = blockIdx.x * 128, n0 = blockIdx.y * 128;
    int mw = m0 + wm * 64;
    int nw = n0 + wn * 32;
    int nl = wn * 32;                  // local B row base in smem
    bool active = (nw < Nfull);
    int K = K1 + K2;
    int nkt = K >> 5;

    wmma::fragment<wmma::accumulator, 16, 16, 16, float> acc[4][2];
#pragma unroll
    for (int i = 0; i < 4; i++)
#pragma unroll
        for (int j = 0; j < 2; j++) wmma::fill_fragment(acc[i][j], 0.0f);

    int row = tid >> 1, half = tid & 1;
    int m = m0 + row;
    bool mok = (m < M);
    // B staging thread mapping (same split)
    int brow = row, bhalf = half;

    // ---- prologue: A tile 0 -> regs; B tile 0 -> cp.async ----
    float4 v[4];
    {
        const float* Ap; int ld, kl;
        if (0 < K1) { Ap = A1; ld = lda1; kl = 0; }
        else        { Ap = A2; ld = lda2; kl = -K1; }
        const float* src = Ap + (size_t)m * ld + kl + half * 16;
#pragma unroll
        for (int i = 0; i < 4; i++)
            v[i] = mok ? *(const float4*)(src + i * 4) : make_float4(0.f, 0.f, 0.f, 0.f);
    }
    {
        const __nv_bfloat16* sH = Bhi + (size_t)(n0 + brow) * ldK + bhalf * 16;
        const __nv_bfloat16* sL = Blo + (size_t)(n0 + brow) * ldK + bhalf * 16;
        uint32_t dH = Bu32 + (uint32_t)(((0 * 2 + 0) * 128 + brow) * 40 + bhalf * 16) * 2;
        uint32_t dL = Bu32 + (uint32_t)(((0 * 2 + 1) * 128 + brow) * 40 + bhalf * 16) * 2;
        cp16(dH, sH); cp16(dH + 16, sH + 8);
        cp16(dL, sL); cp16(dL + 16, sL + 8);
        cp_commit();
    }

    int buf = 0;
    for (int kt = 0; kt < nkt; kt++) {
        // convert prefetched A regs -> smem hi/lo
        {
            __nv_bfloat16* ah = Asm + ((buf * 2 + 0) * 128 + row) * 40;
            __nv_bfloat16* al = Asm + ((buf * 2 + 1) * 128 + row) * 40;
#pragma unroll
            for (int i = 0; i < 4; i++) {
                int col = half * 16 + i * 4;
                float4 x = v[i];
                __nv_bfloat16 hx = __float2bfloat16_rn(x.x);
                __nv_bfloat16 hy = __float2bfloat16_rn(x.y);
                __nv_bfloat16 hz = __float2bfloat16_rn(x.z);
                __nv_bfloat16 hw = __float2bfloat16_rn(x.w);
                ah[col + 0] = hx; ah[col + 1] = hy; ah[col + 2] = hz; ah[col + 3] = hw;
                al[col + 0] = __float2bfloat16_rn(x.x - __bfloat162float(hx));
                al[col + 1] = __float2bfloat16_rn(x.y - __bfloat162float(hy));
                al[col + 2] = __float2bfloat16_rn(x.z - __bfloat162float(hz));
                al[col + 3] = __float2bfloat16_rn(x.w - __bfloat162float(hw));
            }
        }
        cp_wait0();          // B[kt] resident
        __syncthreads();     // A stores visible; everyone past wait
        // issue B[kt+1] into other buffer (lands during MMA)
        if (kt + 1 < nkt) {
            int k0n = (kt + 1) << 5;
            const __nv_bfloat16* sH = Bhi + (size_t)(n0 + brow) * ldK + k0n + bhalf * 16;
            const __nv_bfloat16* sL = Blo + (size_t)(n0 + brow) * ldK + k0n + bhalf * 16;
            int ob = buf ^ 1;
            uint32_t dH = Bu32 + (uint32_t)(((ob * 2 + 0) * 128 + brow) * 40 + bhalf * 16) * 2;
            uint32_t dL = Bu32 + (uint32_t)(((ob * 2 + 1) * 128 + brow) * 40 + bhalf * 16) * 2;
            cp16(dH, sH); cp16(dH + 16, sH + 8);
            cp16(dL, sL); cp16(dL + 16, sL + 8);
            cp_commit();
            // prefetch next A tile
            const float* Ap; int ld, kl;
            if (k0n < K1) { Ap = A1; ld = lda1; kl = k0n; }
            else          { Ap = A2; ld = lda2; kl = k0n - K1; }
            const float* src = Ap + (size_t)m * ld + kl + half * 16;
#pragma unroll
            for (int i = 0; i < 4; i++)
                v[i] = mok ? *(const float4*)(src + i * 4) : make_float4(0.f, 0.f, 0.f, 0.f);
        }
        if (active) {
            const __nv_bfloat16* BsH = Bsm + (buf * 2 + 0) * 128 * 40;
            const __nv_bfloat16* BsL = Bsm + (buf * 2 + 1) * 128 * 40;
#pragma unroll
            for (int kk = 0; kk < 32; kk += 16) {
                wmma::fragment<wmma::matrix_b, 16, 16, 16, __nv_bfloat16, wmma::col_major> bh[2], bl2[2];
#pragma unroll
                for (int j = 0; j < 2; j++) {
                    wmma::load_matrix_sync(bh[j],  BsH + (nl + j * 16) * 40 + kk, 40u);
                    wmma::load_matrix_sync(bl2[j], BsL + (nl + j * 16) * 40 + kk, 40u);
                }
#pragma unroll
                for (int i = 0; i < 4; i++) {
                    wmma::fragment<wmma::matrix_a, 16, 16, 16, __nv_bfloat16, wmma::row_major> ah, al;
                    wmma::load_matrix_sync(ah, Asm + ((buf * 2 + 0) * 128 + wm * 64 + i * 16) * 40 + kk, 40u);
                    wmma::load_matrix_sync(al, Asm + ((buf * 2 + 1) * 128 + wm * 64 + i * 16) * 40 + kk, 40u);
#pragma unroll
                    for (int j = 0; j < 2; j++) {
                        wmma::mma_sync(acc[i][j], ah, bh[j],  acc[i][j]);
                        wmma::mma_sync(acc[i][j], ah, bl2[j], acc[i][j]);
                        wmma::mma_sync(acc[i][j], al, bh[j],  acc[i][j]);
                    }
                }
            }
        }
        buf ^= 1;
    }
    __syncthreads();

    if (active) {
        float* myp = reinterpret_cast<float*>(dynsmem) + wid * 320;
        int base = lane * 8;
        int pr = base >> 4, pc = base & 15;
#pragma unroll
        for (int i = 0; i < 4; i++) {
#pragma unroll
            for (int j = 0; j < 2; j++) {
                wmma::store_matrix_sync(myp, acc[i][j], 20u, wmma::mem_row_major);
                __syncwarp();
                int mb = mw + i * 16, nb = nw + j * 16;
                if (mb + pr < M) {
                    float out[8];
#pragma unroll
                    for (int t = 0; t < 8; t++) {
                        int n = nb + pc + t;
                        float val = myp[pr * 20 + pc + t] * alpha + bias[n];
                        if (EPI >= 1) val = fmaxf(val, 0.0f);
                        if (EPI == 2) val = val * bnS[n] + bnB[n];
                        out[t] = val;
                    }
                    float* dst = C + (size_t)(mb + pr) * ldc + coff + nb + pc;
                    *(float4*)dst = *(float4*)&out[0];
                    *(float4*)(dst + 4) = *(float4*)&out[4];
                }
                __syncwarp();
            }
        }
    }
}

// ================= elementwise kernels =======================================
template <int R>
__global__ void l0post_k(const float* __restrict__ O, int ldo,
                         const float* __restrict__ gg, const float* __restrict__ bb,
                         float* __restrict__ xout, int M) {
    int row = blockIdx.x * 8 + (threadIdx.x >> 5);
    if (row >= M) return;
    int lane = threadIdx.x & 31;
    float acc[4] = {0.f, 0.f, 0.f, 0.f};
#pragma unroll
    for (int rb = 0; rb < R; rb++) {
        const float* p = O + (size_t)row * ldo + rb * 128;
        float v[4]; float ss = 0.f;
#pragma unroll
        for (int j = 0; j < 4; j++) { v[j] = p[lane + 32 * j]; ss += v[j] * v[j]; }
#pragma unroll
        for (int s = 16; s; s >>= 1) ss += __shfl_xor_sync(0xffffffffu, ss, s);
        float inv = 1.0f / fmaxf(sqrtf(ss), 1e-12f);
#pragma unroll
        for (int j = 0; j < 4; j++) acc[j] += v[j] * inv;
    }
    const float invR = 1.0f / R;
    float s = 0.f;
#pragma unroll
    for (int j = 0; j < 4; j++) { acc[j] = fmaxf(acc[j] * invR, 0.f); s += acc[j]; }
#pragma unroll
    for (int o = 16; o; o >>= 1) s += __shfl_xor_sync(0xffffffffu, s, o);
    float m = s * (1.0f / 128.0f);
    float ss = 0.f;
#pragma unroll
    for (int j = 0; j < 4; j++) { float d = acc[j] - m; ss += d * d; }
#pragma unroll
    for (int o = 16; o; o >>= 1) ss += __shfl_xor_sync(0xffffffffu, ss, o);
    float inv = rsqrtf(ss * (1.0f / 128.0f) + 1e-5f);
    float* q = xout + (size_t)row * 128;
#pragma unroll
    for (int j = 0; j < 4; j++) {
        int c = lane + 32 * j;
        q[c] = (acc[j] - m) * inv * gg[c] + bb[c];
    }
}
__global__ void relu_ln_k(const float* __restrict__ acc, float invr,
                          const float* __restrict__ gg, const float* __restrict__ bb,
                          float* __restrict__ xout, int M) {
    int row = blockIdx.x * 8 + (threadIdx.x >> 5);
    if (row >= M) return;
    int lane = threadIdx.x & 31;
    const float* p = acc + (size_t)row * 128;
    float v[4]; float s = 0.f;
#pragma unroll
    for (int j = 0; j < 4; j++) { v[j] = fmaxf(p[lane + 32 * j] * invr, 0.f); s += v[j]; }
#pragma unroll
    for (int o = 16; o; o >>= 1) s += __shfl_xor_sync(0xffffffffu, s, o);
    float m = s * (1.0f / 128.0f);
    float ss = 0.f;
#pragma unroll
    for (int j = 0; j < 4; j++) { float d = v[j] - m; ss += d * d; }
#pragma unroll
    for (int o = 16; o; o >>= 1) ss += __shfl_xor_sync(0xffffffffu, ss, o);
    float inv = rsqrtf(ss * (1.0f / 128.0f) + 1e-5f);
    float* q = xout + (size_t)row * 128;
#pragma unroll
    for (int j = 0; j < 4; j++) {
        int c = lane + 32 * j;
        q[c] = (v[j] - m) * inv * gg[c] + bb[c];
    }
}

// ================= single fused weight-prep kernel ===========================
__device__ __forceinline__ void bsplit(float x, __nv_bfloat16& h, __nv_bfloat16& l) {
    h = __float2bfloat16_rn(x);
    l = __float2bfloat16_rn(x - __bfloat162float(h));
}
__device__ __forceinline__ void lsplit_body(__nv_bfloat16* hi, __nv_bfloat16* lo,
                                            const float* WlL, const float* WrL,
                                            int r0, int r1, int r2, int nrel, int idx) {
    int K = nrel * 128 + 128;
    int n = idx / K, k = idx - n * K;
    float x;
    if (k < nrel * 128) {
        int j = k >> 7, kk = k & 127;
        int r = (j == 0) ? r0 : (j == 1) ? r1 : r2;
        x = WlL[(size_t)r * 16384 + kk * 128 + n];
    } else {
        int kk = k - nrel * 128;
        x = WrL[(size_t)r0 * 16384 + kk * 128 + n] + WrL[(size_t)r1 * 16384 + kk * 128 + n];
        if (nrel == 3) x += WrL[(size_t)r2 * 16384 + kk * 128 + n];
    }
    __nv_bfloat16 h, l;
    bsplit(x, h, l);
    hi[idx] = h;
    lo[idx] = l;
}
#define PREP_TOTAL 305152
__global__ void prep_k(const float* __restrict__ proj_W, const float* __restrict__ proj_b,
                       const float* __restrict__ l0_Wl, const float* __restrict__ l0_bl,
                       const float* __restrict__ l0_Wr,
                       const float* __restrict__ Wl, const float* __restrict__ bl,
                       const float* __restrict__ Wr,
                       const float* __restrict__ mlp_W1, const float* __restrict__ mlp_W2,
                       const float* __restrict__ bn_g) {
    int idx = blockIdx.x * 256 + threadIdx.x;
    __nv_bfloat16 h, l;
    if (idx < 12288) {
        int j = idx >> 12, rem = idx & 4095;
        int k = rem >> 6, c = rem & 63;
        float x = proj_W[(size_t)j * 4096 + k * 64 + c];
        int n = j * 64 + c;
        bsplit(x, h, l);
        g_BtProjN[0][n * 64 + k] = h; g_BtProjN[1][n * 64 + k] = l;
        return;
    }
    idx -= 12288;
    if (idx < 8192) {
        int j = idx >> 12, rem = idx & 4095;
        int k = rem >> 6, c = rem & 63;
        int r = (j == 0) ? 3 : 4;
        float x = proj_W[(size_t)r * 4096 + k * 64 + c];
        int n = j * 64 + c;
        bsplit(x, h, l);
        g_BtProjB[0][n * 64 + k] = h; g_BtProjB[1][n * 64 + k] = l;
        return;
    }
    idx -= 8192;
    if (idx < 81920) {
        int s = idx >> 14, rem = idx & 16383;
        int n = rem >> 7, k = rem & 127;
        const int rels[5] = {0, 1, 3, 2, 4};
        int r = rels[s];
        float x = (k < 64) ? l0_Wr[(size_t)r * 8192 + k * 128 + n]
                           : l0_Wl[(size_t)r * 8192 + (k - 64) * 128 + n];
        bsplit(x, h, l);
        g_BtL0[0][s][rem] = h; g_BtL0[1][s][rem] = l;
        return;
    }
    idx -= 81920;
    if (idx < 65536) { lsplit_body(g_BtL1N[0], g_BtL1N[1], Wl, Wr, 0, 1, 3, 3, idx); return; }
    idx -= 65536;
    if (idx < 49152) { lsplit_body(g_BtL1B[0], g_BtL1B[1], Wl, Wr, 2, 4, 0, 2, idx); return; }
    idx -= 49152;
    if (idx < 65536) { lsplit_body(g_BtL2N[0], g_BtL2N[1], Wl + 5 * 16384, Wr + 5 * 16384, 0, 1, 3, 3, idx); return; }
    idx -= 65536;
    if (idx < 16384) {
        int k = idx >> 7, n = idx & 127;
        bsplit(mlp_W1[idx], h, l);
        g_BtM1[0][n * 128 + k] = h; g_BtM1[1][n * 128 + k] = l;
        return;
    }
    idx -= 16384;
    if (idx < 4096) {
        int k = idx / 32, n = idx - (idx / 32) * 32;
        bsplit(mlp_W2[idx], h, l);
        g_BtM2[0][n * 128 + k] = h; g_BtM2[1][n * 128 + k] = l;
        return;
    }
    idx -= 4096;
    int t = idx;
    if (t < 192) {
        int j = t / 64;
        g_pbCatN[t] = proj_b[(size_t)j * 64 + (t - j * 64)];
    } else if (t < 320) {
        int local = t - 192; int j = local / 64;
        int r = (j == 0) ? 3 : 4;
        g_pbCatB[local] = proj_b[(size_t)r * 64 + (local - j * 64)];
    } else if (t < 704) {
        int local = t - 320; int j = local / 128;
        int r = (j == 0) ? 0 : (j == 1) ? 1 : 3;
        g_l0blCatN[local] = l0_bl[(size_t)r * 128 + (local - j * 128)];
    } else if (t < 960) {
        int local = t - 704; int j = local / 128;
        int r = (j == 0) ? 2 : 4;
        g_l0blCatB[local] = l0_bl[(size_t)r * 128 + (local - j * 128)];
    } else if (t < 1088) {
        int i = t - 960;
        g_b1SumN[i] = bl[i] + bl[128 + i] + bl[3 * 128 + i];
    } else if (t < 1216) {
        int i = t - 1088;
        g_b1SumB[i] = bl[2 * 128 + i] + bl[4 * 128 + i];
    } else if (t < 1344) {
        int i = t - 1216;
        g_b2SumN[i] = bl[(5 + 0) * 128 + i] + bl[(5 + 1) * 128 + i] + bl[(5 + 3) * 128 + i];
    } else if (t < 1472) {
        int i = t - 1344;
        g_bnS[i] = bn_g[i] * rsqrtf(1.0f + 1e-5f);
    }
}

// ================= host dispatch =============================================
static void tgemm(int epi, const float* A1, int lda1, int K1,
                  const float* A2, int lda2, int K2,
                  const __nv_bfloat16* Bh, const __nv_bfloat16* Bl, int ldK,
                  const float* bias, float* C, int ldc, int coff,
                  int M, int Nfull, float alpha,
                  const float* bnS, const float* bnB,
                  int gz = 1, int bStrideZ = 0, int a2StrideZ = 0,
                  int coffStrideZ = 0, int biasStrideZ = 0) {
    dim3 g((M + 127) / 128, (Nfull + 127) / 128, gz);
    if (epi == 0) {
        cudaFuncSetAttribute(tgemm_k<0>, cudaFuncAttributeMaxDynamicSharedMemorySize, TG_DSM);
        tgemm_k<0><<<g, 256, TG_DSM>>>(A1, lda1, K1, A2, lda2, K2, Bh, Bl, ldK, bias, C, ldc, coff, M, Nfull, alpha, bnS, bnB, bStrideZ, a2StrideZ, coffStrideZ, biasStrideZ);
    } else if (epi == 1) {
        cudaFuncSetAttribute(tgemm_k<1>, cudaFuncAttributeMaxDynamicSharedMemorySize, TG_DSM);
        tgemm_k<1><<<g, 256, TG_DSM>>>(A1, lda1, K1, A2, lda2, K2, Bh, Bl, ldK, bias, C, ldc, coff, M, Nfull, alpha, bnS, bnB, bStrideZ, a2StrideZ, coffStrideZ, biasStrideZ);
    } else {
        cudaFuncSetAttribute(tgemm_k<2>, cudaFuncAttributeMaxDynamicSharedMemorySize, TG_DSM);
        tgemm_k<2><<<g, 256, TG_DSM>>>(A1, lda1, K1, A2, lda2, K2, Bh, Bl, ldK, bias, C, ldc, coff, M, Nfull, alpha, bnS, bnB, bStrideZ, a2StrideZ, coffStrideZ, biasStrideZ);
    }
}

extern "C" void kernel_launch(void* const* d_in, const int* in_sizes, int n_in,
                              void* d_out, int out_size) {
    const float* x_note = (const float*)d_in[0];
    const float* x_beat = (const float*)d_in[1];
    const int* e[5] = {(const int*)d_in[2], (const int*)d_in[3], (const int*)d_in[4],
                       (const int*)d_in[5], (const int*)d_in[6]};
    int E[5];
    for (int r = 0; r < 5; r++) E[r] = in_sizes[2 + r] / 2;
    const float* proj_W = (const float*)d_in[7];
    const float* proj_b = (const float*)d_in[8];
    const float* l0_Wl  = (const float*)d_in[9];
    const float* l0_bl  = (const float*)d_in[10];
    const float* l0_Wr  = (const float*)d_in[11];
    const float* Wl     = (const float*)d_in[12];
    const float* bl     = (const float*)d_in[13];
    const float* Wr     = (const float*)d_in[14];
    const float* ln_g   = (const float*)d_in[15];
    const float* ln_b   = (const float*)d_in[16];
    const float* mlp_W1 = (const float*)d_in[17];
    const float* mlp_b1 = (const float*)d_in[18];
    const float* bn_g   = (const float*)d_in[19];
    const float* bn_b   = (const float*)d_in[20];
    const float* mlp_W2 = (const float*)d_in[21];
    const float* mlp_b2 = (const float*)d_in[22];

    float *pn, *pb, *aggn, *aggb, *On, *Ob, *xn0, *xn1, *xb0, *xb1, *outn, *outb, *cntf;
    int *cnti, *rowp, *colx;
    cudaGetSymbolAddress((void**)&pn, g_pn);       cudaGetSymbolAddress((void**)&pb, g_pb);
    cudaGetSymbolAddress((void**)&aggn, g_aggn);   cudaGetSymbolAddress((void**)&aggb, g_aggb);
    cudaGetSymbolAddress((void**)&On, g_On);       cudaGetSymbolAddress((void**)&Ob, g_Ob);
    cudaGetSymbolAddress((void**)&xn0, g_xn0);     cudaGetSymbolAddress((void**)&xn1, g_xn1);
    cudaGetSymbolAddress((void**)&xb0, g_xb0);     cudaGetSymbolAddress((void**)&xb1, g_xb1);
    cudaGetSymbolAddress((void**)&outn, g_outn);   cudaGetSymbolAddress((void**)&outb, g_outb);
    cudaGetSymbolAddress((void**)&cntf, g_cnt);    cudaGetSymbolAddress((void**)&cnti, g_cnti);
    cudaGetSymbolAddress((void**)&rowp, g_rowp);   cudaGetSymbolAddress((void**)&colx, g_col);

    float *pbCatN, *pbCatB, *l0blCatN, *l0blCatB, *b1SumN, *b1SumB, *b2SumN, *bnS;
    cudaGetSymbolAddress((void**)&pbCatN, g_pbCatN);     cudaGetSymbolAddress((void**)&pbCatB, g_pbCatB);
    cudaGetSymbolAddress((void**)&l0blCatN, g_l0blCatN); cudaGetSymbolAddress((void**)&l0blCatB, g_l0blCatB);
    cudaGetSymbolAddress((void**)&b1SumN, g_b1SumN);     cudaGetSymbolAddress((void**)&b1SumB, g_b1SumB);
    cudaGetSymbolAddress((void**)&b2SumN, g_b2SumN);     cudaGetSymbolAddress((void**)&bnS, g_bnS);

    __nv_bfloat16 *BtProjN[2], *BtProjB[2], *BtL0[2], *BtL1N[2], *BtL1B[2], *BtL2N[2], *BtM1[2], *BtM2[2];
    {
        __nv_bfloat16* p;
        cudaGetSymbolAddress((void**)&p, g_BtProjN); BtProjN[0] = p; BtProjN[1] = p + 256 * 64;
        cudaGetSymbolAddress((void**)&p, g_BtProjB); BtProjB[0] = p; BtProjB[1] = p + 128 * 64;
        cudaGetSymbolAddress((void**)&p, g_BtL0);    BtL0[0] = p;    BtL0[1] = p + 5 * 128 * 128;
        cudaGetSymbolAddress((void**)&p, g_BtL1N);   BtL1N[0] = p;   BtL1N[1] = p + 128 * 512;
        cudaGetSymbolAddress((void**)&p, g_BtL1B);   BtL1B[0] = p;   BtL1B[1] = p + 128 * 384;
        cudaGetSymbolAddress((void**)&p, g_BtL2N);   BtL2N[0] = p;   BtL2N[1] = p + 128 * 512;
        cudaGetSymbolAddress((void**)&p, g_BtM1);    BtM1[0] = p;    BtM1[1] = p + 128 * 128;
        cudaGetSymbolAddress((void**)&p, g_BtM2);    BtM2[0] = p;    BtM2[1] = p + 128 * 128;
    }

    int ebase[5];
    { int acc = 0; for (int r = 0; r < 5; r++) { ebase[r] = acc; acc += E[r]; } }
    int maxE = 0;
    for (int r = 0; r < 5; r++) maxE = (E[r] > maxE) ? E[r] : maxE;

    detect_mode_k<<<1, 1>>>(e[0]);

    // ---- CSR build ----
    cudaMemsetAsync(cnti, 0, 5 * NN * sizeof(int));
    counti5_k<<<dim3((maxE + 255) / 256, 5), 256>>>(e[0], e[1], e[2], e[3], e[4],
                                                    E[0], E[1], E[2], E[3], E[4]);
    scan1_k<<<dim3(NBX, 5), 256>>>();
    scan2_k<<<1, 32>>>();
    scan3_k<<<dim3(NBX, 5), 256>>>();
    fill5_k<<<dim3((maxE + 255) / 256, 5), 256>>>(e[0], e[1], e[2], e[3], e[4],
                                                  E[0], E[1], E[2], E[3], E[4],
                                                  ebase[0], ebase[1], ebase[2], ebase[3], ebase[4]);
    const int* rp[5]; const int* cx[5]; const float* ic[5];
    for (int r = 0; r < 5; r++) {
        rp[r] = rowp + r * (NN + 1);
        cx[r] = colx + ebase[r];
        ic[r] = cntf + r * NN;
    }

    // ---- fused weight prep (single launch) ----
    prep_k<<<(PREP_TOTAL + 255) / 256, 256>>>(proj_W, proj_b, l0_Wl, l0_bl, l0_Wr,
                                              Wl, bl, Wr, mlp_W1, mlp_W2, bn_g);

    const int NBLK_N = (NN + 7) / 8;
    const int NBLK_B = (NB + 7) / 8;

    auto mkjob = [&](Agg5& J, int s, const float* xf, int lds, int soff, int rel,
                     float* agg, int ldd, int doff, int n) {
        J.xf[s] = xf; J.lds[s] = lds; J.soff[s] = soff;
        J.rowp[s] = rp[rel]; J.col[s] = cx[rel]; J.invc[s] = ic[rel];
        J.agg[s] = agg; J.ldd[s] = ldd; J.doff[s] = doff; J.n[s] = n;
    };

    // ==================== layer 0 ====================
    tgemm(1, x_note, 64, 64, nullptr, 0, 0, BtProjN[0], BtProjN[1], 64, pbCatN,
          pn, 192, 0, NN, 192, 1.f, nullptr, nullptr);
    tgemm(1, x_beat, 64, 64, nullptr, 0, 0, BtProjB[0], BtProjB[1], 64, pbCatB,
          pb, 128, 0, NB, 128, 1.f, nullptr, nullptr);
    {
        Agg5 J; J.nslots = 5;
        mkjob(J, 0, pn, 192, 0,   0, aggn, 192, 0,   NN);
        mkjob(J, 1, pn, 192, 64,  1, aggn, 192, 64,  NN);
        mkjob(J, 2, pb, 128, 0,   3, aggn, 192, 128, NN);
        mkjob(J, 3, pn, 192, 128, 2, aggb, 128, 0,   NB);
        mkjob(J, 4, pb, 128, 64,  4, aggb, 128, 64,  NB);
        J.boff[0] = 0; J.boff[1] = NBLK_N; J.boff[2] = 2 * NBLK_N; J.boff[3] = 3 * NBLK_N;
        J.boff[4] = 3 * NBLK_N + NBLK_B; J.boff[5] = 3 * NBLK_N + 2 * NBLK_B;
        aggmulti_k<2><<<J.boff[5], 256>>>(J);
    }
    tgemm(0, x_note, 64, 64, aggn, 192, 64, BtL0[0], BtL0[1], 128, l0blCatN,
          On, 384, 0, NN, 128, 1.f, nullptr, nullptr,
          3, 16384, 64, 128, 128);
    tgemm(0, x_beat, 64, 64, aggb, 128, 64, BtL0[0] + 3 * 16384, BtL0[1] + 3 * 16384, 128, l0blCatB,
          Ob, 256, 0, NB, 128, 1.f, nullptr, nullptr,
          2, 16384, 64, 128, 128);
    l0post_k<3><<<NBLK_N, 256>>>(On, 384, ln_g, ln_b, xn0, NN);
    l0post_k<2><<<NBLK_B, 256>>>(Ob, 256, ln_g, ln_b, xb0, NB);

    // ==================== layer 1 ====================
    {
        Agg5 J; J.nslots = 5;
        mkjob(J, 0, xn0, 128, 0, 0, aggn, 384, 0,   NN);
        mkjob(J, 1, xn0, 128, 0, 1, aggn, 384, 128, NN);
        mkjob(J, 2, xb0, 128, 0, 3, aggn, 384, 256, NN);
        mkjob(J, 3, xn0, 128, 0, 2, aggb, 256, 0,   NB);
        mkjob(J, 4, xb0, 128, 0, 4, aggb, 256, 128, NB);
        J.boff[0] = 0; J.boff[1] = NBLK_N; J.boff[2] = 2 * NBLK_N; J.boff[3] = 3 * NBLK_N;
        J.boff[4] = 3 * NBLK_N + NBLK_B; J.boff[5] = 3 * NBLK_N + 2 * NBLK_B;
        aggmulti_k<4><<<J.boff[5], 256>>>(J);
    }
    tgemm(0, aggn, 384, 384, xn0, 128, 128, BtL1N[0], BtL1N[1], 512, b1SumN,
          outn, 128, 0, NN, 128, 1.f, nullptr, nullptr);
    tgemm(0, aggb, 256, 256, xb0, 128, 128, BtL1B[0], BtL1B[1], 384, b1SumB,
          outb, 128, 0, NB, 128, 1.f, nullptr, nullptr);
    relu_ln_k<<<NBLK_N, 256>>>(outn, 1.f / 3.f, ln_g + 128, ln_b + 128, xn1, NN);
    relu_ln_k<<<NBLK_B, 256>>>(outb, 1.f / 2.f, ln_g + 128, ln_b + 128, xb1, NB);

    // ==================== layer 2 (note dst only) ====================
    {
        Agg5 J; J.nslots = 3;
        mkjob(J, 0, xn1, 128, 0, 0, aggn, 384, 0,   NN);
        mkjob(J, 1, xn1, 128, 0, 1, aggn, 384, 128, NN);
        mkjob(J, 2, xb1, 128, 0, 3, aggn, 384, 256, NN);
        J.boff[0] = 0; J.boff[1] = NBLK_N; J.boff[2] = 2 * NBLK_N; J.boff[3] = 3 * NBLK_N;
        J.boff[4] = 3 * NBLK_N; J.boff[5] = 3 * NBLK_N;
        aggmulti_k<4><<<J.boff[3], 256>>>(J);
    }
    tgemm(0, aggn, 384, 384, xn1, 128, 128, BtL2N[0], BtL2N[1], 512, b2SumN,
          outn, 128, 0, NN, 128, 1.f, nullptr, nullptr);

    // ==================== final MLP ====================
    tgemm(2, outn, 128, 128, nullptr, 0, 0, BtM1[0], BtM1[1], 128, mlp_b1,
          On, 128, 0, NN, 128, 1.f / 3.f, bnS, bn_b);
    tgemm(0, On, 128, 128, nullptr, 0, 0, BtM2[0], BtM2[1], 128, mlp_b2,
          (float*)d_out, 32, 0, NN, 32, 1.f, nullptr, nullptr);
}

// round 9
// speedup vs baseline: 4.6868x; 1.0504x over previous
#include <cuda_runtime.h>
#include <cuda_bf16.h>
#include <mma.h>
#include <cstdint>

using namespace nvcuda;

#define NN 100000
#define NB 20000
#define INC 64
#define HID 128
#define NBX 49
#define MAXE 3000000

// ================= scratch (device globals; no runtime allocation) ==========
__device__ float g_pn  [(size_t)NN * 192];
__device__ float g_pb  [(size_t)NB * 128];
__device__ float g_aggn[(size_t)NN * 384];
__device__ float g_aggb[(size_t)NB * 256];
__device__ float g_On  [(size_t)NN * 384];
__device__ float g_Ob  [(size_t)NB * 256];
__device__ float g_xn0 [(size_t)NN * HID];
__device__ float g_xn1 [(size_t)NN * HID];
__device__ float g_xb0 [(size_t)NB * HID];
__device__ float g_xb1 [(size_t)NB * HID];
__device__ float g_outn[(size_t)NN * HID];
__device__ float g_outb[(size_t)NB * HID];
__device__ float g_cnt [5][NN];
__device__ int   g_cnti[5][NN];
__device__ int   g_rowp[5][NN + 1];
__device__ int   g_bsum[5][64];
__device__ int   g_col [MAXE];
__device__ int   g_emode;

// bias scratch
__device__ float g_pbCatN[192];
__device__ float g_pbCatB[128];
__device__ float g_l0blCatN[384];
__device__ float g_l0blCatB[256];
__device__ float g_b1SumN[128];
__device__ float g_b1SumB[128];
__device__ float g_b2SumN[128];
__device__ float g_bnS[128];
// bf16 transposed+split weights [Npad x K], hi/lo
__device__ __nv_bfloat16 g_BtProjN[2][256 * 64];
__device__ __nv_bfloat16 g_BtProjB[2][128 * 64];
__device__ __nv_bfloat16 g_BtL0  [2][5][128 * 128];
__device__ __nv_bfloat16 g_BtL1N [2][128 * 512];
__device__ __nv_bfloat16 g_BtL1B [2][128 * 384];
__device__ __nv_bfloat16 g_BtL2N [2][128 * 512];
__device__ __nv_bfloat16 g_BtM1  [2][128 * 128];
__device__ __nv_bfloat16 g_BtM2  [2][128 * 128];

// ================= edge handling / CSR ======================================
__global__ void detect_mode_k(const int* e) {
    int z = 1;
    for (int i = 1; i < 64; i += 2)
        if (e[i] != 0) z = 0;
    g_emode = z;
}
__device__ __forceinline__ int edge_at(const int* e, long long i) {
    if (g_emode) return (int)((const long long*)e)[i];
    return e[i];
}
__global__ void counti5_k(const int* e0, const int* e1, const int* e2,
                          const int* e3, const int* e4,
                          int E0, int E1, int E2, int E3, int E4) {
    int r = blockIdx.y;
    const int* e; int E;
    switch (r) {
        case 0: e = e0; E = E0; break;
        case 1: e = e1; E = E1; break;
        case 2: e = e2; E = E2; break;
        case 3: e = e3; E = E3; break;
        default: e = e4; E = E4; break;
    }
    int i = blockIdx.x * 256 + threadIdx.x;
    if (i >= E) return;
    atomicAdd(&g_cnti[r][edge_at(e, (long long)E + i)], 1);
}
__global__ void scan1_k() {
    int r = blockIdx.y;
    int n = (r == 2 || r == 4) ? NB : NN;
    int t = threadIdx.x;
    int base = blockIdx.x * 2048 + t * 8;
    int vals[8];
#pragma unroll
    for (int j = 0; j < 8; j++) {
        int idx = base + j;
        vals[j] = (idx < n) ? g_cnti[r][idx] : 0;
        if (idx < n) g_cnt[r][idx] = 1.0f / (float)max(vals[j], 1);
    }
    int tot = 0;
#pragma unroll
    for (int j = 0; j < 8; j++) tot += vals[j];
    int lane = t & 31, wid = t >> 5;
    int x = tot;
#pragma unroll
    for (int o = 1; o < 32; o <<= 1) {
        int y = __shfl_up_sync(0xffffffffu, x, o);
        if (lane >= o) x += y;
    }
    __shared__ int wsum[8];
    if (lane == 31) wsum[wid] = x;
    __syncthreads();
    if (t == 0) {
        int run = 0;
#pragma unroll
        for (int i = 0; i < 8; i++) { int v = wsum[i]; wsum[i] = run; run += v; }
        g_bsum[r][blockIdx.x] = run;
    }
    __syncthreads();
    int run = (x - tot) + wsum[wid];
#pragma unroll
    for (int j = 0; j < 8; j++) {
        int idx = base + j;
        if (idx < n) g_rowp[r][idx] = run;
        run += vals[j];
    }
}
// scan3 with scan2's cross-block prefix folded in (each block sums its
// predecessors' totals; last block also writes rowp[n])
__global__ void scan3_k() {
    int r = blockIdx.y;
    int n = (r == 2 || r == 4) ? NB : NN;
    int bx = blockIdx.x;
    int t = threadIdx.x;
    __shared__ int sb[64];
    __shared__ int s_add;
    if (t < 64) sb[t] = (t < NBX) ? g_bsum[r][t] : 0;
    __syncthreads();
    if (t == 0) {
        int a = 0;
        for (int i = 0; i < bx; i++) a += sb[i];
        s_add = a;
        if (bx == NBX - 1) g_rowp[r][n] = a + sb[NBX - 1];
    }
    __syncthreads();
    int add = s_add;
    int base = bx * 2048 + t * 8;
#pragma unroll
    for (int j = 0; j < 8; j++) {
        int idx = base + j;
        if (idx < n) {
            int v = g_rowp[r][idx] + add;
            g_rowp[r][idx] = v;
            g_cnti[r][idx] = v;
        }
    }
}
__global__ void fill5_k(const int* e0, const int* e1, const int* e2,
                        const int* e3, const int* e4,
                        int E0, int E1, int E2, int E3, int E4,
                        int b0, int b1, int b2, int b3, int b4) {
    int r = blockIdx.y;
    const int* e; int E; int eb;
    switch (r) {
        case 0: e = e0; E = E0; eb = b0; break;
        case 1: e = e1; E = E1; eb = b1; break;
        case 2: e = e2; E = E2; eb = b2; break;
        case 3: e = e3; E = E3; eb = b3; break;
        default: e = e4; E = E4; eb = b4; break;
    }
    int i = blockIdx.x * 256 + threadIdx.x;
    if (i >= E) return;
    int s = edge_at(e, i);
    int d = edge_at(e, (long long)E + i);
    int pos = atomicAdd(&g_cnti[r][d], 1);
    g_col[eb + pos] = s;
}

// ---- merged CSR seg-mean aggregation (job table, warp per dst row) ---------
struct Agg5 {
    const float* xf[5];
    const int* rowp[5];
    const int* col[5];
    const float* invc[5];
    float* agg[5];
    int lds[5], soff[5], ldd[5], doff[5], n[5];
    int boff[6];
    int nslots;
};

template <int V>
__global__ void aggmulti_k(Agg5 J) {
    int b = blockIdx.x;
    int s = 0;
    while (s + 1 < J.nslots && b >= J.boff[s + 1]) s++;
    int row = (b - J.boff[s]) * 8 + (threadIdx.x >> 5);
    if (row >= J.n[s]) return;
    int lane = threadIdx.x & 31;
    const float* xf = J.xf[s];
    const int* col = J.col[s];
    int lds = J.lds[s], soff = J.soff[s];
    int beg = J.rowp[s][row], end = J.rowp[s][row + 1];
    float acc[V];
#pragma unroll
    for (int j = 0; j < V; j++) acc[j] = 0.0f;
    int e = beg;
    for (; e + 7 < end; e += 8) {
        int si[8];
#pragma unroll
        for (int u = 0; u < 8; u++) si[u] = __ldg(&col[e + u]);
        if (V == 4) {
            float4 vv[8];
#pragma unroll
            for (int u = 0; u < 8; u++)
                vv[u] = *(const float4*)(xf + (size_t)si[u] * lds + soff + lane * V);
#pragma unroll
            for (int u = 0; u < 8; u++) {
                acc[0] += vv[u].x; acc[1] += vv[u].y;
                acc[2] += vv[u].z; acc[3] += vv[u].w;
            }
        } else {
            float2 vv[8];
#pragma unroll
            for (int u = 0; u < 8; u++)
                vv[u] = *(const float2*)(xf + (size_t)si[u] * lds + soff + lane * V);
#pragma unroll
            for (int u = 0; u < 8; u++) {
                acc[0] += vv[u].x; acc[1] += vv[u].y;
            }
        }
    }
    for (; e < end; e++) {
        int s0 = __ldg(&col[e]);
        const float* p0 = xf + (size_t)s0 * lds + soff + lane * V;
        if (V == 4) {
            float4 a = *(const float4*)p0;
            acc[0] += a.x; acc[1] += a.y; acc[2] += a.z; acc[3] += a.w;
        } else {
            float2 a = *(const float2*)p0;
            acc[0] += a.x; acc[1] += a.y;
        }
    }
    float inv = J.invc[s][row];
    float* q = J.agg[s] + (size_t)row * J.ldd[s] + J.doff[s] + lane * V;
    if (V == 4) {
        *(float4*)q = make_float4(acc[0] * inv, acc[1] * inv, acc[2] * inv, acc[3] * inv);
    } else {
        *(float2*)q = make_float2(acc[0] * inv, acc[1] * inv);
    }
}

// ================= cp.async helpers =========================================
__device__ __forceinline__ void cp16(uint32_t dst, const void* src) {
    asm volatile("cp.async.ca.shared.global [%0], [%1], 16;" :: "r"(dst), "l"(src));
}
__device__ __forceinline__ void cp_commit() {
    asm volatile("cp.async.commit_group;");
}
__device__ __forceinline__ void cp_wait0() {
    asm volatile("cp.async.wait_group 0;" ::: "memory");
}

// ================= wmma bf16 split GEMM (job table, cp.async B) =============
// Per z-slot: C[m, coff+n] = epi(alpha*([A1|A2]@W) + bias[n]).
// W pre-transposed+split bf16 [Npad x K]. Computes hi*hi + hi*lo + lo*hi.
struct TGJob {
    const float* A1[5];
    const float* A2[5];
    const __nv_bfloat16* Bhi[5];
    const __nv_bfloat16* Blo[5];
    const float* bias[5];
    float* C[5];
    int lda1[5], K1[5], lda2[5], K2[5], ldK[5], ldc[5], coff[5], M[5], Nfull[5];
    float alpha[5];
};
#define TG_DSM 81920
template <int EPI>
__global__ __launch_bounds__(256) void tgemm_k(
    TGJob J, const float* __restrict__ bnS, const float* __restrict__ bnB)
{
    extern __shared__ char dynsmem[];
    __nv_bfloat16* Asm = reinterpret_cast<__nv_bfloat16*>(dynsmem);
    __nv_bfloat16* Bsm = reinterpret_cast<__nv_bfloat16*>(dynsmem + 40960);
    uint32_t Bu32 = (uint32_t)__cvta_generic_to_shared(Bsm);

    int z = blockIdx.z;
    const float* A1 = J.A1[z];
    const float* A2 = J.A2[z];
    const __nv_bfloat16* Bhi = J.Bhi[z];
    const __nv_bfloat16* Blo = J.Blo[z];
    const float* bias = J.bias[z];
    float* C = J.C[z];
    int lda1 = J.lda1[z], K1 = J.K1[z], lda2 = J.lda2[z], K2 = J.K2[z];
    int ldK = J.ldK[z], ldc = J.ldc[z], coff = J.coff[z];
    int M = J.M[z], Nfull = J.Nfull[z];
    float alpha = J.alpha[z];

    int m0 = blockIdx.x * 128;
    int n0 = blockIdx.y * 128;
    if (m0 >= M || n0 >= Nfull) return;

    int tid = threadIdx.x;
    int wid = tid >> 5, lane = tid & 31;
    int wm = wid >> 2, wn = wid & 3;
    int mw = m0 + wm * 64;
    int nw = n0 + wn * 32;
    int nl = wn * 32;
    bool active = (nw < Nfull);
    int K = K1 + K2;
    int nkt = K >> 5;

    wmma::fragment<wmma::accumulator, 16, 16, 16, float> acc[4][2];
#pragma unroll
    for (int i = 0; i < 4; i++)
#pragma unroll
        for (int j = 0; j < 2; j++) wmma::fill_fragment(acc[i][j], 0.0f);

    int row = tid >> 1, half = tid & 1;
    int m = m0 + row;
    bool mok = (m < M);
    int brow = row, bhalf = half;

    // ---- prologue: A tile 0 -> regs; B tile 0 -> cp.async ----
    float4 v[4];
    {
        const float* Ap; int ld, kl;
        if (0 < K1) { Ap = A1; ld = lda1; kl = 0; }
        else        { Ap = A2; ld = lda2; kl = -K1; }
        const float* src = Ap + (size_t)m * ld + kl + half * 16;
#pragma unroll
        for (int i = 0; i < 4; i++)
            v[i] = mok ? *(const float4*)(src + i * 4) : make_float4(0.f, 0.f, 0.f, 0.f);
    }
    {
        const __nv_bfloat16* sH = Bhi + (size_t)(n0 + brow) * ldK + bhalf * 16;
        const __nv_bfloat16* sL = Blo + (size_t)(n0 + brow) * ldK + bhalf * 16;
        uint32_t dH = Bu32 + (uint32_t)(((0 * 2 + 0) * 128 + brow) * 40 + bhalf * 16) * 2;
        uint32_t dL = Bu32 + (uint32_t)(((0 * 2 + 1) * 128 + brow) * 40 + bhalf * 16) * 2;
        cp16(dH, sH); cp16(dH + 16, sH + 8);
        cp16(dL, sL); cp16(dL + 16, sL + 8);
        cp_commit();
    }

    int buf = 0;
    for (int kt = 0; kt < nkt; kt++) {
        // convert prefetched A regs -> smem hi/lo (packed bf16x2 stores)
        {
            __nv_bfloat162* ah = reinterpret_cast<__nv_bfloat162*>(
                Asm + ((buf * 2 + 0) * 128 + row) * 40);
            __nv_bfloat162* al = reinterpret_cast<__nv_bfloat162*>(
                Asm + ((buf * 2 + 1) * 128 + row) * 40);
#pragma unroll
            for (int i = 0; i < 4; i++) {
                int col = half * 16 + i * 4;
                float4 x = v[i];
                __nv_bfloat16 hx = __float2bfloat16_rn(x.x);
                __nv_bfloat16 hy = __float2bfloat16_rn(x.y);
                __nv_bfloat16 hz = __float2bfloat16_rn(x.z);
                __nv_bfloat16 hw = __float2bfloat16_rn(x.w);
                __nv_bfloat162 h01; h01.x = hx; h01.y = hy;
                __nv_bfloat162 h23; h23.x = hz; h23.y = hw;
                ah[(col >> 1) + 0] = h01;
                ah[(col >> 1) + 1] = h23;
                __nv_bfloat162 l01, l23;
                l01.x = __float2bfloat16_rn(x.x - __bfloat162float(hx));
                l01.y = __float2bfloat16_rn(x.y - __bfloat162float(hy));
                l23.x = __float2bfloat16_rn(x.z - __bfloat162float(hz));
                l23.y = __float2bfloat16_rn(x.w - __bfloat162float(hw));
                al[(col >> 1) + 0] = l01;
                al[(col >> 1) + 1] = l23;
            }
        }
        cp_wait0();
        __syncthreads();
        if (kt + 1 < nkt) {
            int k0n = (kt + 1) << 5;
            const __nv_bfloat16* sH = Bhi + (size_t)(n0 + brow) * ldK + k0n + bhalf * 16;
            const __nv_bfloat16* sL = Blo + (size_t)(n0 + brow) * ldK + k0n + bhalf * 16;
            int ob = buf ^ 1;
            uint32_t dH = Bu32 + (uint32_t)(((ob * 2 + 0) * 128 + brow) * 40 + bhalf * 16) * 2;
            uint32_t dL = Bu32 + (uint32_t)(((ob * 2 + 1) * 128 + brow) * 40 + bhalf * 16) * 2;
            cp16(dH, sH); cp16(dH + 16, sH + 8);
            cp16(dL, sL); cp16(dL + 16, sL + 8);
            cp_commit();
            const float* Ap; int ld, kl;
            if (k0n < K1) { Ap = A1; ld = lda1; kl = k0n; }
            else          { Ap = A2; ld = lda2; kl = k0n - K1; }
            const float* src = Ap + (size_t)m * ld + kl + half * 16;
#pragma unroll
            for (int i = 0; i < 4; i++)
                v[i] = mok ? *(const float4*)(src + i * 4) : make_float4(0.f, 0.f, 0.f, 0.f);
        }
        if (active) {
            const __nv_bfloat16* BsH = Bsm + (buf * 2 + 0) * 128 * 40;
            const __nv_bfloat16* BsL = Bsm + (buf * 2 + 1) * 128 * 40;
#pragma unroll
            for (int kk = 0; kk < 32; kk += 16) {
                wmma::fragment<wmma::matrix_b, 16, 16, 16, __nv_bfloat16, wmma::col_major> bh[2], bl2[2];
#pragma unroll
                for (int j = 0; j < 2; j++) {
                    wmma::load_matrix_sync(bh[j],  BsH + (nl + j * 16) * 40 + kk, 40u);
                    wmma::load_matrix_sync(bl2[j], BsL + (nl + j * 16) * 40 + kk, 40u);
                }
#pragma unroll
                for (int i = 0; i < 4; i++) {
                    wmma::fragment<wmma::matrix_a, 16, 16, 16, __nv_bfloat16, wmma::row_major> ah, al;
                    wmma::load_matrix_sync(ah, Asm + ((buf * 2 + 0) * 128 + wm * 64 + i * 16) * 40 + kk, 40u);
                    wmma::load_matrix_sync(al, Asm + ((buf * 2 + 1) * 128 + wm * 64 + i * 16) * 40 + kk, 40u);
#pragma unroll
                    for (int j = 0; j < 2; j++) {
                        wmma::mma_sync(acc[i][j], ah, bh[j],  acc[i][j]);
                        wmma::mma_sync(acc[i][j], ah, bl2[j], acc[i][j]);
                        wmma::mma_sync(acc[i][j], al, bh[j],  acc[i][j]);
                    }
                }
            }
        }
        buf ^= 1;
    }
    __syncthreads();

    if (active) {
        float* myp = reinterpret_cast<float*>(dynsmem) + wid * 320;
        int base = lane * 8;
        int pr = base >> 4, pc = base & 15;
#pragma unroll
        for (int i = 0; i < 4; i++) {
#pragma unroll
            for (int j = 0; j < 2; j++) {
                wmma::store_matrix_sync(myp, acc[i][j], 20u, wmma::mem_row_major);
                __syncwarp();
                int mb = mw + i * 16, nb = nw + j * 16;
                if (mb + pr < M) {
                    float out[8];
#pragma unroll
                    for (int t = 0; t < 8; t++) {
                        int n = nb + pc + t;
                        float val = myp[pr * 20 + pc + t] * alpha + bias[n];
                        if (EPI >= 1) val = fmaxf(val, 0.0f);
                        if (EPI == 2) val = val * bnS[n] + bnB[n];
                        out[t] = val;
                    }
                    float* dst = C + (size_t)(mb + pr) * ldc + coff + nb + pc;
                    *(float4*)dst = *(float4*)&out[0];
                    *(float4*)(dst + 4) = *(float4*)&out[4];
                }
                __syncwarp();
            }
        }
    }
}

// ================= merged elementwise kernels ================================
// l0post for note+beat in one launch (block-range dispatch)
__global__ void l0post2_k(const float* __restrict__ On, const float* __restrict__ Ob,
                          const float* __restrict__ gg, const float* __restrict__ bb,
                          float* __restrict__ xn, float* __restrict__ xb, int nblkN) {
    int b = blockIdx.x;
    const float* O; float* xout; int ldo, M, R;
    if (b < nblkN) { O = On; xout = xn; ldo = 384; M = NN; R = 3; }
    else           { O = Ob; xout = xb; ldo = 256; M = NB; R = 2; b -= nblkN; }
    int row = b * 8 + (threadIdx.x >> 5);
    if (row >= M) return;
    int lane = threadIdx.x & 31;
    float acc[4] = {0.f, 0.f, 0.f, 0.f};
    for (int rb = 0; rb < R; rb++) {
        const float* p = O + (size_t)row * ldo + rb * 128;
        float v[4]; float ss = 0.f;
#pragma unroll
        for (int j = 0; j < 4; j++) { v[j] = p[lane + 32 * j]; ss += v[j] * v[j]; }
#pragma unroll
        for (int s = 16; s; s >>= 1) ss += __shfl_xor_sync(0xffffffffu, ss, s);
        float inv = 1.0f / fmaxf(sqrtf(ss), 1e-12f);
#pragma unroll
        for (int j = 0; j < 4; j++) acc[j] += v[j] * inv;
    }
    const float invR = 1.0f / R;
    float s = 0.f;
#pragma unroll
    for (int j = 0; j < 4; j++) { acc[j] = fmaxf(acc[j] * invR, 0.f); s += acc[j]; }
#pragma unroll
    for (int o = 16; o; o >>= 1) s += __shfl_xor_sync(0xffffffffu, s, o);
    float m = s * (1.0f / 128.0f);
    float ss = 0.f;
#pragma unroll
    for (int j = 0; j < 4; j++) { float d = acc[j] - m; ss += d * d; }
#pragma unroll
    for (int o = 16; o; o >>= 1) ss += __shfl_xor_sync(0xffffffffu, ss, o);
    float inv = rsqrtf(ss * (1.0f / 128.0f) + 1e-5f);
    float* q = xout + (size_t)row * 128;
#pragma unroll
    for (int j = 0; j < 4; j++) {
        int c = lane + 32 * j;
        q[c] = (acc[j] - m) * inv * gg[c] + bb[c];
    }
}
// relu->LN for note+beat in one launch
__global__ void relu_ln2_k(const float* __restrict__ an, const float* __restrict__ ab,
                           const float* __restrict__ gg, const float* __restrict__ bb,
                           float* __restrict__ xn, float* __restrict__ xb, int nblkN) {
    int b = blockIdx.x;
    const float* acc; float* xout; int M; float invr;
    if (b < nblkN) { acc = an; xout = xn; M = NN; invr = 1.f / 3.f; }
    else           { acc = ab; xout = xb; M = NB; invr = 1.f / 2.f; b -= nblkN; }
    int row = b * 8 + (threadIdx.x >> 5);
    if (row >= M) return;
    int lane = threadIdx.x & 31;
    const float* p = acc + (size_t)row * 128;
    float v[4]; float s = 0.f;
#pragma unroll
    for (int j = 0; j < 4; j++) { v[j] = fmaxf(p[lane + 32 * j] * invr, 0.f); s += v[j]; }
#pragma unroll
    for (int o = 16; o; o >>= 1) s += __shfl_xor_sync(0xffffffffu, s, o);
    float m = s * (1.0f / 128.0f);
    float ss = 0.f;
#pragma unroll
    for (int j = 0; j < 4; j++) { float d = v[j] - m; ss += d * d; }
#pragma unroll
    for (int o = 16; o; o >>= 1) ss += __shfl_xor_sync(0xffffffffu, ss, o);
    float inv = rsqrtf(ss * (1.0f / 128.0f) + 1e-5f);
    float* q = xout + (size_t)row * 128;
#pragma unroll
    for (int j = 0; j < 4; j++) {
        int c = lane + 32 * j;
        q[c] = (v[j] - m) * inv * gg[c] + bb[c];
    }
}

// ================= single fused weight-prep kernel ===========================
__device__ __forceinline__ void bsplit(float x, __nv_bfloat16& h, __nv_bfloat16& l) {
    h = __float2bfloat16_rn(x);
    l = __float2bfloat16_rn(x - __bfloat162float(h));
}
__device__ __forceinline__ void lsplit_body(__nv_bfloat16* hi, __nv_bfloat16* lo,
                                            const float* WlL, const float* WrL,
                                            int r0, int r1, int r2, int nrel, int idx) {
    int K = nrel * 128 + 128;
    int n = idx / K, k = idx - n * K;
    float x;
    if (k < nrel * 128) {
        int j = k >> 7, kk = k & 127;
        int r = (j == 0) ? r0 : (j == 1) ? r1 : r2;
        x = WlL[(size_t)r * 16384 + kk * 128 + n];
    } else {
        int kk = k - nrel * 128;
        x = WrL[(size_t)r0 * 16384 + kk * 128 + n] + WrL[(size_t)r1 * 16384 + kk * 128 + n];
        if (nrel == 3) x += WrL[(size_t)r2 * 16384 + kk * 128 + n];
    }
    __nv_bfloat16 h, l;
    bsplit(x, h, l);
    hi[idx] = h;
    lo[idx] = l;
}
#define PREP_TOTAL 305152
__global__ void prep_k(const float* __restrict__ proj_W, const float* __restrict__ proj_b,
                       const float* __restrict__ l0_Wl, const float* __restrict__ l0_bl,
                       const float* __restrict__ l0_Wr,
                       const float* __restrict__ Wl, const float* __restrict__ bl,
                       const float* __restrict__ Wr,
                       const float* __restrict__ mlp_W1, const float* __restrict__ mlp_W2,
                       const float* __restrict__ bn_g) {
    int idx = blockIdx.x * 256 + threadIdx.x;
    __nv_bfloat16 h, l;
    if (idx < 12288) {
        int j = idx >> 12, rem = idx & 4095;
        int k = rem >> 6, c = rem & 63;
        float x = proj_W[(size_t)j * 4096 + k * 64 + c];
        int n = j * 64 + c;
        bsplit(x, h, l);
        g_BtProjN[0][n * 64 + k] = h; g_BtProjN[1][n * 64 + k] = l;
        return;
    }
    idx -= 12288;
    if (idx < 8192) {
        int j = idx >> 12, rem = idx & 4095;
        int k = rem >> 6, c = rem & 63;
        int r = (j == 0) ? 3 : 4;
        float x = proj_W[(size_t)r * 4096 + k * 64 + c];
        int n = j * 64 + c;
        bsplit(x, h, l);
        g_BtProjB[0][n * 64 + k] = h; g_BtProjB[1][n * 64 + k] = l;
        return;
    }
    idx -= 8192;
    if (idx < 81920) {
        int s = idx >> 14, rem = idx & 16383;
        int n = rem >> 7, k = rem & 127;
        const int rels[5] = {0, 1, 3, 2, 4};
        int r = rels[s];
        float x = (k < 64) ? l0_Wr[(size_t)r * 8192 + k * 128 + n]
                           : l0_Wl[(size_t)r * 8192 + (k - 64) * 128 + n];
        bsplit(x, h, l);
        g_BtL0[0][s][rem] = h; g_BtL0[1][s][rem] = l;
        return;
    }
    idx -= 81920;
    if (idx < 65536) { lsplit_body(g_BtL1N[0], g_BtL1N[1], Wl, Wr, 0, 1, 3, 3, idx); return; }
    idx -= 65536;
    if (idx < 49152) { lsplit_body(g_BtL1B[0], g_BtL1B[1], Wl, Wr, 2, 4, 0, 2, idx); return; }
    idx -= 49152;
    if (idx < 65536) { lsplit_body(g_BtL2N[0], g_BtL2N[1], Wl + 5 * 16384, Wr + 5 * 16384, 0, 1, 3, 3, idx); return; }
    idx -= 65536;
    if (idx < 16384) {
        int k = idx >> 7, n = idx & 127;
        bsplit(mlp_W1[idx], h, l);
        g_BtM1[0][n * 128 + k] = h; g_BtM1[1][n * 128 + k] = l;
        return;
    }
    idx -= 16384;
    if (idx < 4096) {
        int k = idx / 32, n = idx - (idx / 32) * 32;
        bsplit(mlp_W2[idx], h, l);
        g_BtM2[0][n * 128 + k] = h; g_BtM2[1][n * 128 + k] = l;
        return;
    }
    idx -= 4096;
    int t = idx;
    if (t < 192) {
        int j = t / 64;
        g_pbCatN[t] = proj_b[(size_t)j * 64 + (t - j * 64)];
    } else if (t < 320) {
        int local = t - 192; int j = local / 64;
        int r = (j == 0) ? 3 : 4;
        g_pbCatB[local] = proj_b[(size_t)r * 64 + (local - j * 64)];
    } else if (t < 704) {
        int local = t - 320; int j = local / 128;
        int r = (j == 0) ? 0 : (j == 1) ? 1 : 3;
        g_l0blCatN[local] = l0_bl[(size_t)r * 128 + (local - j * 128)];
    } else if (t < 960) {
        int local = t - 704; int j = local / 128;
        int r = (j == 0) ? 2 : 4;
        g_l0blCatB[local] = l0_bl[(size_t)r * 128 + (local - j * 128)];
    } else if (t < 1088) {
        int i = t - 960;
        g_b1SumN[i] = bl[i] + bl[128 + i] + bl[3 * 128 + i];
    } else if (t < 1216) {
        int i = t - 1088;
        g_b1SumB[i] = bl[2 * 128 + i] + bl[4 * 128 + i];
    } else if (t < 1344) {
        int i = t - 1216;
        g_b2SumN[i] = bl[(5 + 0) * 128 + i] + bl[(5 + 1) * 128 + i] + bl[(5 + 3) * 128 + i];
    } else if (t < 1472) {
        int i = t - 1344;
        g_bnS[i] = bn_g[i] * rsqrtf(1.0f + 1e-5f);
    }
}

// ================= host dispatch =============================================
static void tgemmJ(int epi, const TGJob& J, int nslots, const float* bnS, const float* bnB) {
    int maxM = 0, maxN = 0;
    for (int s = 0; s < nslots; s++) {
        if (J.M[s] > maxM) maxM = J.M[s];
        if (J.Nfull[s] > maxN) maxN = J.Nfull[s];
    }
    dim3 g((maxM + 127) / 128, (maxN + 127) / 128, nslots);
    if (epi == 0) {
        cudaFuncSetAttribute(tgemm_k<0>, cudaFuncAttributeMaxDynamicSharedMemorySize, TG_DSM);
        tgemm_k<0><<<g, 256, TG_DSM>>>(J, bnS, bnB);
    } else if (epi == 1) {
        cudaFuncSetAttribute(tgemm_k<1>, cudaFuncAttributeMaxDynamicSharedMemorySize, TG_DSM);
        tgemm_k<1><<<g, 256, TG_DSM>>>(J, bnS, bnB);
    } else {
        cudaFuncSetAttribute(tgemm_k<2>, cudaFuncAttributeMaxDynamicSharedMemorySize, TG_DSM);
        tgemm_k<2><<<g, 256, TG_DSM>>>(J, bnS, bnB);
    }
}
static void setslot(TGJob& J, int s, const float* A1, int lda1, int K1,
                    const float* A2, int lda2, int K2,
                    const __nv_bfloat16* Bh, const __nv_bfloat16* Bl, int ldK,
                    const float* bias, float* C, int ldc, int coff,
                    int M, int Nfull, float alpha) {
    J.A1[s] = A1; J.lda1[s] = lda1; J.K1[s] = K1;
    J.A2[s] = A2; J.lda2[s] = lda2; J.K2[s] = K2;
    J.Bhi[s] = Bh; J.Blo[s] = Bl; J.ldK[s] = ldK;
    J.bias[s] = bias; J.C[s] = C; J.ldc[s] = ldc; J.coff[s] = coff;
    J.M[s] = M; J.Nfull[s] = Nfull; J.alpha[s] = alpha;
}

extern "C" void kernel_launch(void* const* d_in, const int* in_sizes, int n_in,
                              void* d_out, int out_size) {
    const float* x_note = (const float*)d_in[0];
    const float* x_beat = (const float*)d_in[1];
    const int* e[5] = {(const int*)d_in[2], (const int*)d_in[3], (const int*)d_in[4],
                       (const int*)d_in[5], (const int*)d_in[6]};
    int E[5];
    for (int r = 0; r < 5; r++) E[r] = in_sizes[2 + r] / 2;
    const float* proj_W = (const float*)d_in[7];
    const float* proj_b = (const float*)d_in[8];
    const float* l0_Wl  = (const float*)d_in[9];
    const float* l0_bl  = (const float*)d_in[10];
    const float* l0_Wr  = (const float*)d_in[11];
    const float* Wl     = (const float*)d_in[12];
    const float* bl     = (const float*)d_in[13];
    const float* Wr     = (const float*)d_in[14];
    const float* ln_g   = (const float*)d_in[15];
    const float* ln_b   = (const float*)d_in[16];
    const float* mlp_W1 = (const float*)d_in[17];
    const float* mlp_b1 = (const float*)d_in[18];
    const float* bn_g   = (const float*)d_in[19];
    const float* bn_b   = (const float*)d_in[20];
    const float* mlp_W2 = (const float*)d_in[21];
    const float* mlp_b2 = (const float*)d_in[22];

    float *pn, *pb, *aggn, *aggb, *On, *Ob, *xn0, *xn1, *xb0, *xb1, *outn, *outb, *cntf;
    int *cnti, *rowp, *colx;
    cudaGetSymbolAddress((void**)&pn, g_pn);       cudaGetSymbolAddress((void**)&pb, g_pb);
    cudaGetSymbolAddress((void**)&aggn, g_aggn);   cudaGetSymbolAddress((void**)&aggb, g_aggb);
    cudaGetSymbolAddress((void**)&On, g_On);       cudaGetSymbolAddress((void**)&Ob, g_Ob);
    cudaGetSymbolAddress((void**)&xn0, g_xn0);     cudaGetSymbolAddress((void**)&xn1, g_xn1);
    cudaGetSymbolAddress((void**)&xb0, g_xb0);     cudaGetSymbolAddress((void**)&xb1, g_xb1);
    cudaGetSymbolAddress((void**)&outn, g_outn);   cudaGetSymbolAddress((void**)&outb, g_outb);
    cudaGetSymbolAddress((void**)&cntf, g_cnt);    cudaGetSymbolAddress((void**)&cnti, g_cnti);
    cudaGetSymbolAddress((void**)&rowp, g_rowp);   cudaGetSymbolAddress((void**)&colx, g_col);

    float *pbCatN, *pbCatB, *l0blCatN, *l0blCatB, *b1SumN, *b1SumB, *b2SumN, *bnS;
    cudaGetSymbolAddress((void**)&pbCatN, g_pbCatN);     cudaGetSymbolAddress((void**)&pbCatB, g_pbCatB);
    cudaGetSymbolAddress((void**)&l0blCatN, g_l0blCatN); cudaGetSymbolAddress((void**)&l0blCatB, g_l0blCatB);
    cudaGetSymbolAddress((void**)&b1SumN, g_b1SumN);     cudaGetSymbolAddress((void**)&b1SumB, g_b1SumB);
    cudaGetSymbolAddress((void**)&b2SumN, g_b2SumN);     cudaGetSymbolAddress((void**)&bnS, g_bnS);

    __nv_bfloat16 *BtProjN[2], *BtProjB[2], *BtL0[2], *BtL1N[2], *BtL1B[2], *BtL2N[2], *BtM1[2], *BtM2[2];
    {
        __nv_bfloat16* p;
        cudaGetSymbolAddress((void**)&p, g_BtProjN); BtProjN[0] = p; BtProjN[1] = p + 256 * 64;
        cudaGetSymbolAddress((void**)&p, g_BtProjB); BtProjB[0] = p; BtProjB[1] = p + 128 * 64;
        cudaGetSymbolAddress((void**)&p, g_BtL0);    BtL0[0] = p;    BtL0[1] = p + 5 * 128 * 128;
        cudaGetSymbolAddress((void**)&p, g_BtL1N);   BtL1N[0] = p;   BtL1N[1] = p + 128 * 512;
        cudaGetSymbolAddress((void**)&p, g_BtL1B);   BtL1B[0] = p;   BtL1B[1] = p + 128 * 384;
        cudaGetSymbolAddress((void**)&p, g_BtL2N);   BtL2N[0] = p;   BtL2N[1] = p + 128 * 512;
        cudaGetSymbolAddress((void**)&p, g_BtM1);    BtM1[0] = p;    BtM1[1] = p + 128 * 128;
        cudaGetSymbolAddress((void**)&p, g_BtM2);    BtM2[0] = p;    BtM2[1] = p + 128 * 128;
    }

    int ebase[5];
    { int acc = 0; for (int r = 0; r < 5; r++) { ebase[r] = acc; acc += E[r]; } }
    int maxE = 0;
    for (int r = 0; r < 5; r++) maxE = (E[r] > maxE) ? E[r] : maxE;

    detect_mode_k<<<1, 1>>>(e[0]);

    // ---- CSR build ----
    cudaMemsetAsync(cnti, 0, 5 * NN * sizeof(int));
    counti5_k<<<dim3((maxE + 255) / 256, 5), 256>>>(e[0], e[1], e[2], e[3], e[4],
                                                    E[0], E[1], E[2], E[3], E[4]);
    scan1_k<<<dim3(NBX, 5), 256>>>();
    scan3_k<<<dim3(NBX, 5), 256>>>();
    fill5_k<<<dim3((maxE + 255) / 256, 5), 256>>>(e[0], e[1], e[2], e[3], e[4],
                                                  E[0], E[1], E[2], E[3], E[4],
                                                  ebase[0], ebase[1], ebase[2], ebase[3], ebase[4]);
    const int* rp[5]; const int* cx[5]; const float* ic[5];
    for (int r = 0; r < 5; r++) {
        rp[r] = rowp + r * (NN + 1);
        cx[r] = colx + ebase[r];
        ic[r] = cntf + r * NN;
    }

    // ---- fused weight prep (single launch) ----
    prep_k<<<(PREP_TOTAL + 255) / 256, 256>>>(proj_W, proj_b, l0_Wl, l0_bl, l0_Wr,
                                              Wl, bl, Wr, mlp_W1, mlp_W2, bn_g);

    const int NBLK_N = (NN + 7) / 8;
    const int NBLK_B = (NB + 7) / 8;

    auto mkjob = [&](Agg5& J, int s, const float* xf, int lds, int soff, int rel,
                     float* agg, int ldd, int doff, int n) {
        J.xf[s] = xf; J.lds[s] = lds; J.soff[s] = soff;
        J.rowp[s] = rp[rel]; J.col[s] = cx[rel]; J.invc[s] = ic[rel];
        J.agg[s] = agg; J.ldd[s] = ldd; J.doff[s] = doff; J.n[s] = n;
    };

    // ==================== layer 0 ====================
    {   // projections, note + beat in one launch
        TGJob G;
        setslot(G, 0, x_note, 64, 64, nullptr, 0, 0, BtProjN[0], BtProjN[1], 64,
                pbCatN, pn, 192, 0, NN, 192, 1.f);
        setslot(G, 1, x_beat, 64, 64, nullptr, 0, 0, BtProjB[0], BtProjB[1], 64,
                pbCatB, pb, 128, 0, NB, 128, 1.f);
        tgemmJ(1, G, 2, nullptr, nullptr);
    }
    {
        Agg5 J; J.nslots = 5;
        mkjob(J, 0, pn, 192, 0,   0, aggn, 192, 0,   NN);
        mkjob(J, 1, pn, 192, 64,  1, aggn, 192, 64,  NN);
        mkjob(J, 2, pb, 128, 0,   3, aggn, 192, 128, NN);
        mkjob(J, 3, pn, 192, 128, 2, aggb, 128, 0,   NB);
        mkjob(J, 4, pb, 128, 64,  4, aggb, 128, 64,  NB);
        J.boff[0] = 0; J.boff[1] = NBLK_N; J.boff[2] = 2 * NBLK_N; J.boff[3] = 3 * NBLK_N;
        J.boff[4] = 3 * NBLK_N + NBLK_B; J.boff[5] = 3 * NBLK_N + 2 * NBLK_B;
        aggmulti_k<2><<<J.boff[5], 256>>>(J);
    }
    {   // per-relation o = [xd | agg_r] @ [Wr_r; Wl_r] + bl_r : 5 slots, 1 launch
        TGJob G;
        for (int j = 0; j < 3; j++)
            setslot(G, j, x_note, 64, 64, aggn + j * 64, 192, 64,
                    BtL0[0] + j * 16384, BtL0[1] + j * 16384, 128,
                    l0blCatN + j * 128, On, 384, j * 128, NN, 128, 1.f);
        for (int j = 0; j < 2; j++)
            setslot(G, 3 + j, x_beat, 64, 64, aggb + j * 64, 128, 64,
                    BtL0[0] + (3 + j) * 16384, BtL0[1] + (3 + j) * 16384, 128,
                    l0blCatB + j * 128, Ob, 256, j * 128, NB, 128, 1.f);
        tgemmJ(0, G, 5, nullptr, nullptr);
    }
    l0post2_k<<<NBLK_N + NBLK_B, 256>>>(On, Ob, ln_g, ln_b, xn0, xb0, NBLK_N);

    // ==================== layer 1 ====================
    {
        Agg5 J; J.nslots = 5;
        mkjob(J, 0, xn0, 128, 0, 0, aggn, 384, 0,   NN);
        mkjob(J, 1, xn0, 128, 0, 1, aggn, 384, 128, NN);
        mkjob(J, 2, xb0, 128, 0, 3, aggn, 384, 256, NN);
        mkjob(J, 3, xn0, 128, 0, 2, aggb, 256, 0,   NB);
        mkjob(J, 4, xb0, 128, 0, 4, aggb, 256, 128, NB);
        J.boff[0] = 0; J.boff[1] = NBLK_N; J.boff[2] = 2 * NBLK_N; J.boff[3] = 3 * NBLK_N;
        J.boff[4] = 3 * NBLK_N + NBLK_B; J.boff[5] = 3 * NBLK_N + 2 * NBLK_B;
        aggmulti_k<4><<<J.boff[5], 256>>>(J);
    }
    {   // layer-1 GEMMs note + beat in one launch
        TGJob G;
        setslot(G, 0, aggn, 384, 384, xn0, 128, 128, BtL1N[0], BtL1N[1], 512,
                b1SumN, outn, 128, 0, NN, 128, 1.f);
        setslot(G, 1, aggb, 256, 256, xb0, 128, 128, BtL1B[0], BtL1B[1], 384,
                b1SumB, outb, 128, 0, NB, 128, 1.f);
        tgemmJ(0, G, 2, nullptr, nullptr);
    }
    relu_ln2_k<<<NBLK_N + NBLK_B, 256>>>(outn, outb, ln_g + 128, ln_b + 128, xn1, xb1, NBLK_N);

    // ==================== layer 2 (note dst only) ====================
    {
        Agg5 J; J.nslots = 3;
        mkjob(J, 0, xn1, 128, 0, 0, aggn, 384, 0,   NN);
        mkjob(J, 1, xn1, 128, 0, 1, aggn, 384, 128, NN);
        mkjob(J, 2, xb1, 128, 0, 3, aggn, 384, 256, NN);
        J.boff[0] = 0; J.boff[1] = NBLK_N; J.boff[2] = 2 * NBLK_N; J.boff[3] = 3 * NBLK_N;
        J.boff[4] = 3 * NBLK_N; J.boff[5] = 3 * NBLK_N;
        aggmulti_k<4><<<J.boff[3], 256>>>(J);
    }
    {
        TGJob G;
        setslot(G, 0, aggn, 384, 384, xn1, 128, 128, BtL2N[0], BtL2N[1], 512,
                b2SumN, outn, 128, 0, NN, 128, 1.f);
        tgemmJ(0, G, 1, nullptr, nullptr);
    }

    // ==================== final MLP ====================
    {
        TGJob G;
        setslot(G, 0, outn, 128, 128, nullptr, 0, 0, BtM1[0], BtM1[1], 128,
                mlp_b1, On, 128, 0, NN, 128, 1.f / 3.f);
        tgemmJ(2, G, 1, bnS, bn_b);
    }
    {
        TGJob G;
        setslot(G, 0, On, 128, 128, nullptr, 0, 0, BtM2[0], BtM2[1], 128,
                mlp_b2, (float*)d_out, 32, 0, NN, 32, 1.f);
        tgemmJ(0, G, 1, nullptr, nullptr);
    }
}

// round 10
// speedup vs baseline: 4.7247x; 1.0081x over previous
#include <cuda_runtime.h>
#include <cuda_bf16.h>
#include <mma.h>
#include <cstdint>

using namespace nvcuda;

#define NN 100000
#define NB 20000
#define INC 64
#define HID 128
#define NBX 49
#define MAXE 3000000

// ================= scratch (device globals; no runtime allocation) ==========
__device__ float g_pn  [(size_t)NN * 192];
__device__ float g_pb  [(size_t)NB * 128];
__device__ float g_aggn[(size_t)NN * 384];
__device__ float g_aggb[(size_t)NB * 256];
__device__ float g_On  [(size_t)NN * 384];
__device__ float g_Ob  [(size_t)NB * 256];
__device__ float g_xn0 [(size_t)NN * HID];
__device__ float g_xn1 [(size_t)NN * HID];
__device__ float g_xb0 [(size_t)NB * HID];
__device__ float g_xb1 [(size_t)NB * HID];
__device__ float g_outn[(size_t)NN * HID];
__device__ float g_cnt [5][NN];
__device__ int   g_cnti[5][NN];
__device__ int   g_rowp[5][NN + 1];
__device__ int   g_bsum[5][64];
__device__ int   g_col [MAXE];
__device__ int   g_emode;

// bias scratch
__device__ float g_pbCatN[192];
__device__ float g_pbCatB[128];
__device__ float g_l0blCatN[384];
__device__ float g_l0blCatB[256];
__device__ float g_b1SumN[128];
__device__ float g_b1SumB[128];
__device__ float g_b2SumN[128];
__device__ float g_bnS[128];
// bf16 transposed+split weights [Npad x K], hi/lo
__device__ __nv_bfloat16 g_BtProjN[2][256 * 64];
__device__ __nv_bfloat16 g_BtProjB[2][128 * 64];
__device__ __nv_bfloat16 g_BtL0  [2][5][128 * 128];
__device__ __nv_bfloat16 g_BtL1N [2][128 * 512];
__device__ __nv_bfloat16 g_BtL1B [2][128 * 384];
__device__ __nv_bfloat16 g_BtL2N [2][128 * 512];
__device__ __nv_bfloat16 g_BtM1  [2][128 * 128];
__device__ __nv_bfloat16 g_BtM2  [2][128 * 128];

// ================= init: zero counters + edge dtype detection ===============
__global__ void init_k(const int* e) {
    long long idx = (long long)blockIdx.x * 256 + threadIdx.x;
    if (idx < 5LL * NN) ((int*)g_cnti)[idx] = 0;
    if (idx == 0) {
        int z = 1;
        for (int i = 1; i < 64; i += 2)
            if (e[i] != 0) z = 0;
        g_emode = z;
    }
}
__device__ __forceinline__ int edge_at(const int* e, long long i) {
    if (g_emode) return (int)((const long long*)e)[i];
    return e[i];
}
__global__ void counti5_k(const int* e0, const int* e1, const int* e2,
                          const int* e3, const int* e4,
                          int E0, int E1, int E2, int E3, int E4) {
    int r = blockIdx.y;
    const int* e; int E;
    switch (r) {
        case 0: e = e0; E = E0; break;
        case 1: e = e1; E = E1; break;
        case 2: e = e2; E = E2; break;
        case 3: e = e3; E = E3; break;
        default: e = e4; E = E4; break;
    }
    int i = blockIdx.x * 256 + threadIdx.x;
    if (i >= E) return;
    atomicAdd(&g_cnti[r][edge_at(e, (long long)E + i)], 1);
}
__global__ void scan1_k() {
    int r = blockIdx.y;
    int n = (r == 2 || r == 4) ? NB : NN;
    int t = threadIdx.x;
    int base = blockIdx.x * 2048 + t * 8;
    int vals[8];
#pragma unroll
    for (int j = 0; j < 8; j++) {
        int idx = base + j;
        vals[j] = (idx < n) ? g_cnti[r][idx] : 0;
        if (idx < n) g_cnt[r][idx] = 1.0f / (float)max(vals[j], 1);
    }
    int tot = 0;
#pragma unroll
    for (int j = 0; j < 8; j++) tot += vals[j];
    int lane = t & 31, wid = t >> 5;
    int x = tot;
#pragma unroll
    for (int o = 1; o < 32; o <<= 1) {
        int y = __shfl_up_sync(0xffffffffu, x, o);
        if (lane >= o) x += y;
    }
    __shared__ int wsum[8];
    if (lane == 31) wsum[wid] = x;
    __syncthreads();
    if (t == 0) {
        int run = 0;
#pragma unroll
        for (int i = 0; i < 8; i++) { int v = wsum[i]; wsum[i] = run; run += v; }
        g_bsum[r][blockIdx.x] = run;
    }
    __syncthreads();
    int run = (x - tot) + wsum[wid];
#pragma unroll
    for (int j = 0; j < 8; j++) {
        int idx = base + j;
        if (idx < n) g_rowp[r][idx] = run;
        run += vals[j];
    }
}
__global__ void scan3_k() {
    int r = blockIdx.y;
    int n = (r == 2 || r == 4) ? NB : NN;
    int bx = blockIdx.x;
    int t = threadIdx.x;
    __shared__ int sb[64];
    __shared__ int s_add;
    if (t < 64) sb[t] = (t < NBX) ? g_bsum[r][t] : 0;
    __syncthreads();
    if (t == 0) {
        int a = 0;
        for (int i = 0; i < bx; i++) a += sb[i];
        s_add = a;
        if (bx == NBX - 1) g_rowp[r][n] = a + sb[NBX - 1];
    }
    __syncthreads();
    int add = s_add;
    int base = bx * 2048 + t * 8;
#pragma unroll
    for (int j = 0; j < 8; j++) {
        int idx = base + j;
        if (idx < n) {
            int v = g_rowp[r][idx] + add;
            g_rowp[r][idx] = v;
            g_cnti[r][idx] = v;
        }
    }
}
__global__ void fill5_k(const int* e0, const int* e1, const int* e2,
                        const int* e3, const int* e4,
                        int E0, int E1, int E2, int E3, int E4,
                        int b0, int b1, int b2, int b3, int b4) {
    int r = blockIdx.y;
    const int* e; int E; int eb;
    switch (r) {
        case 0: e = e0; E = E0; eb = b0; break;
        case 1: e = e1; E = E1; eb = b1; break;
        case 2: e = e2; E = E2; eb = b2; break;
        case 3: e = e3; E = E3; eb = b3; break;
        default: e = e4; E = E4; eb = b4; break;
    }
    int i = blockIdx.x * 256 + threadIdx.x;
    if (i >= E) return;
    int s = edge_at(e, i);
    int d = edge_at(e, (long long)E + i);
    int pos = atomicAdd(&g_cnti[r][d], 1);
    g_col[eb + pos] = s;
}

// ---- merged CSR seg-mean aggregation (job table, warp per dst row) ---------
struct Agg5 {
    const float* xf[5];
    const int* rowp[5];
    const int* col[5];
    const float* invc[5];
    float* agg[5];
    int lds[5], soff[5], ldd[5], doff[5], n[5];
    int boff[6];
    int nslots;
};

template <int V>
__global__ void aggmulti_k(Agg5 J) {
    int b = blockIdx.x;
    int s = 0;
    while (s + 1 < J.nslots && b >= J.boff[s + 1]) s++;
    int row = (b - J.boff[s]) * 8 + (threadIdx.x >> 5);
    if (row >= J.n[s]) return;
    int lane = threadIdx.x & 31;
    const float* xf = J.xf[s];
    const int* col = J.col[s];
    int lds = J.lds[s], soff = J.soff[s];
    int beg = J.rowp[s][row], end = J.rowp[s][row + 1];
    float acc[V];
#pragma unroll
    for (int j = 0; j < V; j++) acc[j] = 0.0f;
    int e = beg;
    for (; e + 7 < end; e += 8) {
        int si[8];
#pragma unroll
        for (int u = 0; u < 8; u++) si[u] = __ldg(&col[e + u]);
        if (V == 4) {
            float4 vv[8];
#pragma unroll
            for (int u = 0; u < 8; u++)
                vv[u] = *(const float4*)(xf + (size_t)si[u] * lds + soff + lane * V);
#pragma unroll
            for (int u = 0; u < 8; u++) {
                acc[0] += vv[u].x; acc[1] += vv[u].y;
                acc[2] += vv[u].z; acc[3] += vv[u].w;
            }
        } else {
            float2 vv[8];
#pragma unroll
            for (int u = 0; u < 8; u++)
                vv[u] = *(const float2*)(xf + (size_t)si[u] * lds + soff + lane * V);
#pragma unroll
            for (int u = 0; u < 8; u++) {
                acc[0] += vv[u].x; acc[1] += vv[u].y;
            }
        }
    }
    for (; e < end; e++) {
        int s0 = __ldg(&col[e]);
        const float* p0 = xf + (size_t)s0 * lds + soff + lane * V;
        if (V == 4) {
            float4 a = *(const float4*)p0;
            acc[0] += a.x; acc[1] += a.y; acc[2] += a.z; acc[3] += a.w;
        } else {
            float2 a = *(const float2*)p0;
            acc[0] += a.x; acc[1] += a.y;
        }
    }
    float inv = J.invc[s][row];
    float* q = J.agg[s] + (size_t)row * J.ldd[s] + J.doff[s] + lane * V;
    if (V == 4) {
        *(float4*)q = make_float4(acc[0] * inv, acc[1] * inv, acc[2] * inv, acc[3] * inv);
    } else {
        *(float2*)q = make_float2(acc[0] * inv, acc[1] * inv);
    }
}

// ================= cp.async helpers =========================================
__device__ __forceinline__ void cp16(uint32_t dst, const void* src) {
    asm volatile("cp.async.ca.shared.global [%0], [%1], 16;" :: "r"(dst), "l"(src));
}
__device__ __forceinline__ void cp_commit() {
    asm volatile("cp.async.commit_group;");
}
__device__ __forceinline__ void cp_wait0() {
    asm volatile("cp.async.wait_group 0;" ::: "memory");
}

// ================= wmma bf16 split GEMM (job table, cp.async B) =============
// Per z-slot: epi(alpha*([A1|A2]@W) + bias[n]).
// EPI: 0 plain, 1 relu, 2 relu+bn, 3 relu+LayerNorm fused (Nfull must be 128;
// writes C as the LN output x, ldc=128).
struct TGJob {
    const float* A1[5];
    const float* A2[5];
    const __nv_bfloat16* Bhi[5];
    const __nv_bfloat16* Blo[5];
    const float* bias[5];
    float* C[5];
    int lda1[5], K1[5], lda2[5], K2[5], ldK[5], ldc[5], coff[5], M[5], Nfull[5];
    float alpha[5];
    float invr[5];
};
#define TG_DSM 81920
template <int EPI>
__global__ __launch_bounds__(256) void tgemm_k(
    TGJob J, const float* __restrict__ bnS, const float* __restrict__ bnB)
{
    extern __shared__ char dynsmem[];
    __nv_bfloat16* Asm = reinterpret_cast<__nv_bfloat16*>(dynsmem);
    __nv_bfloat16* Bsm = reinterpret_cast<__nv_bfloat16*>(dynsmem + 40960);
    uint32_t Bu32 = (uint32_t)__cvta_generic_to_shared(Bsm);

    int z = blockIdx.z;
    const float* A1 = J.A1[z];
    const float* A2 = J.A2[z];
    const __nv_bfloat16* Bhi = J.Bhi[z];
    const __nv_bfloat16* Blo = J.Blo[z];
    const float* bias = J.bias[z];
    float* C = J.C[z];
    int lda1 = J.lda1[z], K1 = J.K1[z], lda2 = J.lda2[z], K2 = J.K2[z];
    int ldK = J.ldK[z], ldc = J.ldc[z], coff = J.coff[z];
    int M = J.M[z], Nfull = J.Nfull[z];
    float alpha = J.alpha[z];

    int m0 = blockIdx.x * 128;
    int n0 = blockIdx.y * 128;
    if (m0 >= M || n0 >= Nfull) return;

    int tid = threadIdx.x;
    int wid = tid >> 5, lane = tid & 31;
    int wm = wid >> 2, wn = wid & 3;
    int mw = m0 + wm * 64;
    int nw = n0 + wn * 32;
    int nl = wn * 32;
    bool active = (nw < Nfull);
    int K = K1 + K2;
    int nkt = K >> 5;

    wmma::fragment<wmma::accumulator, 16, 16, 16, float> acc[4][2];
#pragma unroll
    for (int i = 0; i < 4; i++)
#pragma unroll
        for (int j = 0; j < 2; j++) wmma::fill_fragment(acc[i][j], 0.0f);

    int row = tid >> 1, half = tid & 1;
    int m = m0 + row;
    bool mok = (m < M);
    int brow = row, bhalf = half;

    // ---- prologue: A tile 0 -> regs; B tile 0 -> cp.async ----
    float4 v[4];
    {
        const float* Ap; int ld, kl;
        if (0 < K1) { Ap = A1; ld = lda1; kl = 0; }
        else        { Ap = A2; ld = lda2; kl = -K1; }
        const float* src = Ap + (size_t)m * ld + kl + half * 16;
#pragma unroll
        for (int i = 0; i < 4; i++)
            v[i] = mok ? *(const float4*)(src + i * 4) : make_float4(0.f, 0.f, 0.f, 0.f);
    }
    {
        const __nv_bfloat16* sH = Bhi + (size_t)(n0 + brow) * ldK + bhalf * 16;
        const __nv_bfloat16* sL = Blo + (size_t)(n0 + brow) * ldK + bhalf * 16;
        uint32_t dH = Bu32 + (uint32_t)(((0 * 2 + 0) * 128 + brow) * 40 + bhalf * 16) * 2;
        uint32_t dL = Bu32 + (uint32_t)(((0 * 2 + 1) * 128 + brow) * 40 + bhalf * 16) * 2;
        cp16(dH, sH); cp16(dH + 16, sH + 8);
        cp16(dL, sL); cp16(dL + 16, sL + 8);
        cp_commit();
    }

    int buf = 0;
    for (int kt = 0; kt < nkt; kt++) {
        {
            __nv_bfloat162* ah = reinterpret_cast<__nv_bfloat162*>(
                Asm + ((buf * 2 + 0) * 128 + row) * 40);
            __nv_bfloat162* al = reinterpret_cast<__nv_bfloat162*>(
                Asm + ((buf * 2 + 1) * 128 + row) * 40);
#pragma unroll
            for (int i = 0; i < 4; i++) {
                int col = half * 16 + i * 4;
                float4 x = v[i];
                __nv_bfloat16 hx = __float2bfloat16_rn(x.x);
                __nv_bfloat16 hy = __float2bfloat16_rn(x.y);
                __nv_bfloat16 hz = __float2bfloat16_rn(x.z);
                __nv_bfloat16 hw = __float2bfloat16_rn(x.w);
                __nv_bfloat162 h01; h01.x = hx; h01.y = hy;
                __nv_bfloat162 h23; h23.x = hz; h23.y = hw;
                ah[(col >> 1) + 0] = h01;
                ah[(col >> 1) + 1] = h23;
                __nv_bfloat162 l01, l23;
                l01.x = __float2bfloat16_rn(x.x - __bfloat162float(hx));
                l01.y = __float2bfloat16_rn(x.y - __bfloat162float(hy));
                l23.x = __float2bfloat16_rn(x.z - __bfloat162float(hz));
                l23.y = __float2bfloat16_rn(x.w - __bfloat162float(hw));
                al[(col >> 1) + 0] = l01;
                al[(col >> 1) + 1] = l23;
            }
        }
        cp_wait0();
        __syncthreads();
        if (kt + 1 < nkt) {
            int k0n = (kt + 1) << 5;
            const __nv_bfloat16* sH = Bhi + (size_t)(n0 + brow) * ldK + k0n + bhalf * 16;
            const __nv_bfloat16* sL = Blo + (size_t)(n0 + brow) * ldK + k0n + bhalf * 16;
            int ob = buf ^ 1;
            uint32_t dH = Bu32 + (uint32_t)(((ob * 2 + 0) * 128 + brow) * 40 + bhalf * 16) * 2;
            uint32_t dL = Bu32 + (uint32_t)(((ob * 2 + 1) * 128 + brow) * 40 + bhalf * 16) * 2;
            cp16(dH, sH); cp16(dH + 16, sH + 8);
            cp16(dL, sL); cp16(dL + 16, sL + 8);
            cp_commit();
            const float* Ap; int ld, kl;
            if (k0n < K1) { Ap = A1; ld = lda1; kl = k0n; }
            else          { Ap = A2; ld = lda2; kl = k0n - K1; }
            const float* src = Ap + (size_t)m * ld + kl + half * 16;
#pragma unroll
            for (int i = 0; i < 4; i++)
                v[i] = mok ? *(const float4*)(src + i * 4) : make_float4(0.f, 0.f, 0.f, 0.f);
        }
        if (active) {
            const __nv_bfloat16* BsH = Bsm + (buf * 2 + 0) * 128 * 40;
            const __nv_bfloat16* BsL = Bsm + (buf * 2 + 1) * 128 * 40;
#pragma unroll
            for (int kk = 0; kk < 32; kk += 16) {
                wmma::fragment<wmma::matrix_b, 16, 16, 16, __nv_bfloat16, wmma::col_major> bh[2], bl2[2];
#pragma unroll
                for (int j = 0; j < 2; j++) {
                    wmma::load_matrix_sync(bh[j],  BsH + (nl + j * 16) * 40 + kk, 40u);
                    wmma::load_matrix_sync(bl2[j], BsL + (nl + j * 16) * 40 + kk, 40u);
                }
#pragma unroll
                for (int i = 0; i < 4; i++) {
                    wmma::fragment<wmma::matrix_a, 16, 16, 16, __nv_bfloat16, wmma::row_major> ah, al;
                    wmma::load_matrix_sync(ah, Asm + ((buf * 2 + 0) * 128 + wm * 64 + i * 16) * 40 + kk, 40u);
                    wmma::load_matrix_sync(al, Asm + ((buf * 2 + 1) * 128 + wm * 64 + i * 16) * 40 + kk, 40u);
#pragma unroll
                    for (int j = 0; j < 2; j++) {
                        wmma::mma_sync(acc[i][j], ah, bh[j],  acc[i][j]);
                        wmma::mma_sync(acc[i][j], ah, bl2[j], acc[i][j]);
                        wmma::mma_sync(acc[i][j], al, bh[j],  acc[i][j]);
                    }
                }
            }
        }
        buf ^= 1;
    }
    __syncthreads();

    if (EPI == 3) {
        // ---- fused relu -> LayerNorm epilogue (Nfull == 128) ----
        float* obuf = reinterpret_cast<float*>(dynsmem);   // 128 x 132 f32
#pragma unroll
        for (int i = 0; i < 4; i++)
#pragma unroll
            for (int j = 0; j < 2; j++)
                wmma::store_matrix_sync(obuf + (wm * 64 + i * 16) * 132 + nl + j * 16,
                                        acc[i][j], 132u, wmma::mem_row_major);
        __syncthreads();
        float invr = J.invr[z];
        int r0 = wid * 16;
        for (int rr = 0; rr < 16; rr++) {
            int rloc = r0 + rr;
            int mm = m0 + rloc;
            if (mm >= M) continue;
            float vv[4]; float s = 0.f;
#pragma unroll
            for (int j = 0; j < 4; j++) {
                int c = lane + 32 * j;
                float val = obuf[rloc * 132 + c] * alpha + bias[c];
                vv[j] = fmaxf(val * invr, 0.f);
                s += vv[j];
            }
#pragma unroll
            for (int o = 16; o; o >>= 1) s += __shfl_xor_sync(0xffffffffu, s, o);
            float mean = s * (1.0f / 128.0f);
            float ss = 0.f;
#pragma unroll
            for (int j = 0; j < 4; j++) { float d = vv[j] - mean; ss += d * d; }
#pragma unroll
            for (int o = 16; o; o >>= 1) ss += __shfl_xor_sync(0xffffffffu, ss, o);
            float inv = rsqrtf(ss * (1.0f / 128.0f) + 1e-5f);
            float* q = C + (size_t)mm * ldc;
#pragma unroll
            for (int j = 0; j < 4; j++) {
                int c = lane + 32 * j;
                q[c] = (vv[j] - mean) * inv * bnS[c] + bnB[c];   // bnS/bnB carry ln_g/ln_b
            }
        }
    } else if (active) {
        float* myp = reinterpret_cast<float*>(dynsmem) + wid * 320;
        int base = lane * 8;
        int pr = base >> 4, pc = base & 15;
#pragma unroll
        for (int i = 0; i < 4; i++) {
#pragma unroll
            for (int j = 0; j < 2; j++) {
                wmma::store_matrix_sync(myp, acc[i][j], 20u, wmma::mem_row_major);
                __syncwarp();
                int mb = mw + i * 16, nb = nw + j * 16;
                if (mb + pr < M) {
                    float out[8];
#pragma unroll
                    for (int t = 0; t < 8; t++) {
                        int n = nb + pc + t;
                        float val = myp[pr * 20 + pc + t] * alpha + bias[n];
                        if (EPI >= 1) val = fmaxf(val, 0.0f);
                        if (EPI == 2) val = val * bnS[n] + bnB[n];
                        out[t] = val;
                    }
                    float* dst = C + (size_t)(mb + pr) * ldc + coff + nb + pc;
                    *(float4*)dst = *(float4*)&out[0];
                    *(float4*)(dst + 4) = *(float4*)&out[4];
                }
                __syncwarp();
            }
        }
    }
}

// ================= merged elementwise: layer-0 post ==========================
__global__ void l0post2_k(const float* __restrict__ On, const float* __restrict__ Ob,
                          const float* __restrict__ gg, const float* __restrict__ bb,
                          float* __restrict__ xn, float* __restrict__ xb, int nblkN) {
    int b = blockIdx.x;
    const float* O; float* xout; int ldo, M, R;
    if (b < nblkN) { O = On; xout = xn; ldo = 384; M = NN; R = 3; }
    else           { O = Ob; xout = xb; ldo = 256; M = NB; R = 2; b -= nblkN; }
    int row = b * 8 + (threadIdx.x >> 5);
    if (row >= M) return;
    int lane = threadIdx.x & 31;
    float acc[4] = {0.f, 0.f, 0.f, 0.f};
    for (int rb = 0; rb < R; rb++) {
        const float* p = O + (size_t)row * ldo + rb * 128;
        float v[4]; float ss = 0.f;
#pragma unroll
        for (int j = 0; j < 4; j++) { v[j] = p[lane + 32 * j]; ss += v[j] * v[j]; }
#pragma unroll
        for (int s = 16; s; s >>= 1) ss += __shfl_xor_sync(0xffffffffu, ss, s);
        float inv = 1.0f / fmaxf(sqrtf(ss), 1e-12f);
#pragma unroll
        for (int j = 0; j < 4; j++) acc[j] += v[j] * inv;
    }
    const float invR = 1.0f / R;
    float s = 0.f;
#pragma unroll
    for (int j = 0; j < 4; j++) { acc[j] = fmaxf(acc[j] * invR, 0.f); s += acc[j]; }
#pragma unroll
    for (int o = 16; o; o >>= 1) s += __shfl_xor_sync(0xffffffffu, s, o);
    float m = s * (1.0f / 128.0f);
    float ss = 0.f;
#pragma unroll
    for (int j = 0; j < 4; j++) { float d = acc[j] - m; ss += d * d; }
#pragma unroll
    for (int o = 16; o; o >>= 1) ss += __shfl_xor_sync(0xffffffffu, ss, o);
    float inv = rsqrtf(ss * (1.0f / 128.0f) + 1e-5f);
    float* q = xout + (size_t)row * 128;
#pragma unroll
    for (int j = 0; j < 4; j++) {
        int c = lane + 32 * j;
        q[c] = (acc[j] - m) * inv * gg[c] + bb[c];
    }
}

// ================= single fused weight-prep kernel ===========================
__device__ __forceinline__ void bsplit(float x, __nv_bfloat16& h, __nv_bfloat16& l) {
    h = __float2bfloat16_rn(x);
    l = __float2bfloat16_rn(x - __bfloat162float(h));
}
__device__ __forceinline__ void lsplit_body(__nv_bfloat16* hi, __nv_bfloat16* lo,
                                            const float* WlL, const float* WrL,
                                            int r0, int r1, int r2, int nrel, int idx) {
    int K = nrel * 128 + 128;
    int n = idx / K, k = idx - n * K;
    float x;
    if (k < nrel * 128) {
        int j = k >> 7, kk = k & 127;
        int r = (j == 0) ? r0 : (j == 1) ? r1 : r2;
        x = WlL[(size_t)r * 16384 + kk * 128 + n];
    } else {
        int kk = k - nrel * 128;
        x = WrL[(size_t)r0 * 16384 + kk * 128 + n] + WrL[(size_t)r1 * 16384 + kk * 128 + n];
        if (nrel == 3) x += WrL[(size_t)r2 * 16384 + kk * 128 + n];
    }
    __nv_bfloat16 h, l;
    bsplit(x, h, l);
    hi[idx] = h;
    lo[idx] = l;
}
#define PREP_TOTAL 305152
__global__ void prep_k(const float* __restrict__ proj_W, const float* __restrict__ proj_b,
                       const float* __restrict__ l0_Wl, const float* __restrict__ l0_bl,
                       const float* __restrict__ l0_Wr,
                       const float* __restrict__ Wl, const float* __restrict__ bl,
                       const float* __restrict__ Wr,
                       const float* __restrict__ mlp_W1, const float* __restrict__ mlp_W2,
                       const float* __restrict__ bn_g) {
    int idx = blockIdx.x * 256 + threadIdx.x;
    __nv_bfloat16 h, l;
    if (idx < 12288) {
        int j = idx >> 12, rem = idx & 4095;
        int k = rem >> 6, c = rem & 63;
        float x = proj_W[(size_t)j * 4096 + k * 64 + c];
        int n = j * 64 + c;
        bsplit(x, h, l);
        g_BtProjN[0][n * 64 + k] = h; g_BtProjN[1][n * 64 + k] = l;
        return;
    }
    idx -= 12288;
    if (idx < 8192) {
        int j = idx >> 12, rem = idx & 4095;
        int k = rem >> 6, c = rem & 63;
        int r = (j == 0) ? 3 : 4;
        float x = proj_W[(size_t)r * 4096 + k * 64 + c];
        int n = j * 64 + c;
        bsplit(x, h, l);
        g_BtProjB[0][n * 64 + k] = h; g_BtProjB[1][n * 64 + k] = l;
        return;
    }
    idx -= 8192;
    if (idx < 81920) {
        int s = idx >> 14, rem = idx & 16383;
        int n = rem >> 7, k = rem & 127;
        const int rels[5] = {0, 1, 3, 2, 4};
        int r = rels[s];
        float x = (k < 64) ? l0_Wr[(size_t)r * 8192 + k * 128 + n]
                           : l0_Wl[(size_t)r * 8192 + (k - 64) * 128 + n];
        bsplit(x, h, l);
        g_BtL0[0][s][rem] = h; g_BtL0[1][s][rem] = l;
        return;
    }
    idx -= 81920;
    if (idx < 65536) { lsplit_body(g_BtL1N[0], g_BtL1N[1], Wl, Wr, 0, 1, 3, 3, idx); return; }
    idx -= 65536;
    if (idx < 49152) { lsplit_body(g_BtL1B[0], g_BtL1B[1], Wl, Wr, 2, 4, 0, 2, idx); return; }
    idx -= 49152;
    if (idx < 65536) { lsplit_body(g_BtL2N[0], g_BtL2N[1], Wl + 5 * 16384, Wr + 5 * 16384, 0, 1, 3, 3, idx); return; }
    idx -= 65536;
    if (idx < 16384) {
        int k = idx >> 7, n = idx & 127;
        bsplit(mlp_W1[idx], h, l);
        g_BtM1[0][n * 128 + k] = h; g_BtM1[1][n * 128 + k] = l;
        return;
    }
    idx -= 16384;
    if (idx < 4096) {
        int k = idx / 32, n = idx - (idx / 32) * 32;
        bsplit(mlp_W2[idx], h, l);
        g_BtM2[0][n * 128 + k] = h; g_BtM2[1][n * 128 + k] = l;
        return;
    }
    idx -= 4096;
    int t = idx;
    if (t < 192) {
        int j = t / 64;
        g_pbCatN[t] = proj_b[(size_t)j * 64 + (t - j * 64)];
    } else if (t < 320) {
        int local = t - 192; int j = local / 64;
        int r = (j == 0) ? 3 : 4;
        g_pbCatB[local] = proj_b[(size_t)r * 64 + (local - j * 64)];
    } else if (t < 704) {
        int local = t - 320; int j = local / 128;
        int r = (j == 0) ? 0 : (j == 1) ? 1 : 3;
        g_l0blCatN[local] = l0_bl[(size_t)r * 128 + (local - j * 128)];
    } else if (t < 960) {
        int local = t - 704; int j = local / 128;
        int r = (j == 0) ? 2 : 4;
        g_l0blCatB[local] = l0_bl[(size_t)r * 128 + (local - j * 128)];
    } else if (t < 1088) {
        int i = t - 960;
        g_b1SumN[i] = bl[i] + bl[128 + i] + bl[3 * 128 + i];
    } else if (t < 1216) {
        int i = t - 1088;
        g_b1SumB[i] = bl[2 * 128 + i] + bl[4 * 128 + i];
    } else if (t < 1344) {
        int i = t - 1216;
        g_b2SumN[i] = bl[(5 + 0) * 128 + i] + bl[(5 + 1) * 128 + i] + bl[(5 + 3) * 128 + i];
    } else if (t < 1472) {
        int i = t - 1344;
        g_bnS[i] = bn_g[i] * rsqrtf(1.0f + 1e-5f);
    }
}

// ================= host dispatch =============================================
static void tgemmJ(int epi, const TGJob& J, int nslots, const float* p0, const float* p1) {
    int maxM = 0, maxN = 0;
    for (int s = 0; s < nslots; s++) {
        if (J.M[s] > maxM) maxM = J.M[s];
        if (J.Nfull[s] > maxN) maxN = J.Nfull[s];
    }
    dim3 g((maxM + 127) / 128, (maxN + 127) / 128, nslots);
    if (epi == 0) {
        cudaFuncSetAttribute(tgemm_k<0>, cudaFuncAttributeMaxDynamicSharedMemorySize, TG_DSM);
        tgemm_k<0><<<g, 256, TG_DSM>>>(J, p0, p1);
    } else if (epi == 1) {
        cudaFuncSetAttribute(tgemm_k<1>, cudaFuncAttributeMaxDynamicSharedMemorySize, TG_DSM);
        tgemm_k<1><<<g, 256, TG_DSM>>>(J, p0, p1);
    } else if (epi == 2) {
        cudaFuncSetAttribute(tgemm_k<2>, cudaFuncAttributeMaxDynamicSharedMemorySize, TG_DSM);
        tgemm_k<2><<<g, 256, TG_DSM>>>(J, p0, p1);
    } else {
        cudaFuncSetAttribute(tgemm_k<3>, cudaFuncAttributeMaxDynamicSharedMemorySize, TG_DSM);
        tgemm_k<3><<<g, 256, TG_DSM>>>(J, p0, p1);
    }
}
static void setslot(TGJob& J, int s, const float* A1, int lda1, int K1,
                    const float* A2, int lda2, int K2,
                    const __nv_bfloat16* Bh, const __nv_bfloat16* Bl, int ldK,
                    const float* bias, float* C, int ldc, int coff,
                    int M, int Nfull, float alpha, float invr = 1.0f) {
    J.A1[s] = A1; J.lda1[s] = lda1; J.K1[s] = K1;
    J.A2[s] = A2; J.lda2[s] = lda2; J.K2[s] = K2;
    J.Bhi[s] = Bh; J.Blo[s] = Bl; J.ldK[s] = ldK;
    J.bias[s] = bias; J.C[s] = C; J.ldc[s] = ldc; J.coff[s] = coff;
    J.M[s] = M; J.Nfull[s] = Nfull; J.alpha[s] = alpha; J.invr[s] = invr;
}

extern "C" void kernel_launch(void* const* d_in, const int* in_sizes, int n_in,
                              void* d_out, int out_size) {
    const float* x_note = (const float*)d_in[0];
    const float* x_beat = (const float*)d_in[1];
    const int* e[5] = {(const int*)d_in[2], (const int*)d_in[3], (const int*)d_in[4],
                       (const int*)d_in[5], (const int*)d_in[6]};
    int E[5];
    for (int r = 0; r < 5; r++) E[r] = in_sizes[2 + r] / 2;
    const float* proj_W = (const float*)d_in[7];
    const float* proj_b = (const float*)d_in[8];
    const float* l0_Wl  = (const float*)d_in[9];
    const float* l0_bl  = (const float*)d_in[10];
    const float* l0_Wr  = (const float*)d_in[11];
    const float* Wl     = (const float*)d_in[12];
    const float* bl     = (const float*)d_in[13];
    const float* Wr     = (const float*)d_in[14];
    const float* ln_g   = (const float*)d_in[15];
    const float* ln_b   = (const float*)d_in[16];
    const float* mlp_W1 = (const float*)d_in[17];
    const float* mlp_b1 = (const float*)d_in[18];
    const float* bn_g   = (const float*)d_in[19];
    const float* bn_b   = (const float*)d_in[20];
    const float* mlp_W2 = (const float*)d_in[21];
    const float* mlp_b2 = (const float*)d_in[22];

    float *pn, *pb, *aggn, *aggb, *On, *Ob, *xn0, *xn1, *xb0, *xb1, *outn, *cntf;
    int *cnti, *rowp, *colx;
    cudaGetSymbolAddress((void**)&pn, g_pn);       cudaGetSymbolAddress((void**)&pb, g_pb);
    cudaGetSymbolAddress((void**)&aggn, g_aggn);   cudaGetSymbolAddress((void**)&aggb, g_aggb);
    cudaGetSymbolAddress((void**)&On, g_On);       cudaGetSymbolAddress((void**)&Ob, g_Ob);
    cudaGetSymbolAddress((void**)&xn0, g_xn0);     cudaGetSymbolAddress((void**)&xn1, g_xn1);
    cudaGetSymbolAddress((void**)&xb0, g_xb0);     cudaGetSymbolAddress((void**)&xb1, g_xb1);
    cudaGetSymbolAddress((void**)&outn, g_outn);
    cudaGetSymbolAddress((void**)&cntf, g_cnt);    cudaGetSymbolAddress((void**)&cnti, g_cnti);
    cudaGetSymbolAddress((void**)&rowp, g_rowp);   cudaGetSymbolAddress((void**)&colx, g_col);

    float *pbCatN, *pbCatB, *l0blCatN, *l0blCatB, *b1SumN, *b1SumB, *b2SumN, *bnS;
    cudaGetSymbolAddress((void**)&pbCatN, g_pbCatN);     cudaGetSymbolAddress((void**)&pbCatB, g_pbCatB);
    cudaGetSymbolAddress((void**)&l0blCatN, g_l0blCatN); cudaGetSymbolAddress((void**)&l0blCatB, g_l0blCatB);
    cudaGetSymbolAddress((void**)&b1SumN, g_b1SumN);     cudaGetSymbolAddress((void**)&b1SumB, g_b1SumB);
    cudaGetSymbolAddress((void**)&b2SumN, g_b2SumN);     cudaGetSymbolAddress((void**)&bnS, g_bnS);

    __nv_bfloat16 *BtProjN[2], *BtProjB[2], *BtL0[2], *BtL1N[2], *BtL1B[2], *BtL2N[2], *BtM1[2], *BtM2[2];
    {
        __nv_bfloat16* p;
        cudaGetSymbolAddress((void**)&p, g_BtProjN); BtProjN[0] = p; BtProjN[1] = p + 256 * 64;
        cudaGetSymbolAddress((void**)&p, g_BtProjB); BtProjB[0] = p; BtProjB[1] = p + 128 * 64;
        cudaGetSymbolAddress((void**)&p, g_BtL0);    BtL0[0] = p;    BtL0[1] = p + 5 * 128 * 128;
        cudaGetSymbolAddress((void**)&p, g_BtL1N);   BtL1N[0] = p;   BtL1N[1] = p + 128 * 512;
        cudaGetSymbolAddress((void**)&p, g_BtL1B);   BtL1B[0] = p;   BtL1B[1] = p + 128 * 384;
        cudaGetSymbolAddress((void**)&p, g_BtL2N);   BtL2N[0] = p;   BtL2N[1] = p + 128 * 512;
        cudaGetSymbolAddress((void**)&p, g_BtM1);    BtM1[0] = p;    BtM1[1] = p + 128 * 128;
        cudaGetSymbolAddress((void**)&p, g_BtM2);    BtM2[0] = p;    BtM2[1] = p + 128 * 128;
    }

    int ebase[5];
    { int acc = 0; for (int r = 0; r < 5; r++) { ebase[r] = acc; acc += E[r]; } }
    int maxE = 0;
    for (int r = 0; r < 5; r++) maxE = (E[r] > maxE) ? E[r] : maxE;

    // ---- CSR build ----
    init_k<<<(5 * NN + 255) / 256, 256>>>(e[0]);
    counti5_k<<<dim3((maxE + 255) / 256, 5), 256>>>(e[0], e[1], e[2], e[3], e[4],
                                                    E[0], E[1], E[2], E[3], E[4]);
    scan1_k<<<dim3(NBX, 5), 256>>>();
    scan3_k<<<dim3(NBX, 5), 256>>>();
    fill5_k<<<dim3((maxE + 255) / 256, 5), 256>>>(e[0], e[1], e[2], e[3], e[4],
                                                  E[0], E[1], E[2], E[3], E[4],
                                                  ebase[0], ebase[1], ebase[2], ebase[3], ebase[4]);
    const int* rp[5]; const int* cx[5]; const float* ic[5];
    for (int r = 0; r < 5; r++) {
        rp[r] = rowp + r * (NN + 1);
        cx[r] = colx + ebase[r];
        ic[r] = cntf + r * NN;
    }

    // ---- fused weight prep (single launch) ----
    prep_k<<<(PREP_TOTAL + 255) / 256, 256>>>(proj_W, proj_b, l0_Wl, l0_bl, l0_Wr,
                                              Wl, bl, Wr, mlp_W1, mlp_W2, bn_g);

    const int NBLK_N = (NN + 7) / 8;
    const int NBLK_B = (NB + 7) / 8;

    auto mkjob = [&](Agg5& J, int s, const float* xf, int lds, int soff, int rel,
                     float* agg, int ldd, int doff, int n) {
        J.xf[s] = xf; J.lds[s] = lds; J.soff[s] = soff;
        J.rowp[s] = rp[rel]; J.col[s] = cx[rel]; J.invc[s] = ic[rel];
        J.agg[s] = agg; J.ldd[s] = ldd; J.doff[s] = doff; J.n[s] = n;
    };

    // ==================== layer 0 ====================
    {
        TGJob G;
        setslot(G, 0, x_note, 64, 64, nullptr, 0, 0, BtProjN[0], BtProjN[1], 64,
                pbCatN, pn, 192, 0, NN, 192, 1.f);
        setslot(G, 1, x_beat, 64, 64, nullptr, 0, 0, BtProjB[0], BtProjB[1], 64,
                pbCatB, pb, 128, 0, NB, 128, 1.f);
        tgemmJ(1, G, 2, nullptr, nullptr);
    }
    {
        Agg5 J; J.nslots = 5;
        mkjob(J, 0, pn, 192, 0,   0, aggn, 192, 0,   NN);
        mkjob(J, 1, pn, 192, 64,  1, aggn, 192, 64,  NN);
        mkjob(J, 2, pb, 128, 0,   3, aggn, 192, 128, NN);
        mkjob(J, 3, pn, 192, 128, 2, aggb, 128, 0,   NB);
        mkjob(J, 4, pb, 128, 64,  4, aggb, 128, 64,  NB);
        J.boff[0] = 0; J.boff[1] = NBLK_N; J.boff[2] = 2 * NBLK_N; J.boff[3] = 3 * NBLK_N;
        J.boff[4] = 3 * NBLK_N + NBLK_B; J.boff[5] = 3 * NBLK_N + 2 * NBLK_B;
        aggmulti_k<2><<<J.boff[5], 256>>>(J);
    }
    {
        TGJob G;
        for (int j = 0; j < 3; j++)
            setslot(G, j, x_note, 64, 64, aggn + j * 64, 192, 64,
                    BtL0[0] + j * 16384, BtL0[1] + j * 16384, 128,
                    l0blCatN + j * 128, On, 384, j * 128, NN, 128, 1.f);
        for (int j = 0; j < 2; j++)
            setslot(G, 3 + j, x_beat, 64, 64, aggb + j * 64, 128, 64,
                    BtL0[0] + (3 + j) * 16384, BtL0[1] + (3 + j) * 16384, 128,
                    l0blCatB + j * 128, Ob, 256, j * 128, NB, 128, 1.f);
        tgemmJ(0, G, 5, nullptr, nullptr);
    }
    l0post2_k<<<NBLK_N + NBLK_B, 256>>>(On, Ob, ln_g, ln_b, xn0, xb0, NBLK_N);

    // ==================== layer 1 (GEMM with fused relu+LN epilogue) =========
    {
        Agg5 J; J.nslots = 5;
        mkjob(J, 0, xn0, 128, 0, 0, aggn, 384, 0,   NN);
        mkjob(J, 1, xn0, 128, 0, 1, aggn, 384, 128, NN);
        mkjob(J, 2, xb0, 128, 0, 3, aggn, 384, 256, NN);
        mkjob(J, 3, xn0, 128, 0, 2, aggb, 256, 0,   NB);
        mkjob(J, 4, xb0, 128, 0, 4, aggb, 256, 128, NB);
        J.boff[0] = 0; J.boff[1] = NBLK_N; J.boff[2] = 2 * NBLK_N; J.boff[3] = 3 * NBLK_N;
        J.boff[4] = 3 * NBLK_N + NBLK_B; J.boff[5] = 3 * NBLK_N + 2 * NBLK_B;
        aggmulti_k<4><<<J.boff[5], 256>>>(J);
    }
    {
        TGJob G;
        setslot(G, 0, aggn, 384, 384, xn0, 128, 128, BtL1N[0], BtL1N[1], 512,
                b1SumN, xn1, 128, 0, NN, 128, 1.f, 1.f / 3.f);
        setslot(G, 1, aggb, 256, 256, xb0, 128, 128, BtL1B[0], BtL1B[1], 384,
                b1SumB, xb1, 128, 0, NB, 128, 1.f, 1.f / 2.f);
        tgemmJ(3, G, 2, ln_g + 128, ln_b + 128);
    }

    // ==================== layer 2 (note dst only) ====================
    {
        Agg5 J; J.nslots = 3;
        mkjob(J, 0, xn1, 128, 0, 0, aggn, 384, 0,   NN);
        mkjob(J, 1, xn1, 128, 0, 1, aggn, 384, 128, NN);
        mkjob(J, 2, xb1, 128, 0, 3, aggn, 384, 256, NN);
        J.boff[0] = 0; J.boff[1] = NBLK_N; J.boff[2] = 2 * NBLK_N; J.boff[3] = 3 * NBLK_N;
        J.boff[4] = 3 * NBLK_N; J.boff[5] = 3 * NBLK_N;
        aggmulti_k<4><<<J.boff[3], 256>>>(J);
    }
    {
        TGJob G;
        setslot(G, 0, aggn, 384, 384, xn1, 128, 128, BtL2N[0], BtL2N[1], 512,
                b2SumN, outn, 128, 0, NN, 128, 1.f);
        tgemmJ(0, G, 1, nullptr, nullptr);
    }

    // ==================== final MLP ====================
    {
        TGJob G;
        setslot(G, 0, outn, 128, 128, nullptr, 0, 0, BtM1[0], BtM1[1], 128,
                mlp_b1, On, 128, 0, NN, 128, 1.f / 3.f);
        tgemmJ(2, G, 1, bnS, bn_b);
    }
    {
        TGJob G;
        setslot(G, 0, On, 128, 128, nullptr, 0, 0, BtM2[0], BtM2[1], 128,
                mlp_b2, (float*)d_out, 32, 0, NN, 32, 1.f);
        tgemmJ(0, G, 1, nullptr, nullptr);
    }
}

// round 12
// speedup vs baseline: 4.7751x; 1.0107x over previous
#include <cuda_runtime.h>
#include <cuda_bf16.h>
#include <mma.h>
#include <cstdint>

using namespace nvcuda;

#define NN 100000
#define NB 20000
#define INC 64
#define HID 128
#define NBX 49
#define MAXE 3000000

// ================= scratch (device globals; no runtime allocation) ==========
__device__ float g_pn  [(size_t)NN * 192];
__device__ float g_pb  [(size_t)NB * 128];
__device__ float g_aggn[(size_t)NN * 384];
__device__ float g_aggb[(size_t)NB * 256];
__device__ float g_On  [(size_t)NN * 384];
__device__ float g_Ob  [(size_t)NB * 256];
__device__ float g_xn0 [(size_t)NN * HID];
__device__ float g_xn1 [(size_t)NN * HID];
__device__ float g_xb0 [(size_t)NB * HID];
__device__ float g_xb1 [(size_t)NB * HID];
__device__ float g_outn[(size_t)NN * HID];
__device__ float g_cnt [5][NN];
__device__ int   g_cnti[5][NN];
__device__ int   g_rowp[5][NN + 1];
__device__ int   g_bsum[5][64];
__device__ int   g_col [MAXE];
__device__ int   g_emode;

// bias scratch
__device__ float g_pbCatN[192];
__device__ float g_pbCatB[128];
__device__ float g_l0blCatN[384];
__device__ float g_l0blCatB[256];
__device__ float g_b1SumN[128];
__device__ float g_b1SumB[128];
__device__ float g_b2SumN[128];
__device__ float g_bnS[128];
// bf16 transposed+split weights [Npad x K], hi/lo
__device__ __nv_bfloat16 g_BtProjN[2][256 * 64];
__device__ __nv_bfloat16 g_BtProjB[2][128 * 64];
__device__ __nv_bfloat16 g_BtL0  [2][5][128 * 128];
__device__ __nv_bfloat16 g_BtL1N [2][128 * 512];
__device__ __nv_bfloat16 g_BtL1B [2][128 * 384];
__device__ __nv_bfloat16 g_BtL2N [2][128 * 512];
__device__ __nv_bfloat16 g_BtM1  [2][128 * 128];
__device__ __nv_bfloat16 g_BtM2  [2][128 * 128];

// ================= init: zero counters + edge dtype detection ===============
__global__ void init_k(const int* e) {
    long long idx = (long long)blockIdx.x * 256 + threadIdx.x;
    if (idx < 5LL * NN) ((int*)g_cnti)[idx] = 0;
    if (idx == 0) {
        int z = 1;
        for (int i = 1; i < 64; i += 2)
            if (e[i] != 0) z = 0;
        g_emode = z;
    }
}
__device__ __forceinline__ int edge_at(const int* e, long long i) {
    if (g_emode) return (int)((const long long*)e)[i];
    return e[i];
}
__global__ void counti5_k(const int* e0, const int* e1, const int* e2,
                          const int* e3, const int* e4,
                          int E0, int E1, int E2, int E3, int E4) {
    int r = blockIdx.y;
    const int* e; int E;
    switch (r) {
        case 0: e = e0; E = E0; break;
        case 1: e = e1; E = E1; break;
        case 2: e = e2; E = E2; break;
        case 3: e = e3; E = E3; break;
        default: e = e4; E = E4; break;
    }
    int i = blockIdx.x * 256 + threadIdx.x;
    if (i >= E) return;
    atomicAdd(&g_cnti[r][edge_at(e, (long long)E + i)], 1);
}
__global__ void scan1_k() {
    int r = blockIdx.y;
    int n = (r == 2 || r == 4) ? NB : NN;
    int t = threadIdx.x;
    int base = blockIdx.x * 2048 + t * 8;
    int vals[8];
#pragma unroll
    for (int j = 0; j < 8; j++) {
        int idx = base + j;
        vals[j] = (idx < n) ? g_cnti[r][idx] : 0;
        if (idx < n) g_cnt[r][idx] = 1.0f / (float)max(vals[j], 1);
    }
    int tot = 0;
#pragma unroll
    for (int j = 0; j < 8; j++) tot += vals[j];
    int lane = t & 31, wid = t >> 5;
    int x = tot;
#pragma unroll
    for (int o = 1; o < 32; o <<= 1) {
        int y = __shfl_up_sync(0xffffffffu, x, o);
        if (lane >= o) x += y;
    }
    __shared__ int wsum[8];
    if (lane == 31) wsum[wid] = x;
    __syncthreads();
    if (t == 0) {
        int run = 0;
#pragma unroll
        for (int i = 0; i < 8; i++) { int v = wsum[i]; wsum[i] = run; run += v; }
        g_bsum[r][blockIdx.x] = run;
    }
    __syncthreads();
    int run = (x - tot) + wsum[wid];
#pragma unroll
    for (int j = 0; j < 8; j++) {
        int idx = base + j;
        if (idx < n) g_rowp[r][idx] = run;
        run += vals[j];
    }
}
__global__ void scan3_k() {
    int r = blockIdx.y;
    int n = (r == 2 || r == 4) ? NB : NN;
    int bx = blockIdx.x;
    int t = threadIdx.x;
    __shared__ int sb[64];
    __shared__ int s_add;
    if (t < 64) sb[t] = (t < NBX) ? g_bsum[r][t] : 0;
    __syncthreads();
    if (t == 0) {
        int a = 0;
        for (int i = 0; i < bx; i++) a += sb[i];
        s_add = a;
        if (bx == NBX - 1) g_rowp[r][n] = a + sb[NBX - 1];
    }
    __syncthreads();
    int add = s_add;
    int base = bx * 2048 + t * 8;
#pragma unroll
    for (int j = 0; j < 8; j++) {
        int idx = base + j;
        if (idx < n) {
            int v = g_rowp[r][idx] + add;
            g_rowp[r][idx] = v;
            g_cnti[r][idx] = v;
        }
    }
}
__global__ void fill5_k(const int* e0, const int* e1, const int* e2,
                        const int* e3, const int* e4,
                        int E0, int E1, int E2, int E3, int E4,
                        int b0, int b1, int b2, int b3, int b4) {
    int r = blockIdx.y;
    const int* e; int E; int eb;
    switch (r) {
        case 0: e = e0; E = E0; eb = b0; break;
        case 1: e = e1; E = E1; eb = b1; break;
        case 2: e = e2; E = E2; eb = b2; break;
        case 3: e = e3; E = E3; eb = b3; break;
        default: e = e4; E = E4; eb = b4; break;
    }
    int i = blockIdx.x * 256 + threadIdx.x;
    if (i >= E) return;
    int s = edge_at(e, i);
    int d = edge_at(e, (long long)E + i);
    int pos = atomicAdd(&g_cnti[r][d], 1);
    g_col[eb + pos] = s;
}

// ---- merged CSR seg-mean aggregation (job table, warp per dst row) ---------
struct Agg5 {
    const float* xf[5];
    const int* rowp[5];
    const int* col[5];
    const float* invc[5];
    float* agg[5];
    int lds[5], soff[5], ldd[5], doff[5], n[5];
    int boff[6];
    int nslots;
};

template <int V>
__global__ void aggmulti_k(Agg5 J) {
    int b = blockIdx.x;
    int s = 0;
    while (s + 1 < J.nslots && b >= J.boff[s + 1]) s++;
    int row = (b - J.boff[s]) * 8 + (threadIdx.x >> 5);
    if (row >= J.n[s]) return;
    int lane = threadIdx.x & 31;
    const float* xf = J.xf[s];
    const int* col = J.col[s];
    int lds = J.lds[s], soff = J.soff[s];
    int beg = J.rowp[s][row], end = J.rowp[s][row + 1];
    float acc[V];
#pragma unroll
    for (int j = 0; j < V; j++) acc[j] = 0.0f;
    int e = beg;
    for (; e + 7 < end; e += 8) {
        int si[8];
#pragma unroll
        for (int u = 0; u < 8; u++) si[u] = __ldg(&col[e + u]);
        if (V == 4) {
            float4 vv[8];
#pragma unroll
            for (int u = 0; u < 8; u++)
                vv[u] = *(const float4*)(xf + (size_t)si[u] * lds + soff + lane * V);
#pragma unroll
            for (int u = 0; u < 8; u++) {
                acc[0] += vv[u].x; acc[1] += vv[u].y;
                acc[2] += vv[u].z; acc[3] += vv[u].w;
            }
        } else {
            float2 vv[8];
#pragma unroll
            for (int u = 0; u < 8; u++)
                vv[u] = *(const float2*)(xf + (size_t)si[u] * lds + soff + lane * V);
#pragma unroll
            for (int u = 0; u < 8; u++) {
                acc[0] += vv[u].x; acc[1] += vv[u].y;
            }
        }
    }
    for (; e < end; e++) {
        int s0 = __ldg(&col[e]);
        const float* p0 = xf + (size_t)s0 * lds + soff + lane * V;
        if (V == 4) {
            float4 a = *(const float4*)p0;
            acc[0] += a.x; acc[1] += a.y; acc[2] += a.z; acc[3] += a.w;
        } else {
            float2 a = *(const float2*)p0;
            acc[0] += a.x; acc[1] += a.y;
        }
    }
    float inv = J.invc[s][row];
    float* q = J.agg[s] + (size_t)row * J.ldd[s] + J.doff[s] + lane * V;
    if (V == 4) {
        *(float4*)q = make_float4(acc[0] * inv, acc[1] * inv, acc[2] * inv, acc[3] * inv);
    } else {
        *(float2*)q = make_float2(acc[0] * inv, acc[1] * inv);
    }
}

// ================= cp.async helpers =========================================
__device__ __forceinline__ void cp16(uint32_t dst, const void* src) {
    asm volatile("cp.async.ca.shared.global [%0], [%1], 16;" :: "r"(dst), "l"(src));
}
__device__ __forceinline__ void cp_commit() {
    asm volatile("cp.async.commit_group;");
}
__device__ __forceinline__ void cp_wait0() {
    asm volatile("cp.async.wait_group 0;" ::: "memory");
}

__device__ __forceinline__ void bsplit(float x, __nv_bfloat16& h, __nv_bfloat16& l) {
    h = __float2bfloat16_rn(x);
    l = __float2bfloat16_rn(x - __bfloat162float(h));
}

// ================= wmma bf16 split GEMM (job table, cp.async B) =============
// Per z-slot: epi(alpha*([A1|A2]@W) + bias[n]).
// EPI: 0 plain, 1 relu, 3 relu+LN fused (Nfull==128), 4 relu+BN -> h@W2+b2 -> Cout.
struct TGJob {
    const float* A1[5];
    const float* A2[5];
    const __nv_bfloat16* Bhi[5];
    const __nv_bfloat16* Blo[5];
    const float* bias[5];
    float* C[5];
    int lda1[5], K1[5], lda2[5], K2[5], ldK[5], ldc[5], coff[5], M[5], Nfull[5];
    float alpha[5];
    float invr[5];
    // EPI=4 extras (slot 0 only)
    const __nv_bfloat16* W2h;
    const __nv_bfloat16* W2l;
    const float* b2;
    float* Cout;
};
#define TG_DSM 81920
template <int EPI>
__global__ __launch_bounds__(256) void tgemm_k(
    TGJob J, const float* __restrict__ bnS, const float* __restrict__ bnB)
{
    extern __shared__ char dynsmem[];
    __nv_bfloat16* Asm = reinterpret_cast<__nv_bfloat16*>(dynsmem);
    __nv_bfloat16* Bsm = reinterpret_cast<__nv_bfloat16*>(dynsmem + 40960);
    uint32_t Bu32 = (uint32_t)__cvta_generic_to_shared(Bsm);

    int z = blockIdx.z;
    const float* A1 = J.A1[z];
    const float* A2 = J.A2[z];
    const __nv_bfloat16* Bhi = J.Bhi[z];
    const __nv_bfloat16* Blo = J.Blo[z];
    const float* bias = J.bias[z];
    float* C = J.C[z];
    int lda1 = J.lda1[z], K1 = J.K1[z], lda2 = J.lda2[z], K2 = J.K2[z];
    int ldK = J.ldK[z], ldc = J.ldc[z], coff = J.coff[z];
    int M = J.M[z], Nfull = J.Nfull[z];
    float alpha = J.alpha[z];

    int m0 = blockIdx.x * 128;
    int n0 = blockIdx.y * 128;
    if (m0 >= M || n0 >= Nfull) return;

    int tid = threadIdx.x;
    int wid = tid >> 5, lane = tid & 31;
    int wm = wid >> 2, wn = wid & 3;
    int mw = m0 + wm * 64;
    int nw = n0 + wn * 32;
    int nl = wn * 32;
    bool active = (nw < Nfull);
    int K = K1 + K2;
    int nkt = K >> 5;

    wmma::fragment<wmma::accumulator, 16, 16, 16, float> acc[4][2];
#pragma unroll
    for (int i = 0; i < 4; i++)
#pragma unroll
        for (int j = 0; j < 2; j++) wmma::fill_fragment(acc[i][j], 0.0f);

    int row = tid >> 1, half = tid & 1;
    int m = m0 + row;
    bool mok = (m < M);
    int brow = row, bhalf = half;

    // ---- prologue ----
    float4 v[4];
    {
        const float* Ap; int ld, kl;
        if (0 < K1) { Ap = A1; ld = lda1; kl = 0; }
        else        { Ap = A2; ld = lda2; kl = -K1; }
        const float* src = Ap + (size_t)m * ld + kl + half * 16;
#pragma unroll
        for (int i = 0; i < 4; i++)
            v[i] = mok ? *(const float4*)(src + i * 4) : make_float4(0.f, 0.f, 0.f, 0.f);
    }
    {
        const __nv_bfloat16* sH = Bhi + (size_t)(n0 + brow) * ldK + bhalf * 16;
        const __nv_bfloat16* sL = Blo + (size_t)(n0 + brow) * ldK + bhalf * 16;
        uint32_t dH = Bu32 + (uint32_t)(((0 * 2 + 0) * 128 + brow) * 40 + bhalf * 16) * 2;
        uint32_t dL = Bu32 + (uint32_t)(((0 * 2 + 1) * 128 + brow) * 40 + bhalf * 16) * 2;
        cp16(dH, sH); cp16(dH + 16, sH + 8);
        cp16(dL, sL); cp16(dL + 16, sL + 8);
        cp_commit();
    }

    int buf = 0;
    for (int kt = 0; kt < nkt; kt++) {
        {
            __nv_bfloat162* ah = reinterpret_cast<__nv_bfloat162*>(
                Asm + ((buf * 2 + 0) * 128 + row) * 40);
            __nv_bfloat162* al = reinterpret_cast<__nv_bfloat162*>(
                Asm + ((buf * 2 + 1) * 128 + row) * 40);
#pragma unroll
            for (int i = 0; i < 4; i++) {
                int col = half * 16 + i * 4;
                float4 x = v[i];
                __nv_bfloat16 hx = __float2bfloat16_rn(x.x);
                __nv_bfloat16 hy = __float2bfloat16_rn(x.y);
                __nv_bfloat16 hz = __float2bfloat16_rn(x.z);
                __nv_bfloat16 hw = __float2bfloat16_rn(x.w);
                __nv_bfloat162 h01; h01.x = hx; h01.y = hy;
                __nv_bfloat162 h23; h23.x = hz; h23.y = hw;
                ah[(col >> 1) + 0] = h01;
                ah[(col >> 1) + 1] = h23;
                __nv_bfloat162 l01, l23;
                l01.x = __float2bfloat16_rn(x.x - __bfloat162float(hx));
                l01.y = __float2bfloat16_rn(x.y - __bfloat162float(hy));
                l23.x = __float2bfloat16_rn(x.z - __bfloat162float(hz));
                l23.y = __float2bfloat16_rn(x.w - __bfloat162float(hw));
                al[(col >> 1) + 0] = l01;
                al[(col >> 1) + 1] = l23;
            }
        }
        cp_wait0();
        __syncthreads();
        if (kt + 1 < nkt) {
            int k0n = (kt + 1) << 5;
            const __nv_bfloat16* sH = Bhi + (size_t)(n0 + brow) * ldK + k0n + bhalf * 16;
            const __nv_bfloat16* sL = Blo + (size_t)(n0 + brow) * ldK + k0n + bhalf * 16;
            int ob = buf ^ 1;
            uint32_t dH = Bu32 + (uint32_t)(((ob * 2 + 0) * 128 + brow) * 40 + bhalf * 16) * 2;
            uint32_t dL = Bu32 + (uint32_t)(((ob * 2 + 1) * 128 + brow) * 40 + bhalf * 16) * 2;
            cp16(dH, sH); cp16(dH + 16, sH + 8);
            cp16(dL, sL); cp16(dL + 16, sL + 8);
            cp_commit();
            const float* Ap; int ld, kl;
            if (k0n < K1) { Ap = A1; ld = lda1; kl = k0n; }
            else          { Ap = A2; ld = lda2; kl = k0n - K1; }
            const float* src = Ap + (size_t)m * ld + kl + half * 16;
#pragma unroll
            for (int i = 0; i < 4; i++)
                v[i] = mok ? *(const float4*)(src + i * 4) : make_float4(0.f, 0.f, 0.f, 0.f);
        }
        if (active) {
            const __nv_bfloat16* BsH = Bsm + (buf * 2 + 0) * 128 * 40;
            const __nv_bfloat16* BsL = Bsm + (buf * 2 + 1) * 128 * 40;
#pragma unroll
            for (int kk = 0; kk < 32; kk += 16) {
                wmma::fragment<wmma::matrix_b, 16, 16, 16, __nv_bfloat16, wmma::col_major> bh[2], bl2[2];
#pragma unroll
                for (int j = 0; j < 2; j++) {
                    wmma::load_matrix_sync(bh[j],  BsH + (nl + j * 16) * 40 + kk, 40u);
                    wmma::load_matrix_sync(bl2[j], BsL + (nl + j * 16) * 40 + kk, 40u);
                }
#pragma unroll
                for (int i = 0; i < 4; i++) {
                    wmma::fragment<wmma::matrix_a, 16, 16, 16, __nv_bfloat16, wmma::row_major> ah, al;
                    wmma::load_matrix_sync(ah, Asm + ((buf * 2 + 0) * 128 + wm * 64 + i * 16) * 40 + kk, 40u);
                    wmma::load_matrix_sync(al, Asm + ((buf * 2 + 1) * 128 + wm * 64 + i * 16) * 40 + kk, 40u);
#pragma unroll
                    for (int j = 0; j < 2; j++) {
                        wmma::mma_sync(acc[i][j], ah, bh[j],  acc[i][j]);
                        wmma::mma_sync(acc[i][j], ah, bl2[j], acc[i][j]);
                        wmma::mma_sync(acc[i][j], al, bh[j],  acc[i][j]);
                    }
                }
            }
        }
        buf ^= 1;
    }
    __syncthreads();

    if (EPI == 3) {
        // ---- fused relu -> LayerNorm epilogue (Nfull == 128) ----
        float* obuf = reinterpret_cast<float*>(dynsmem);   // 128 x 132 f32
#pragma unroll
        for (int i = 0; i < 4; i++)
#pragma unroll
            for (int j = 0; j < 2; j++)
                wmma::store_matrix_sync(obuf + (wm * 64 + i * 16) * 132 + nl + j * 16,
                                        acc[i][j], 132u, wmma::mem_row_major);
        __syncthreads();
        float invr = J.invr[z];
        int r0 = wid * 16;
        for (int rr = 0; rr < 16; rr++) {
            int rloc = r0 + rr;
            int mm = m0 + rloc;
            if (mm >= M) continue;
            float vv[4]; float s = 0.f;
#pragma unroll
            for (int j = 0; j < 4; j++) {
                int c = lane + 32 * j;
                float val = obuf[rloc * 132 + c] * alpha + bias[c];
                vv[j] = fmaxf(val * invr, 0.f);
                s += vv[j];
            }
#pragma unroll
            for (int o = 16; o; o >>= 1) s += __shfl_xor_sync(0xffffffffu, s, o);
            float mean = s * (1.0f / 128.0f);
            float ss = 0.f;
#pragma unroll
            for (int j = 0; j < 4; j++) { float d = vv[j] - mean; ss += d * d; }
#pragma unroll
            for (int o = 16; o; o >>= 1) ss += __shfl_xor_sync(0xffffffffu, ss, o);
            float inv = rsqrtf(ss * (1.0f / 128.0f) + 1e-5f);
            float* q = C + (size_t)mm * ldc;
#pragma unroll
            for (int j = 0; j < 4; j++) {
                int c = lane + 32 * j;
                q[c] = (vv[j] - mean) * inv * bnS[c] + bnB[c];
            }
        }
    } else if (EPI == 4) {
        // ---- relu+BN -> h (bf16 hi/lo, stride 136) -> h@W2+b2 -> Cout ----
        // smem budget: hHb/hLb = 2*128*136*2 = 69632 B at offset 0;
        // patch = 8 warps * 320 f32 = 10240 B at offset 69632; total 79872 <= 81920.
        __nv_bfloat16* hHb = reinterpret_cast<__nv_bfloat16*>(dynsmem);
        __nv_bfloat16* hLb = hHb + 128 * 136;
        float* myp = reinterpret_cast<float*>(dynsmem + 69632) + wid * 320;
        int base = lane * 8;
        int pr = base >> 4, pc = base & 15;
#pragma unroll
        for (int i = 0; i < 4; i++) {
#pragma unroll
            for (int j = 0; j < 2; j++) {
                wmma::store_matrix_sync(myp, acc[i][j], 20u, wmma::mem_row_major);
                __syncwarp();
                int rloc = wm * 64 + i * 16 + pr;
                int nb = nl + j * 16;
                bool rok = (m0 + rloc < M);
#pragma unroll
                for (int t = 0; t < 8; t++) {
                    int n = nb + pc + t;
                    float val = rok ? (myp[pr * 20 + pc + t] * alpha + bias[n]) : 0.f;
                    val = fmaxf(val, 0.f) * bnS[n] + bnB[n];
                    __nv_bfloat16 hh, ll;
                    bsplit(val, hh, ll);
                    hHb[rloc * 136 + n] = hh;
                    hLb[rloc * 136 + n] = ll;
                }
                __syncwarp();
            }
        }
        __syncthreads();
        // second GEMM: each warp computes 16 rows x 32 cols of d_out
        wmma::fragment<wmma::accumulator, 16, 16, 16, float> acc2[2];
#pragma unroll
        for (int j = 0; j < 2; j++) wmma::fill_fragment(acc2[j], 0.0f);
        const __nv_bfloat16* W2h = J.W2h;
        const __nv_bfloat16* W2l = J.W2l;
        int r0 = wid * 16;
#pragma unroll
        for (int kf = 0; kf < 8; kf++) {
            wmma::fragment<wmma::matrix_a, 16, 16, 16, __nv_bfloat16, wmma::row_major> ah, al;
            wmma::load_matrix_sync(ah, hHb + r0 * 136 + kf * 16, 136u);
            wmma::load_matrix_sync(al, hLb + r0 * 136 + kf * 16, 136u);
#pragma unroll
            for (int j = 0; j < 2; j++) {
                wmma::fragment<wmma::matrix_b, 16, 16, 16, __nv_bfloat16, wmma::col_major> bh, bl2;
                wmma::load_matrix_sync(bh,  W2h + (size_t)(j * 16) * 128 + kf * 16, 128u);
                wmma::load_matrix_sync(bl2, W2l + (size_t)(j * 16) * 128 + kf * 16, 128u);
                wmma::mma_sync(acc2[j], ah, bh,  acc2[j]);
                wmma::mma_sync(acc2[j], ah, bl2, acc2[j]);
                wmma::mma_sync(acc2[j], al, bh,  acc2[j]);
            }
        }
        const float* b2 = J.b2;
        float* Cout = J.Cout;
#pragma unroll
        for (int j = 0; j < 2; j++) {
            wmma::store_matrix_sync(myp, acc2[j], 20u, wmma::mem_row_major);
            __syncwarp();
            int mm = m0 + r0 + pr;
            if (mm < M) {
                float out[8];
#pragma unroll
                for (int t = 0; t < 8; t++) {
                    int n = j * 16 + pc + t;
                    out[t] = myp[pr * 20 + pc + t] + b2[n];
                }
                float* dst = Cout + (size_t)mm * 32 + j * 16 + pc;
                *(float4*)dst = *(float4*)&out[0];
                *(float4*)(dst + 4) = *(float4*)&out[4];
            }
            __syncwarp();
        }
    } else if (active) {
        float* myp = reinterpret_cast<float*>(dynsmem) + wid * 320;
        int base = lane * 8;
        int pr = base >> 4, pc = base & 15;
#pragma unroll
        for (int i = 0; i < 4; i++) {
#pragma unroll
            for (int j = 0; j < 2; j++) {
                wmma::store_matrix_sync(myp, acc[i][j], 20u, wmma::mem_row_major);
                __syncwarp();
                int mb = mw + i * 16, nb = nw + j * 16;
                if (mb + pr < M) {
                    float out[8];
#pragma unroll
                    for (int t = 0; t < 8; t++) {
                        int n = nb + pc + t;
                        float val = myp[pr * 20 + pc + t] * alpha + bias[n];
                        if (EPI >= 1) val = fmaxf(val, 0.0f);
                        out[t] = val;
                    }
                    float* dst = C + (size_t)(mb + pr) * ldc + coff + nb + pc;
                    *(float4*)dst = *(float4*)&out[0];
                    *(float4*)(dst + 4) = *(float4*)&out[4];
                }
                __syncwarp();
            }
        }
    }
}

// ================= merged elementwise: layer-0 post ==========================
__global__ void l0post2_k(const float* __restrict__ On, const float* __restrict__ Ob,
                          const float* __restrict__ gg, const float* __restrict__ bb,
                          float* __restrict__ xn, float* __restrict__ xb, int nblkN) {
    int b = blockIdx.x;
    const float* O; float* xout; int ldo, M, R;
    if (b < nblkN) { O = On; xout = xn; ldo = 384; M = NN; R = 3; }
    else           { O = Ob; xout = xb; ldo = 256; M = NB; R = 2; b -= nblkN; }
    int row = b * 8 + (threadIdx.x >> 5);
    if (row >= M) return;
    int lane = threadIdx.x & 31;
    float acc[4] = {0.f, 0.f, 0.f, 0.f};
    for (int rb = 0; rb < R; rb++) {
        const float* p = O + (size_t)row * ldo + rb * 128;
        float v[4]; float ss = 0.f;
#pragma unroll
        for (int j = 0; j < 4; j++) { v[j] = p[lane + 32 * j]; ss += v[j] * v[j]; }
#pragma unroll
        for (int s = 16; s; s >>= 1) ss += __shfl_xor_sync(0xffffffffu, ss, s);
        float inv = 1.0f / fmaxf(sqrtf(ss), 1e-12f);
#pragma unroll
        for (int j = 0; j < 4; j++) acc[j] += v[j] * inv;
    }
    const float invR = 1.0f / R;
    float s = 0.f;
#pragma unroll
    for (int j = 0; j < 4; j++) { acc[j] = fmaxf(acc[j] * invR, 0.f); s += acc[j]; }
#pragma unroll
    for (int o = 16; o; o >>= 1) s += __shfl_xor_sync(0xffffffffu, s, o);
    float m = s * (1.0f / 128.0f);
    float ss = 0.f;
#pragma unroll
    for (int j = 0; j < 4; j++) { float d = acc[j] - m; ss += d * d; }
#pragma unroll
    for (int o = 16; o; o >>= 1) ss += __shfl_xor_sync(0xffffffffu, ss, o);
    float inv = rsqrtf(ss * (1.0f / 128.0f) + 1e-5f);
    float* q = xout + (size_t)row * 128;
#pragma unroll
    for (int j = 0; j < 4; j++) {
        int c = lane + 32 * j;
        q[c] = (acc[j] - m) * inv * gg[c] + bb[c];
    }
}

// ================= single fused weight-prep kernel ===========================
__device__ __forceinline__ void lsplit_body(__nv_bfloat16* hi, __nv_bfloat16* lo,
                                            const float* WlL, const float* WrL,
                                            int r0, int r1, int r2, int nrel, int idx) {
    int K = nrel * 128 + 128;
    int n = idx / K, k = idx - n * K;
    float x;
    if (k < nrel * 128) {
        int j = k >> 7, kk = k & 127;
        int r = (j == 0) ? r0 : (j == 1) ? r1 : r2;
        x = WlL[(size_t)r * 16384 + kk * 128 + n];
    } else {
        int kk = k - nrel * 128;
        x = WrL[(size_t)r0 * 16384 + kk * 128 + n] + WrL[(size_t)r1 * 16384 + kk * 128 + n];
        if (nrel == 3) x += WrL[(size_t)r2 * 16384 + kk * 128 + n];
    }
    __nv_bfloat16 h, l;
    bsplit(x, h, l);
    hi[idx] = h;
    lo[idx] = l;
}
#define PREP_TOTAL 305152
__global__ void prep_k(const float* __restrict__ proj_W, const float* __restrict__ proj_b,
                       const float* __restrict__ l0_Wl, const float* __restrict__ l0_bl,
                       const float* __restrict__ l0_Wr,
                       const float* __restrict__ Wl, const float* __restrict__ bl,
                       const float* __restrict__ Wr,
                       const float* __restrict__ mlp_W1, const float* __restrict__ mlp_W2,
                       const float* __restrict__ bn_g) {
    int idx = blockIdx.x * 256 + threadIdx.x;
    __nv_bfloat16 h, l;
    if (idx < 12288) {
        int j = idx >> 12, rem = idx & 4095;
        int k = rem >> 6, c = rem & 63;
        float x = proj_W[(size_t)j * 4096 + k * 64 + c];
        int n = j * 64 + c;
        bsplit(x, h, l);
        g_BtProjN[0][n * 64 + k] = h; g_BtProjN[1][n * 64 + k] = l;
        return;
    }
    idx -= 12288;
    if (idx < 8192) {
        int j = idx >> 12, rem = idx & 4095;
        int k = rem >> 6, c = rem & 63;
        int r = (j == 0) ? 3 : 4;
        float x = proj_W[(size_t)r * 4096 + k * 64 + c];
        int n = j * 64 + c;
        bsplit(x, h, l);
        g_BtProjB[0][n * 64 + k] = h; g_BtProjB[1][n * 64 + k] = l;
        return;
    }
    idx -= 8192;
    if (idx < 81920) {
        int s = idx >> 14, rem = idx & 16383;
        int n = rem >> 7, k = rem & 127;
        const int rels[5] = {0, 1, 3, 2, 4};
        int r = rels[s];
        float x = (k < 64) ? l0_Wr[(size_t)r * 8192 + k * 128 + n]
                           : l0_Wl[(size_t)r * 8192 + (k - 64) * 128 + n];
        bsplit(x, h, l);
        g_BtL0[0][s][rem] = h; g_BtL0[1][s][rem] = l;
        return;
    }
    idx -= 81920;
    if (idx < 65536) { lsplit_body(g_BtL1N[0], g_BtL1N[1], Wl, Wr, 0, 1, 3, 3, idx); return; }
    idx -= 65536;
    if (idx < 49152) { lsplit_body(g_BtL1B[0], g_BtL1B[1], Wl, Wr, 2, 4, 0, 2, idx); return; }
    idx -= 49152;
    if (idx < 65536) { lsplit_body(g_BtL2N[0], g_BtL2N[1], Wl + 5 * 16384, Wr + 5 * 16384, 0, 1, 3, 3, idx); return; }
    idx -= 65536;
    if (idx < 16384) {
        int k = idx >> 7, n = idx & 127;
        bsplit(mlp_W1[idx], h, l);
        g_BtM1[0][n * 128 + k] = h; g_BtM1[1][n * 128 + k] = l;
        return;
    }
    idx -= 16384;
    if (idx < 4096) {
        int k = idx / 32, n = idx - (idx / 32) * 32;
        bsplit(mlp_W2[idx], h, l);
        g_BtM2[0][n * 128 + k] = h; g_BtM2[1][n * 128 + k] = l;
        return;
    }
    idx -= 4096;
    int t = idx;
    if (t < 192) {
        int j = t / 64;
        g_pbCatN[t] = proj_b[(size_t)j * 64 + (t - j * 64)];
    } else if (t < 320) {
        int local = t - 192; int j = local / 64;
        int r = (j == 0) ? 3 : 4;
        g_pbCatB[local] = proj_b[(size_t)r * 64 + (local - j * 64)];
    } else if (t < 704) {
        int local = t - 320; int j = local / 128;
        int r = (j == 0) ? 0 : (j == 1) ? 1 : 3;
        g_l0blCatN[local] = l0_bl[(size_t)r * 128 + (local - j * 128)];
    } else if (t < 960) {
        int local = t - 704; int j = local / 128;
        int r = (j == 0) ? 2 : 4;
        g_l0blCatB[local] = l0_bl[(size_t)r * 128 + (local - j * 128)];
    } else if (t < 1088) {
        int i = t - 960;
        g_b1SumN[i] = bl[i] + bl[128 + i] + bl[3 * 128 + i];
    } else if (t < 1216) {
        int i = t - 1088;
        g_b1SumB[i] = bl[2 * 128 + i] + bl[4 * 128 + i];
    } else if (t < 1344) {
        int i = t - 1216;
        g_b2SumN[i] = bl[(5 + 0) * 128 + i] + bl[(5 + 1) * 128 + i] + bl[(5 + 3) * 128 + i];
    } else if (t < 1472) {
        int i = t - 1344;
        g_bnS[i] = bn_g[i] * rsqrtf(1.0f + 1e-5f);
    }
}

// ================= host dispatch =============================================
static void tgemmJ(int epi, const TGJob& J, int nslots, const float* p0, const float* p1) {
    int maxM = 0, maxN = 0;
    for (int s = 0; s < nslots; s++) {
        if (J.M[s] > maxM) maxM = J.M[s];
        if (J.Nfull[s] > maxN) maxN = J.Nfull[s];
    }
    dim3 g((maxM + 127) / 128, (maxN + 127) / 128, nslots);
    if (epi == 0) {
        cudaFuncSetAttribute(tgemm_k<0>, cudaFuncAttributeMaxDynamicSharedMemorySize, TG_DSM);
        tgemm_k<0><<<g, 256, TG_DSM>>>(J, p0, p1);
    } else if (epi == 1) {
        cudaFuncSetAttribute(tgemm_k<1>, cudaFuncAttributeMaxDynamicSharedMemorySize, TG_DSM);
        tgemm_k<1><<<g, 256, TG_DSM>>>(J, p0, p1);
    } else if (epi == 3) {
        cudaFuncSetAttribute(tgemm_k<3>, cudaFuncAttributeMaxDynamicSharedMemorySize, TG_DSM);
        tgemm_k<3><<<g, 256, TG_DSM>>>(J, p0, p1);
    } else {
        cudaFuncSetAttribute(tgemm_k<4>, cudaFuncAttributeMaxDynamicSharedMemorySize, TG_DSM);
        tgemm_k<4><<<g, 256, TG_DSM>>>(J, p0, p1);
    }
}
static void setslot(TGJob& J, int s, const float* A1, int lda1, int K1,
                    const float* A2, int lda2, int K2,
                    const __nv_bfloat16* Bh, const __nv_bfloat16* Bl, int ldK,
                    const float* bias, float* C, int ldc, int coff,
                    int M, int Nfull, float alpha, float invr = 1.0f) {
    J.A1[s] = A1; J.lda1[s] = lda1; J.K1[s] = K1;
    J.A2[s] = A2; J.lda2[s] = lda2; J.K2[s] = K2;
    J.Bhi[s] = Bh; J.Blo[s] = Bl; J.ldK[s] = ldK;
    J.bias[s] = bias; J.C[s] = C; J.ldc[s] = ldc; J.coff[s] = coff;
    J.M[s] = M; J.Nfull[s] = Nfull; J.alpha[s] = alpha; J.invr[s] = invr;
}

extern "C" void kernel_launch(void* const* d_in, const int* in_sizes, int n_in,
                              void* d_out, int out_size) {
    const float* x_note = (const float*)d_in[0];
    const float* x_beat = (const float*)d_in[1];
    const int* e[5] = {(const int*)d_in[2], (const int*)d_in[3], (const int*)d_in[4],
                       (const int*)d_in[5], (const int*)d_in[6]};
    int E[5];
    for (int r = 0; r < 5; r++) E[r] = in_sizes[2 + r] / 2;
    const float* proj_W = (const float*)d_in[7];
    const float* proj_b = (const float*)d_in[8];
    const float* l0_Wl  = (const float*)d_in[9];
    const float* l0_bl  = (const float*)d_in[10];
    const float* l0_Wr  = (const float*)d_in[11];
    const float* Wl     = (const float*)d_in[12];
    const float* bl     = (const float*)d_in[13];
    const float* Wr     = (const float*)d_in[14];
    const float* ln_g   = (const float*)d_in[15];
    const float* ln_b   = (const float*)d_in[16];
    const float* mlp_W1 = (const float*)d_in[17];
    const float* mlp_b1 = (const float*)d_in[18];
    const float* bn_g   = (const float*)d_in[19];
    const float* bn_b   = (const float*)d_in[20];
    const float* mlp_W2 = (const float*)d_in[21];
    const float* mlp_b2 = (const float*)d_in[22];

    float *pn, *pb, *aggn, *aggb, *On, *Ob, *xn0, *xn1, *xb0, *xb1, *outn, *cntf;
    int *cnti, *rowp, *colx;
    cudaGetSymbolAddress((void**)&pn, g_pn);       cudaGetSymbolAddress((void**)&pb, g_pb);
    cudaGetSymbolAddress((void**)&aggn, g_aggn);   cudaGetSymbolAddress((void**)&aggb, g_aggb);
    cudaGetSymbolAddress((void**)&On, g_On);       cudaGetSymbolAddress((void**)&Ob, g_Ob);
    cudaGetSymbolAddress((void**)&xn0, g_xn0);     cudaGetSymbolAddress((void**)&xn1, g_xn1);
    cudaGetSymbolAddress((void**)&xb0, g_xb0);     cudaGetSymbolAddress((void**)&xb1, g_xb1);
    cudaGetSymbolAddress((void**)&outn, g_outn);
    cudaGetSymbolAddress((void**)&cntf, g_cnt);    cudaGetSymbolAddress((void**)&cnti, g_cnti);
    cudaGetSymbolAddress((void**)&rowp, g_rowp);   cudaGetSymbolAddress((void**)&colx, g_col);

    float *pbCatN, *pbCatB, *l0blCatN, *l0blCatB, *b1SumN, *b1SumB, *b2SumN, *bnS;
    cudaGetSymbolAddress((void**)&pbCatN, g_pbCatN);     cudaGetSymbolAddress((void**)&pbCatB, g_pbCatB);
    cudaGetSymbolAddress((void**)&l0blCatN, g_l0blCatN); cudaGetSymbolAddress((void**)&l0blCatB, g_l0blCatB);
    cudaGetSymbolAddress((void**)&b1SumN, g_b1SumN);     cudaGetSymbolAddress((void**)&b1SumB, g_b1SumB);
    cudaGetSymbolAddress((void**)&b2SumN, g_b2SumN);     cudaGetSymbolAddress((void**)&bnS, g_bnS);

    __nv_bfloat16 *BtProjN[2], *BtProjB[2], *BtL0[2], *BtL1N[2], *BtL1B[2], *BtL2N[2], *BtM1[2], *BtM2[2];
    {
        __nv_bfloat16* p;
        cudaGetSymbolAddress((void**)&p, g_BtProjN); BtProjN[0] = p; BtProjN[1] = p + 256 * 64;
        cudaGetSymbolAddress((void**)&p, g_BtProjB); BtProjB[0] = p; BtProjB[1] = p + 128 * 64;
        cudaGetSymbolAddress((void**)&p, g_BtL0);    BtL0[0] = p;    BtL0[1] = p + 5 * 128 * 128;
        cudaGetSymbolAddress((void**)&p, g_BtL1N);   BtL1N[0] = p;   BtL1N[1] = p + 128 * 512;
        cudaGetSymbolAddress((void**)&p, g_BtL1B);   BtL1B[0] = p;   BtL1B[1] = p + 128 * 384;
        cudaGetSymbolAddress((void**)&p, g_BtL2N);   BtL2N[0] = p;   BtL2N[1] = p + 128 * 512;
        cudaGetSymbolAddress((void**)&p, g_BtM1);    BtM1[0] = p;    BtM1[1] = p + 128 * 128;
        cudaGetSymbolAddress((void**)&p, g_BtM2);    BtM2[0] = p;    BtM2[1] = p + 128 * 128;
    }

    int ebase[5];
    { int acc = 0; for (int r = 0; r < 5; r++) { ebase[r] = acc; acc += E[r]; } }
    int maxE = 0;
    for (int r = 0; r < 5; r++) maxE = (E[r] > maxE) ? E[r] : maxE;

    // ---- CSR build ----
    init_k<<<(5 * NN + 255) / 256, 256>>>(e[0]);
    counti5_k<<<dim3((maxE + 255) / 256, 5), 256>>>(e[0], e[1], e[2], e[3], e[4],
                                                    E[0], E[1], E[2], E[3], E[4]);
    scan1_k<<<dim3(NBX, 5), 256>>>();
    scan3_k<<<dim3(NBX, 5), 256>>>();
    fill5_k<<<dim3((maxE + 255) / 256, 5), 256>>>(e[0], e[1], e[2], e[3], e[4],
                                                  E[0], E[1], E[2], E[3], E[4],
                                                  ebase[0], ebase[1], ebase[2], ebase[3], ebase[4]);
    const int* rp[5]; const int* cx[5]; const float* ic[5];
    for (int r = 0; r < 5; r++) {
        rp[r] = rowp + r * (NN + 1);
        cx[r] = colx + ebase[r];
        ic[r] = cntf + r * NN;
    }

    // ---- fused weight prep ----
    prep_k<<<(PREP_TOTAL + 255) / 256, 256>>>(proj_W, proj_b, l0_Wl, l0_bl, l0_Wr,
                                              Wl, bl, Wr, mlp_W1, mlp_W2, bn_g);

    const int NBLK_N = (NN + 7) / 8;
    const int NBLK_B = (NB + 7) / 8;

    auto mkjob = [&](Agg5& J, int s, const float* xf, int lds, int soff, int rel,
                     float* agg, int ldd, int doff, int n) {
        J.xf[s] = xf; J.lds[s] = lds; J.soff[s] = soff;
        J.rowp[s] = rp[rel]; J.col[s] = cx[rel]; J.invc[s] = ic[rel];
        J.agg[s] = agg; J.ldd[s] = ldd; J.doff[s] = doff; J.n[s] = n;
    };

    // ==================== layer 0 ====================
    {
        TGJob G;
        setslot(G, 0, x_note, 64, 64, nullptr, 0, 0, BtProjN[0], BtProjN[1], 64,
                pbCatN, pn, 192, 0, NN, 192, 1.f);
        setslot(G, 1, x_beat, 64, 64, nullptr, 0, 0, BtProjB[0], BtProjB[1], 64,
                pbCatB, pb, 128, 0, NB, 128, 1.f);
        tgemmJ(1, G, 2, nullptr, nullptr);
    }
    {
        Agg5 J; J.nslots = 5;
        mkjob(J, 0, pn, 192, 0,   0, aggn, 192, 0,   NN);
        mkjob(J, 1, pn, 192, 64,  1, aggn, 192, 64,  NN);
        mkjob(J, 2, pb, 128, 0,   3, aggn, 192, 128, NN);
        mkjob(J, 3, pn, 192, 128, 2, aggb, 128, 0,   NB);
        mkjob(J, 4, pb, 128, 64,  4, aggb, 128, 64,  NB);
        J.boff[0] = 0; J.boff[1] = NBLK_N; J.boff[2] = 2 * NBLK_N; J.boff[3] = 3 * NBLK_N;
        J.boff[4] = 3 * NBLK_N + NBLK_B; J.boff[5] = 3 * NBLK_N + 2 * NBLK_B;
        aggmulti_k<2><<<J.boff[5], 256>>>(J);
    }
    {
        TGJob G;
        for (int j = 0; j < 3; j++)
            setslot(G, j, x_note, 64, 64, aggn + j * 64, 192, 64,
                    BtL0[0] + j * 16384, BtL0[1] + j * 16384, 128,
                    l0blCatN + j * 128, On, 384, j * 128, NN, 128, 1.f);
        for (int j = 0; j < 2; j++)
            setslot(G, 3 + j, x_beat, 64, 64, aggb + j * 64, 128, 64,
                    BtL0[0] + (3 + j) * 16384, BtL0[1] + (3 + j) * 16384, 128,
                    l0blCatB + j * 128, Ob, 256, j * 128, NB, 128, 1.f);
        tgemmJ(0, G, 5, nullptr, nullptr);
    }
    l0post2_k<<<NBLK_N + NBLK_B, 256>>>(On, Ob, ln_g, ln_b, xn0, xb0, NBLK_N);

    // ==================== layer 1 (GEMM with fused relu+LN epilogue) =========
    {
        Agg5 J; J.nslots = 5;
        mkjob(J, 0, xn0, 128, 0, 0, aggn, 384, 0,   NN);
        mkjob(J, 1, xn0, 128, 0, 1, aggn, 384, 128, NN);
        mkjob(J, 2, xb0, 128, 0, 3, aggn, 384, 256, NN);
        mkjob(J, 3, xn0, 128, 0, 2, aggb, 256, 0,   NB);
        mkjob(J, 4, xb0, 128, 0, 4, aggb, 256, 128, NB);
        J.boff[0] = 0; J.boff[1] = NBLK_N; J.boff[2] = 2 * NBLK_N; J.boff[3] = 3 * NBLK_N;
        J.boff[4] = 3 * NBLK_N + NBLK_B; J.boff[5] = 3 * NBLK_N + 2 * NBLK_B;
        aggmulti_k<4><<<J.boff[5], 256>>>(J);
    }
    {
        TGJob G;
        setslot(G, 0, aggn, 384, 384, xn0, 128, 128, BtL1N[0], BtL1N[1], 512,
                b1SumN, xn1, 128, 0, NN, 128, 1.f, 1.f / 3.f);
        setslot(G, 1, aggb, 256, 256, xb0, 128, 128, BtL1B[0], BtL1B[1], 384,
                b1SumB, xb1, 128, 0, NB, 128, 1.f, 1.f / 2.f);
        tgemmJ(3, G, 2, ln_g + 128, ln_b + 128);
    }

    // ==================== layer 2 (note dst only) ====================
    {
        Agg5 J; J.nslots = 3;
        mkjob(J, 0, xn1, 128, 0, 0, aggn, 384, 0,   NN);
        mkjob(J, 1, xn1, 128, 0, 1, aggn, 384, 128, NN);
        mkjob(J, 2, xb1, 128, 0, 3, aggn, 384, 256, NN);
        J.boff[0] = 0; J.boff[1] = NBLK_N; J.boff[2] = 2 * NBLK_N; J.boff[3] = 3 * NBLK_N;
        J.boff[4] = 3 * NBLK_N; J.boff[5] = 3 * NBLK_N;
        aggmulti_k<4><<<J.boff[3], 256>>>(J);
    }
    {
        TGJob G;
        setslot(G, 0, aggn, 384, 384, xn1, 128, 128, BtL2N[0], BtL2N[1], 512,
                b2SumN, outn, 128, 0, NN, 128, 1.f);
        tgemmJ(0, G, 1, nullptr, nullptr);
    }

    // ==================== final MLP (fused MLP1+BN+MLP2, writes d_out) =======
    {
        TGJob G;
        setslot(G, 0, outn, 128, 128, nullptr, 0, 0, BtM1[0], BtM1[1], 128,
                mlp_b1, On, 128, 0, NN, 128, 1.f / 3.f);
        G.W2h = BtM2[0]; G.W2l = BtM2[1]; G.b2 = mlp_b2; G.Cout = (float*)d_out;
        tgemmJ(4, G, 1, bnS, bn_b);
    }
}